// round 9
// baseline (speedup 1.0000x reference)
#include <cuda_runtime.h>
#include <cstdint>
#include <cstddef>

#define B_  32
#define P_  2048
#define D_  256
#define BP_ (B_ * P_)   // 65536

// ---------------- device scratch ----------------
__device__ float g_H[(size_t)BP_ * D_];        // 64 MB
__device__ float g_logits[(size_t)BP_ * P_];   // 512 MB
__device__ float g_agg[(size_t)BP_ * D_];      // 64 MB
__device__ float g_xT[(size_t)BP_ * D_];       // 64 MB  x transposed per batch [D][P]
__device__ float g_wlT[(size_t)P_ * D_];       // wl_w^T  [P][D]
__device__ float g_hisT[(size_t)D_ * D_];      // his_w^T [D][D]
__device__ float g_rowoff[BP_];                // m + log(sum exp)
__device__ float g_wc[BP_];                    // per-row gate scalar
__device__ float g_weff[D_];
__device__ float g_beff;

// ---------------- helpers ----------------
__device__ __forceinline__ void mma2(float4& c, const uint32_t a[4],
                                     uint32_t b0, uint32_t b1) {
    asm volatile(
        "mma.sync.aligned.m16n8k8.row.col.f32.tf32.tf32.f32 "
        "{%0,%1,%2,%3}, {%4,%5,%6,%7}, {%8,%9}, {%0,%1,%2,%3};\n"
        : "+f"(c.x), "+f"(c.y), "+f"(c.z), "+f"(c.w)
        : "r"(a[0]), "r"(a[1]), "r"(a[2]), "r"(a[3]), "r"(b0), "r"(b1));
}

__device__ __forceinline__ void ldsm_x4(uint32_t r[4], uint32_t addr) {
    asm volatile("ldmatrix.sync.aligned.m8n8.x4.shared.b16 {%0,%1,%2,%3}, [%4];"
                 : "=r"(r[0]), "=r"(r[1]), "=r"(r[2]), "=r"(r[3]) : "r"(addr));
}

__device__ __forceinline__ void cp16(uint32_t dst_smem, const void* src) {
    asm volatile("cp.async.cg.shared.global [%0], [%1], 16;\n"
                 :: "r"(dst_smem), "l"(src));
}
#define CP_COMMIT()  asm volatile("cp.async.commit_group;\n" ::: "memory")
#define CP_WAIT(n)   asm volatile("cp.async.wait_group %0;\n" :: "n"(n) : "memory")

// ---------------- tiled transpose: dst[c][r] = src[r][c], per-z slice ----------------
__global__ void k_transpose(const float* __restrict__ src, float* __restrict__ dst,
                            int R, int Cc)
{
    __shared__ float t[32][33];
    const size_t zoff = (size_t)blockIdx.z * R * Cc;
    src += zoff; dst += zoff;
    int c0 = blockIdx.x * 32, r0 = blockIdx.y * 32;
    int tx = threadIdx.x, ty = threadIdx.y;
#pragma unroll
    for (int i = ty; i < 32; i += 8)
        t[i][tx] = src[(size_t)(r0 + i) * Cc + c0 + tx];
    __syncthreads();
#pragma unroll
    for (int i = ty; i < 32; i += 8)
        dst[(size_t)(c0 + i) * R + r0 + tx] = t[tx][i];
}

// ---------------- kernel: w_eff = cur_w @ gate_w, b_eff = cur_b.gate_w + gate_b
__global__ void k_weff(const float* __restrict__ cur_w, const float* __restrict__ cur_b,
                       const float* __restrict__ gate_w, const float* __restrict__ gate_b)
{
    __shared__ float gw[D_];
    __shared__ float red[D_];
    int k = threadIdx.x;
    gw[k] = gate_w[k];
    __syncthreads();
    float s = 0.f;
#pragma unroll 8
    for (int d = 0; d < D_; d++) s += cur_w[k * D_ + d] * gw[d];
    g_weff[k] = s;
    red[k] = cur_b[k] * gw[k];
    __syncthreads();
    for (int off = 128; off > 0; off >>= 1) {
        if (k < off) red[k] += red[k + off];
        __syncthreads();
    }
    if (k == 0) g_beff = red[0] + gate_b[0];
}

// ---------------- kernel: wc[row] = x[row,:].w_eff + b_eff  (1 warp / row)
__global__ void k_wc(const float* __restrict__ x)
{
    int row  = blockIdx.x * 8 + (threadIdx.x >> 5);
    int lane = threadIdx.x & 31;
    const float* xr = x + (size_t)row * D_;
    float s = 0.f;
#pragma unroll
    for (int i = 0; i < 8; i++) s += xr[lane + 32 * i] * g_weff[lane + 32 * i];
#pragma unroll
    for (int o = 16; o; o >>= 1) s += __shfl_xor_sync(0xffffffffu, s, o);
    if (lane == 0) g_wc[row] = s + g_beff;
}

// ---------------- TF32 GEMM: C[M,N] = A[M,256] @ BT[N,256]^T + bias[N]
// block 128x128, 8 warps (2m x 4n), warp tile 64x32, K-step 32, K=256 fixed.
// Both operands [row][k] stride 36 in smem; ALL fragments via ldmatrix.x4.
#define G_AS 36
#define G_AW (128 * G_AS)            // 4608 words
#define G_STG (2 * G_AW)             // 9216 words per stage

__global__ __launch_bounds__(256, 2) void k_gemm_tf32(
    const float* __restrict__ A, const float* __restrict__ BT,
    const float* __restrict__ bias, float* __restrict__ C, int N)
{
    extern __shared__ float sm[];
    const uint32_t smb = (uint32_t)__cvta_generic_to_shared(sm);

    const int tid  = threadIdx.x;
    const int lane = tid & 31;
    const int warp = tid >> 5;
    const int wm = (warp & 1) * 64;
    const int wn = (warp >> 1) * 32;
    const int g   = lane >> 2;
    const int tig = lane & 3;
    const int row0 = blockIdx.y * 128;
    const int col0 = blockIdx.x * 128;

    // loaders: 2 threads per row, each 16 consecutive k floats
    const int lr = tid >> 1;
    const int lq = (tid & 1) * 16;
    const float* Ap = A  + (size_t)(row0 + lr) * 256 + lq;
    const float* Bp = BT + (size_t)(col0 + lr) * 256 + lq;

    const int rowit = lane & 15;
    const int colw  = (lane & 16) ? 4 : 0;

    float4 acc[4][4];
#pragma unroll
    for (int mi = 0; mi < 4; mi++)
#pragma unroll
        for (int ni = 0; ni < 4; ni++) acc[mi][ni] = make_float4(0.f, 0.f, 0.f, 0.f);

    // stage 0 loads
    {
#pragma unroll
        for (int v = 0; v < 4; v++) {
            cp16(smb + (uint32_t)(lr * G_AS + lq + v * 4) * 4, Ap + v * 4);
            cp16(smb + (uint32_t)(G_AW + lr * G_AS + lq + v * 4) * 4, Bp + v * 4);
        }
        CP_COMMIT();
    }

#pragma unroll 2
    for (int kt = 0; kt < 8; kt++) {
        const int s = kt & 1;
        if (kt < 7) {
            uint32_t base = smb + (uint32_t)((s ^ 1) * G_STG) * 4;
            const int k0 = (kt + 1) * 32;
#pragma unroll
            for (int v = 0; v < 4; v++) {
                cp16(base + (uint32_t)(lr * G_AS + lq + v * 4) * 4, Ap + k0 + v * 4);
                cp16(base + (uint32_t)(G_AW + lr * G_AS + lq + v * 4) * 4, Bp + k0 + v * 4);
            }
            CP_COMMIT();
            CP_WAIT(1);
        } else {
            CP_WAIT(0);
        }
        __syncthreads();

        const uint32_t aB = smb + (uint32_t)(s * G_STG + (wm + rowit) * G_AS + colw) * 4;
        const uint32_t bB = smb + (uint32_t)(s * G_STG + G_AW + (wn + rowit) * G_AS + colw) * 4;
#pragma unroll
        for (int ks = 0; ks < 4; ks++) {
            uint32_t af[4][4];
#pragma unroll
            for (int mi = 0; mi < 4; mi++)
                ldsm_x4(af[mi], aB + (uint32_t)(mi * 16 * G_AS * 4 + ks * 32));
            uint32_t b0[4], b1[4];
            ldsm_x4(b0, bB + (uint32_t)(ks * 32));
            ldsm_x4(b1, bB + (uint32_t)(16 * G_AS * 4 + ks * 32));
#pragma unroll
            for (int mi = 0; mi < 4; mi++) {
                mma2(acc[mi][0], af[mi], b0[0], b0[2]);
                mma2(acc[mi][1], af[mi], b0[1], b0[3]);
                mma2(acc[mi][2], af[mi], b1[0], b1[2]);
                mma2(acc[mi][3], af[mi], b1[1], b1[3]);
            }
        }
        __syncthreads();
    }

    // epilogue: +bias, store
#pragma unroll
    for (int mi = 0; mi < 4; mi++) {
        int r = row0 + wm + mi * 16 + g;
#pragma unroll
        for (int ni = 0; ni < 4; ni++) {
            int c = col0 + wn + ni * 8 + tig * 2;
            float b0 = bias[c], b1 = bias[c + 1];
            float2 v0 = make_float2(acc[mi][ni].x + b0, acc[mi][ni].y + b1);
            float2 v1 = make_float2(acc[mi][ni].z + b0, acc[mi][ni].w + b1);
            *(float2*)(C + (size_t)r * N + c) = v0;
            *(float2*)(C + (size_t)(r + 8) * N + c) = v1;
        }
    }
}

// ---------------- per-row softmax offset = max + log(sum exp)  (1 warp / row)
__global__ void k_rowstat()
{
    int row  = blockIdx.x * 8 + (threadIdx.x >> 5);
    int lane = threadIdx.x & 31;
    const float4* L4 = (const float4*)(g_logits + (size_t)row * P_);
    float m = -1e30f;
#pragma unroll 4
    for (int i = lane; i < P_ / 4; i += 32) {
        float4 v = L4[i];
        m = fmaxf(m, fmaxf(fmaxf(v.x, v.y), fmaxf(v.z, v.w)));
    }
#pragma unroll
    for (int o = 16; o; o >>= 1) m = fmaxf(m, __shfl_xor_sync(0xffffffffu, m, o));
    float s = 0.f;
#pragma unroll 4
    for (int i = lane; i < P_ / 4; i += 32) {
        float4 v = L4[i];
        s += __expf(v.x - m) + __expf(v.y - m) + __expf(v.z - m) + __expf(v.w - m);
    }
#pragma unroll
    for (int o = 16; o; o >>= 1) s += __shfl_xor_sync(0xffffffffu, s, o);
    if (lane == 0) g_rowoff[row] = m + __logf(s);
}

// ---------------- TF32 agg: agg[b,p,:] = sum_{q<=p} exp(l[p,q]-off[p]) * x[b,q,:]
// block 64 rows x 256 cols, 8 warps (2m x 4n), warp tile 32x64.
// A (exp) [m=64][k=32] stride 36; B from xT [n=256][k=32] stride 36; all ldmatrix.
#define AG_S 36

__global__ __launch_bounds__(256, 2) void k_agg_tf32()
{
    __shared__ float As[64 * AG_S];    //  9216 B
    __shared__ float Bs[256 * AG_S];   // 36864 B

    const uint32_t asb = (uint32_t)__cvta_generic_to_shared(As);
    const uint32_t bsb = (uint32_t)__cvta_generic_to_shared(Bs);

    const int b  = blockIdx.z;
    const int p0 = blockIdx.x * 64;
    const int tid  = threadIdx.x;
    const int lane = tid & 31;
    const int warp = tid >> 5;
    const int wm = (warp & 1) * 32;
    const int wn = (warp >> 1) * 64;
    const int g   = lane >> 2;
    const int tig = lane & 3;

    // exp-weight loader: thread handles row ar, 8 k's at ac8
    const int ar  = tid >> 2;              // 0..63
    const int ac8 = (tid & 3) * 8;
    const int prow = p0 + ar;
    const float off = g_rowoff[b * P_ + prow];
    const float* Lp = g_logits + (size_t)(b * P_ + prow) * P_ + ac8;

    const float* xTb = g_xT + (size_t)b * D_ * P_;

    const int rowit = lane & 15;
    const int colw  = (lane & 16) ? 4 : 0;

    float4 acc[2][8];
#pragma unroll
    for (int mi = 0; mi < 2; mi++)
#pragma unroll
        for (int ni = 0; ni < 8; ni++) acc[mi][ni] = make_float4(0.f, 0.f, 0.f, 0.f);

    const int nkt = (p0 + 64) / 32;

    float4 l0 = *(const float4*)(Lp + 0);
    float4 l1 = *(const float4*)(Lp + 4);

    for (int kt = 0; kt < nkt; kt++) {
        const int k0 = kt * 32;
        __syncthreads();   // previous tile fully consumed

        // exp + mask + store A tile
        {
            int kq = k0 + ac8;
            float4 e0, e1;
            e0.x = (kq     <= prow) ? __expf(l0.x - off) : 0.f;
            e0.y = (kq + 1 <= prow) ? __expf(l0.y - off) : 0.f;
            e0.z = (kq + 2 <= prow) ? __expf(l0.z - off) : 0.f;
            e0.w = (kq + 3 <= prow) ? __expf(l0.w - off) : 0.f;
            e1.x = (kq + 4 <= prow) ? __expf(l1.x - off) : 0.f;
            e1.y = (kq + 5 <= prow) ? __expf(l1.y - off) : 0.f;
            e1.z = (kq + 6 <= prow) ? __expf(l1.z - off) : 0.f;
            e1.w = (kq + 7 <= prow) ? __expf(l1.w - off) : 0.f;
            *(float4*)&As[ar * AG_S + ac8]     = e0;
            *(float4*)&As[ar * AG_S + ac8 + 4] = e1;
        }

        // cp.async xT tile [n=256][k=32]: id -> row=id>>3, 16B chunk=id&7
#pragma unroll
        for (int t = 0; t < 8; t++) {
            int id = tid + t * 256;
            int row = id >> 3;
            int ch  = (id & 7) * 4;
            cp16(bsb + (uint32_t)(row * AG_S + ch) * 4,
                 xTb + (size_t)row * P_ + k0 + ch);
        }
        CP_COMMIT();

        if (kt + 1 < nkt) {
            l0 = *(const float4*)(Lp + k0 + 32);
            l1 = *(const float4*)(Lp + k0 + 36);
        }

        CP_WAIT(0);
        __syncthreads();

        const uint32_t aB = asb + (uint32_t)((wm + rowit) * AG_S + colw) * 4;
        const uint32_t bB = bsb + (uint32_t)((wn + rowit) * AG_S + colw) * 4;
#pragma unroll
        for (int ks = 0; ks < 4; ks++) {
            uint32_t af[2][4];
#pragma unroll
            for (int mi = 0; mi < 2; mi++)
                ldsm_x4(af[mi], aB + (uint32_t)(mi * 16 * AG_S * 4 + ks * 32));
#pragma unroll
            for (int j = 0; j < 4; j++) {
                uint32_t bq[4];
                ldsm_x4(bq, bB + (uint32_t)(j * 16 * AG_S * 4 + ks * 32));
#pragma unroll
                for (int mi = 0; mi < 2; mi++) {
                    mma2(acc[mi][2 * j],     af[mi], bq[0], bq[2]);
                    mma2(acc[mi][2 * j + 1], af[mi], bq[1], bq[3]);
                }
            }
        }
    }

#pragma unroll
    for (int mi = 0; mi < 2; mi++) {
        int r = p0 + wm + mi * 16 + g;
#pragma unroll
        for (int ni = 0; ni < 8; ni++) {
            int c = wn + ni * 8 + tig * 2;
            float2 v0 = make_float2(acc[mi][ni].x, acc[mi][ni].y);
            float2 v1 = make_float2(acc[mi][ni].z, acc[mi][ni].w);
            *(float2*)(g_agg + (size_t)(b * P_ + r) * D_ + c) = v0;
            *(float2*)(g_agg + (size_t)(b * P_ + r + 8) * D_ + c) = v1;
        }
    }
}

// ---------------- kernel: out = LN(agg@mlp_w + mlp_b + wc*x) * ln_g + ln_b
__global__ __launch_bounds__(256) void k_final(
    const float* __restrict__ x, const float* __restrict__ mlp_w,
    const float* __restrict__ mlp_b, const float* __restrict__ ln_g,
    const float* __restrict__ ln_b, float* __restrict__ out)
{
    const int row0 = blockIdx.x * 32;
    const int tid = threadIdx.x;
    const int tx  = tid & 31;
    const int ty  = tid >> 5;

    __shared__ float As[16][36];
    __shared__ float Bs[16][256];
    __shared__ float s_mb[256], s_g[256], s_b[256];

    s_mb[tid] = mlp_b[tid];
    s_g[tid]  = ln_g[tid];
    s_b[tid]  = ln_b[tid];

    const int ar = tid >> 3;
    const int ac = (tid & 7) * 2;
    const float* Ap = g_agg + (size_t)(row0 + ar) * D_ + ac;

    float acc[4][8];
#pragma unroll
    for (int i = 0; i < 4; i++)
#pragma unroll
        for (int j = 0; j < 8; j++) acc[i][j] = 0.f;

    __syncthreads();
    for (int k0 = 0; k0 < D_; k0 += 16) {
        float2 a2 = *(const float2*)(Ap + k0);
        float4 bv[4];
#pragma unroll
        for (int t = 0; t < 4; t++) {
            int idx4 = tid + t * 256;
            int br = idx4 >> 6;
            int bc = (idx4 & 63) * 4;
            bv[t] = *(const float4*)(mlp_w + (size_t)(k0 + br) * D_ + bc);
        }
        As[ac][ar] = a2.x;
        As[ac + 1][ar] = a2.y;
#pragma unroll
        for (int t = 0; t < 4; t++) {
            int idx4 = tid + t * 256;
            int br = idx4 >> 6;
            int bc = (idx4 & 63) * 4;
            *(float4*)&Bs[br][bc] = bv[t];
        }
        __syncthreads();
#pragma unroll
        for (int k = 0; k < 16; k++) {
            float4 a  = *(const float4*)&As[k][ty * 4];
            float4 b0 = *(const float4*)&Bs[k][tx * 4];
            float4 b1 = *(const float4*)&Bs[k][tx * 4 + 128];
            float av[4] = {a.x, a.y, a.z, a.w};
            float bb[8] = {b0.x, b0.y, b0.z, b0.w, b1.x, b1.y, b1.z, b1.w};
#pragma unroll
            for (int i = 0; i < 4; i++)
#pragma unroll
                for (int j = 0; j < 8; j++)
                    acc[i][j] += av[i] * bb[j];
        }
        __syncthreads();
    }

#pragma unroll
    for (int i = 0; i < 4; i++) {
        int r = row0 + ty * 4 + i;
        float w = g_wc[r];
        const float* xr = x + (size_t)r * D_;
        float4 x0 = *(const float4*)(xr + tx * 4);
        float4 x1 = *(const float4*)(xr + tx * 4 + 128);
        float xv[8] = {x0.x, x0.y, x0.z, x0.w, x1.x, x1.y, x1.z, x1.w};
        float h[8];
#pragma unroll
        for (int j = 0; j < 8; j++) {
            int c = (j < 4) ? (tx * 4 + j) : (tx * 4 + 128 + (j - 4));
            h[j] = acc[i][j] + s_mb[c] + w * xv[j];
        }
        float s = 0.f;
#pragma unroll
        for (int j = 0; j < 8; j++) s += h[j];
#pragma unroll
        for (int o = 16; o; o >>= 1) s += __shfl_xor_sync(0xffffffffu, s, o);
        float mu = s * (1.0f / 256.0f);
        float d = 0.f;
#pragma unroll
        for (int j = 0; j < 8; j++) { float t = h[j] - mu; d += t * t; }
#pragma unroll
        for (int o = 16; o; o >>= 1) d += __shfl_xor_sync(0xffffffffu, d, o);
        float inv = rsqrtf(d * (1.0f / 256.0f) + 1e-5f);

        float y[8];
#pragma unroll
        for (int j = 0; j < 8; j++) {
            int c = (j < 4) ? (tx * 4 + j) : (tx * 4 + 128 + (j - 4));
            y[j] = (h[j] - mu) * inv * s_g[c] + s_b[c];
        }
        float4 w0 = make_float4(y[0], y[1], y[2], y[3]);
        float4 w1 = make_float4(y[4], y[5], y[6], y[7]);
        *(float4*)(out + (size_t)r * D_ + tx * 4) = w0;
        *(float4*)(out + (size_t)r * D_ + tx * 4 + 128) = w1;
    }
}

// ---------------- launch ----------------
extern "C" void kernel_launch(void* const* d_in, const int* in_sizes, int n_in,
                              void* d_out, int out_size)
{
    const float* x      = (const float*)d_in[0];
    const float* mlp_w  = (const float*)d_in[1];
    const float* mlp_b  = (const float*)d_in[2];
    const float* his_w  = (const float*)d_in[3];
    const float* his_b  = (const float*)d_in[4];
    const float* cur_w  = (const float*)d_in[5];
    const float* cur_b  = (const float*)d_in[6];
    const float* wl_w   = (const float*)d_in[7];
    const float* wl_b   = (const float*)d_in[8];
    const float* gate_w = (const float*)d_in[9];
    const float* gate_b = (const float*)d_in[10];
    const float* ln_g   = (const float*)d_in[11];
    const float* ln_b   = (const float*)d_in[12];
    float* out = (float*)d_out;

    void *pH, *pL, *pXT, *pWLT, *pHIST;
    cudaGetSymbolAddress(&pH, g_H);
    cudaGetSymbolAddress(&pL, g_logits);
    cudaGetSymbolAddress(&pXT, g_xT);
    cudaGetSymbolAddress(&pWLT, g_wlT);
    cudaGetSymbolAddress(&pHIST, g_hisT);
    float* gH   = (float*)pH;
    float* gL   = (float*)pL;
    float* gXT  = (float*)pXT;
    float* gWLT = (float*)pWLT;
    float* gHT  = (float*)pHIST;

    const int gemm_smem = G_STG * 2 * 4;   // 73728 bytes
    cudaFuncSetAttribute(k_gemm_tf32, cudaFuncAttributeMaxDynamicSharedMemorySize, gemm_smem);

    dim3 tb(32, 8);
    // transposes (his_w, wl_w, x)
    k_transpose<<<dim3(D_ / 32, D_ / 32, 1), tb>>>(his_w, gHT, D_, D_);
    k_transpose<<<dim3(P_ / 32, D_ / 32, 1), tb>>>(wl_w, gWLT, D_, P_);
    k_transpose<<<dim3(D_ / 32, P_ / 32, B_), tb>>>(x, gXT, P_, D_);

    // fused gate weight precompute + per-row gate scalar
    k_weff<<<1, 256>>>(cur_w, cur_b, gate_w, gate_b);
    k_wc<<<BP_ / 8, 256>>>(x);

    // H = x @ his_w + his_b
    k_gemm_tf32<<<dim3(D_ / 128, BP_ / 128), 256, gemm_smem>>>(x, gHT, his_b, gH, D_);
    // logits = H @ wl_w + wl_b
    k_gemm_tf32<<<dim3(P_ / 128, BP_ / 128), 256, gemm_smem>>>(gH, gWLT, wl_b, gL, P_);
    // per-row softmax offsets
    k_rowstat<<<BP_ / 8, 256>>>();
    // agg = tril(softmax(logits)) @ x
    k_agg_tf32<<<dim3(P_ / 64, 1, B_), 256>>>();
    // out = LN(agg @ mlp_w + mlp_b + wc*x)
    k_final<<<BP_ / 32, 256>>>(x, mlp_w, mlp_b, ln_g, ln_b, out);
    // second output: origin (copy of x)
    cudaMemcpyAsync(out + (size_t)BP_ * D_, x,
                    (size_t)BP_ * D_ * sizeof(float),
                    cudaMemcpyDeviceToDevice);
}

// round 10
// speedup vs baseline: 1.2108x; 1.2108x over previous
#include <cuda_runtime.h>
#include <cstdint>
#include <cstddef>

#define B_  32
#define P_  2048
#define D_  256
#define BP_ (B_ * P_)   // 65536

// ---------------- device scratch ----------------
__device__ float g_H[(size_t)BP_ * D_];        // 64 MB
__device__ float g_logits[(size_t)BP_ * P_];   // 512 MB
__device__ float g_agg[(size_t)BP_ * D_];      // 64 MB
__device__ float g_pmax[(size_t)BP_ * 16];     // per-(row, colblk) partial max
__device__ float g_psum[(size_t)BP_ * 16];     // per-(row, colblk) partial sumexp
__device__ float g_rowoff[BP_];                // m + log(sum exp)
__device__ float g_wc[BP_];                    // per-row gate scalar
__device__ float g_weff[D_];
__device__ float g_beff;

// ---------------- helpers ----------------
__device__ __forceinline__ void mma_tf32(float4& c, const uint32_t a[4], const uint32_t b[2]) {
    asm volatile(
        "mma.sync.aligned.m16n8k8.row.col.f32.tf32.tf32.f32 "
        "{%0,%1,%2,%3}, {%4,%5,%6,%7}, {%8,%9}, {%0,%1,%2,%3};\n"
        : "+f"(c.x), "+f"(c.y), "+f"(c.z), "+f"(c.w)
        : "r"(a[0]), "r"(a[1]), "r"(a[2]), "r"(a[3]),
          "r"(b[0]), "r"(b[1]));
}

__device__ __forceinline__ void ldsm_x4(uint32_t r[4], uint32_t addr) {
    asm volatile("ldmatrix.sync.aligned.m8n8.x4.shared.b16 {%0,%1,%2,%3}, [%4];"
                 : "=r"(r[0]), "=r"(r[1]), "=r"(r[2]), "=r"(r[3]) : "r"(addr));
}

__device__ __forceinline__ void cp16(uint32_t dst_smem, const void* src) {
    asm volatile("cp.async.cg.shared.global [%0], [%1], 16;\n"
                 :: "r"(dst_smem), "l"(src));
}
#define CP_COMMIT()  asm volatile("cp.async.commit_group;\n" ::: "memory")
#define CP_WAIT(n)   asm volatile("cp.async.wait_group %0;\n" :: "n"(n) : "memory")

// ---------------- kernel: w_eff[k] = cur_w[k,:].gate_w; b_eff = cur_b.gate_w + gate_b
// one warp per output row, coalesced.
__global__ void k_weff(const float* __restrict__ cur_w, const float* __restrict__ cur_b,
                       const float* __restrict__ gate_w, const float* __restrict__ gate_b)
{
    int warp = threadIdx.x >> 5;
    int lane = threadIdx.x & 31;
    int k = blockIdx.x * 8 + warp;
    float s = 0.f;
#pragma unroll
    for (int i = 0; i < 8; i++)
        s += cur_w[(size_t)k * D_ + lane + 32 * i] * __ldg(&gate_w[lane + 32 * i]);
#pragma unroll
    for (int o = 16; o; o >>= 1) s += __shfl_xor_sync(0xffffffffu, s, o);
    if (lane == 0) g_weff[k] = s;

    if (blockIdx.x == 0 && warp == 0) {
        float t = 0.f;
#pragma unroll
        for (int i = 0; i < 8; i++)
            t += cur_b[lane + 32 * i] * __ldg(&gate_w[lane + 32 * i]);
#pragma unroll
        for (int o = 16; o; o >>= 1) t += __shfl_xor_sync(0xffffffffu, t, o);
        if (lane == 0) g_beff = t + gate_b[0];
    }
}

// ---------------- kernel: wc[row] = x[row,:].w_eff + b_eff  (1 warp / row)
__global__ void k_wc(const float* __restrict__ x)
{
    int row  = blockIdx.x * 8 + (threadIdx.x >> 5);
    int lane = threadIdx.x & 31;
    const float* xr = x + (size_t)row * D_;
    float s = 0.f;
#pragma unroll
    for (int i = 0; i < 8; i++) s += xr[lane + 32 * i] * g_weff[lane + 32 * i];
#pragma unroll
    for (int o = 16; o; o >>= 1) s += __shfl_xor_sync(0xffffffffu, s, o);
    if (lane == 0) g_wc[row] = s + g_beff;
}

// ---------------- TF32 GEMM: C[M,N] = A[M,K]@B[K,N] + bias[N]
// block 128x128, 8 warps (2m x 4n), warp tile 64x32, K-step 32.
// A smem [m][k] stride 36 (ldmatrix.x4); B smem [k][n] stride 136 (pad-8).
// Optional fused softmax-stats epilogue: per-(row,colblock) partial max/sumexp.
#define G_AS 36
#define G_BS 136
#define G_AW (128 * G_AS)            // 4608 words
#define G_BW (32 * G_BS)             // 4352 words
#define G_STG (G_AW + G_BW)          // 8960 words per stage

__global__ __launch_bounds__(256, 2) void k_gemm_tf32(
    const float* __restrict__ A, const float* __restrict__ Bm,
    const float* __restrict__ bias, float* __restrict__ C,
    int N, int K, int do_stats,
    float* __restrict__ pmax, float* __restrict__ psum)
{
    extern __shared__ float sm[];
    const uint32_t smb = (uint32_t)__cvta_generic_to_shared(sm);
    const uint32_t* smu = (const uint32_t*)sm;

    const int tid  = threadIdx.x;
    const int lane = tid & 31;
    const int warp = tid >> 5;
    const int wm = (warp & 1) * 64;
    const int wn = (warp >> 1) * 32;
    const int wcol = warp >> 1;          // 0..3
    const int g   = lane >> 2;
    const int tig = lane & 3;
    const int row0 = blockIdx.y * 128;
    const int col0 = blockIdx.x * 128;

    // loaders
    const int am = tid & 127;
    const int aq = (tid >> 7) * 16;
    const float* Ap = A + (size_t)(row0 + am) * K + aq;
    const int bk  = tid >> 5;           // 0..7
    const int bn4 = (tid & 31) * 4;
    const float* Bp = Bm + (size_t)bk * N + col0 + bn4;

    // ldmatrix lane pointer components
    const int rowit = (lane & 7) + ((lane & 8) ? 8 : 0);
    const int colw  = (lane & 16) ? 4 : 0;

    float4 acc[4][4];
#pragma unroll
    for (int mi = 0; mi < 4; mi++)
#pragma unroll
        for (int ni = 0; ni < 4; ni++) acc[mi][ni] = make_float4(0.f, 0.f, 0.f, 0.f);

    const int nk = K / 32;

    // stage 0 loads
    {
        uint32_t base = smb;
#pragma unroll
        for (int v = 0; v < 4; v++)
            cp16(base + (uint32_t)(am * G_AS + aq + v * 4) * 4, Ap + v * 4);
#pragma unroll
        for (int v = 0; v < 4; v++)
            cp16(base + (uint32_t)(G_AW + (bk + v * 8) * G_BS + bn4) * 4,
                 Bp + (size_t)(v * 8) * N);
        CP_COMMIT();
    }

    for (int kt = 0; kt < nk; kt++) {
        const int s = kt & 1;
        if (kt + 1 < nk) {
            uint32_t base = smb + (uint32_t)((s ^ 1) * G_STG) * 4;
            const int k0 = (kt + 1) * 32;
#pragma unroll
            for (int v = 0; v < 4; v++)
                cp16(base + (uint32_t)(am * G_AS + aq + v * 4) * 4, Ap + k0 + v * 4);
#pragma unroll
            for (int v = 0; v < 4; v++)
                cp16(base + (uint32_t)(G_AW + (bk + v * 8) * G_BS + bn4) * 4,
                     Bp + (size_t)(k0 + v * 8) * N);
            CP_COMMIT();
            CP_WAIT(1);
        } else {
            CP_WAIT(0);
        }
        __syncthreads();

        const uint32_t aBase = smb + (uint32_t)(s * G_STG + (wm + rowit) * G_AS + colw) * 4;
        const int bBase = s * G_STG + G_AW;
#pragma unroll
        for (int ks = 0; ks < 4; ks++) {
            uint32_t af[4][4];
#pragma unroll
            for (int mi = 0; mi < 4; mi++)
                ldsm_x4(af[mi], aBase + (uint32_t)(mi * 16 * G_AS * 4 + ks * 32));
            uint32_t bf[4][2];
#pragma unroll
            for (int ni = 0; ni < 4; ni++) {
                int c = wn + ni * 8 + g;
                bf[ni][0] = smu[bBase + (ks * 8 + tig) * G_BS + c];
                bf[ni][1] = smu[bBase + (ks * 8 + tig + 4) * G_BS + c];
            }
#pragma unroll
            for (int mi = 0; mi < 4; mi++)
#pragma unroll
                for (int ni = 0; ni < 4; ni++)
                    mma_tf32(acc[mi][ni], af[mi], bf[ni]);
        }
        __syncthreads();
    }

    // bias add (into acc so the stats path sees biased logits)
    float bb[4][2];
#pragma unroll
    for (int ni = 0; ni < 4; ni++) {
        int c = col0 + wn + ni * 8 + tig * 2;
        bb[ni][0] = bias[c];
        bb[ni][1] = bias[c + 1];
    }
#pragma unroll
    for (int mi = 0; mi < 4; mi++)
#pragma unroll
        for (int ni = 0; ni < 4; ni++) {
            acc[mi][ni].x += bb[ni][0]; acc[mi][ni].y += bb[ni][1];
            acc[mi][ni].z += bb[ni][0]; acc[mi][ni].w += bb[ni][1];
        }

    // store
#pragma unroll
    for (int mi = 0; mi < 4; mi++) {
        int r = row0 + wm + mi * 16 + g;
#pragma unroll
        for (int ni = 0; ni < 4; ni++) {
            int c = col0 + wn + ni * 8 + tig * 2;
            *(float2*)(C + (size_t)r * N + c) = make_float2(acc[mi][ni].x, acc[mi][ni].y);
            *(float2*)(C + (size_t)(r + 8) * N + c) = make_float2(acc[mi][ni].z, acc[mi][ni].w);
        }
    }

    // fused softmax partial stats over this block's 128 columns
    if (do_stats) {
        float* red_m = sm;          // [128][4]
        float* red_s = sm + 512;    // [128][4]
#pragma unroll
        for (int mi = 0; mi < 4; mi++) {
            float m1 = -1e30f, m2 = -1e30f;
#pragma unroll
            for (int ni = 0; ni < 4; ni++) {
                m1 = fmaxf(m1, fmaxf(acc[mi][ni].x, acc[mi][ni].y));
                m2 = fmaxf(m2, fmaxf(acc[mi][ni].z, acc[mi][ni].w));
            }
            m1 = fmaxf(m1, __shfl_xor_sync(0xffffffffu, m1, 1));
            m1 = fmaxf(m1, __shfl_xor_sync(0xffffffffu, m1, 2));
            m2 = fmaxf(m2, __shfl_xor_sync(0xffffffffu, m2, 1));
            m2 = fmaxf(m2, __shfl_xor_sync(0xffffffffu, m2, 2));
            float s1 = 0.f, s2 = 0.f;
#pragma unroll
            for (int ni = 0; ni < 4; ni++) {
                s1 += __expf(acc[mi][ni].x - m1) + __expf(acc[mi][ni].y - m1);
                s2 += __expf(acc[mi][ni].z - m2) + __expf(acc[mi][ni].w - m2);
            }
            s1 += __shfl_xor_sync(0xffffffffu, s1, 1);
            s1 += __shfl_xor_sync(0xffffffffu, s1, 2);
            s2 += __shfl_xor_sync(0xffffffffu, s2, 1);
            s2 += __shfl_xor_sync(0xffffffffu, s2, 2);
            if (tig == 0) {
                int rb1 = wm + mi * 16 + g;
                red_m[rb1 * 4 + wcol] = m1;  red_s[rb1 * 4 + wcol] = s1;
                red_m[(rb1 + 8) * 4 + wcol] = m2;  red_s[(rb1 + 8) * 4 + wcol] = s2;
            }
        }
        __syncthreads();
        if (tid < 128) {
            float M = -1e30f;
#pragma unroll
            for (int j = 0; j < 4; j++) M = fmaxf(M, red_m[tid * 4 + j]);
            float S = 0.f;
#pragma unroll
            for (int j = 0; j < 4; j++)
                S += red_s[tid * 4 + j] * __expf(red_m[tid * 4 + j] - M);
            size_t idx = (size_t)(row0 + tid) * 16 + blockIdx.x;
            pmax[idx] = M;
            psum[idx] = S;
        }
    }
}

// ---------------- combine partials: off = M + log(sum_i s_i exp(m_i - M))
__global__ void k_rowstat2()
{
    int row = blockIdx.x * 256 + threadIdx.x;
    const float* pm = g_pmax + (size_t)row * 16;
    const float* ps = g_psum + (size_t)row * 16;
    float M = -1e30f;
#pragma unroll
    for (int j = 0; j < 16; j++) M = fmaxf(M, pm[j]);
    float S = 0.f;
#pragma unroll
    for (int j = 0; j < 16; j++) S += ps[j] * __expf(pm[j] - M);
    g_rowoff[row] = M + __logf(S);
}

// ---------------- TF32 agg: agg[b,p,:] = sum_{q<=p} exp(l[p,q]-off[p]) * x[b,q,:]
// block 64 rows x 256 cols, 8 warps (2m x 4n), warp tile 32x64.
#define AG_AS 36
#define AG_BS 264

__global__ __launch_bounds__(256, 2) void k_agg_tf32(const float* __restrict__ x)
{
    __shared__ float As[64 * AG_AS];   // 9216 B
    __shared__ float Bs[32 * AG_BS];   // 33792 B

    const uint32_t asb = (uint32_t)__cvta_generic_to_shared(As);
    const uint32_t bsb = (uint32_t)__cvta_generic_to_shared(Bs);
    const uint32_t* BsU = (const uint32_t*)Bs;

    const int b  = blockIdx.z;
    const int p0 = blockIdx.x * 64;
    const int tid  = threadIdx.x;
    const int lane = tid & 31;
    const int warp = tid >> 5;
    const int wm = (warp & 1) * 32;
    const int wn = (warp >> 1) * 64;
    const int g   = lane >> 2;
    const int tig = lane & 3;

    // exp-weight loader: thread handles row ar, 8 k's starting at ac8
    const int ar  = tid >> 2;              // 0..63
    const int ac8 = (tid & 3) * 8;
    const int prow = p0 + ar;
    const float off = g_rowoff[b * P_ + prow];
    const float* Lp = g_logits + (size_t)(b * P_ + prow) * P_ + ac8;

    const float* xb = x + (size_t)b * P_ * D_;

    const int rowit = (lane & 7) + ((lane & 8) ? 8 : 0);
    const int colw  = (lane & 16) ? 4 : 0;

    float4 acc[2][8];
#pragma unroll
    for (int mi = 0; mi < 2; mi++)
#pragma unroll
        for (int ni = 0; ni < 8; ni++) acc[mi][ni] = make_float4(0.f, 0.f, 0.f, 0.f);

    const int nkt = (p0 + 64) / 32;

    // preload logits regs for kt=0
    float4 l0 = *(const float4*)(Lp + 0);
    float4 l1 = *(const float4*)(Lp + 4);

    for (int kt = 0; kt < nkt; kt++) {
        const int k0 = kt * 32;
        __syncthreads();   // previous tile fully consumed

        // exp + mask + store A tile
        {
            int kq = k0 + ac8;
            float4 e0, e1;
            e0.x = (kq     <= prow) ? __expf(l0.x - off) : 0.f;
            e0.y = (kq + 1 <= prow) ? __expf(l0.y - off) : 0.f;
            e0.z = (kq + 2 <= prow) ? __expf(l0.z - off) : 0.f;
            e0.w = (kq + 3 <= prow) ? __expf(l0.w - off) : 0.f;
            e1.x = (kq + 4 <= prow) ? __expf(l1.x - off) : 0.f;
            e1.y = (kq + 5 <= prow) ? __expf(l1.y - off) : 0.f;
            e1.z = (kq + 6 <= prow) ? __expf(l1.z - off) : 0.f;
            e1.w = (kq + 7 <= prow) ? __expf(l1.w - off) : 0.f;
            *(float4*)&As[ar * AG_AS + ac8]     = e0;
            *(float4*)&As[ar * AG_AS + ac8 + 4] = e1;
        }

        // cp.async x tile [k=32][n=256]
#pragma unroll
        for (int t = 0; t < 8; t++) {
            int id = tid + t * 256;
            int krow = id >> 6;
            int n4 = (id & 63) * 4;
            cp16(bsb + (uint32_t)(krow * AG_BS + n4) * 4,
                 xb + (size_t)(k0 + krow) * D_ + n4);
        }
        CP_COMMIT();

        // preload next logits regs (overlaps cp.async)
        if (kt + 1 < nkt) {
            l0 = *(const float4*)(Lp + k0 + 32);
            l1 = *(const float4*)(Lp + k0 + 36);
        }

        CP_WAIT(0);
        __syncthreads();

        const uint32_t aBase = asb + (uint32_t)((wm + rowit) * AG_AS + colw) * 4;
#pragma unroll
        for (int ks = 0; ks < 4; ks++) {
            uint32_t af[2][4];
#pragma unroll
            for (int mi = 0; mi < 2; mi++)
                ldsm_x4(af[mi], aBase + (uint32_t)(mi * 16 * AG_AS * 4 + ks * 32));
            uint32_t bf[8][2];
#pragma unroll
            for (int ni = 0; ni < 8; ni++) {
                int c = wn + ni * 8 + g;
                bf[ni][0] = BsU[(ks * 8 + tig) * AG_BS + c];
                bf[ni][1] = BsU[(ks * 8 + tig + 4) * AG_BS + c];
            }
#pragma unroll
            for (int mi = 0; mi < 2; mi++)
#pragma unroll
                for (int ni = 0; ni < 8; ni++)
                    mma_tf32(acc[mi][ni], af[mi], bf[ni]);
        }
    }

#pragma unroll
    for (int mi = 0; mi < 2; mi++) {
        int r = p0 + wm + mi * 16 + g;
#pragma unroll
        for (int ni = 0; ni < 8; ni++) {
            int c = wn + ni * 8 + tig * 2;
            float2 v0 = make_float2(acc[mi][ni].x, acc[mi][ni].y);
            float2 v1 = make_float2(acc[mi][ni].z, acc[mi][ni].w);
            *(float2*)(g_agg + (size_t)(b * P_ + r) * D_ + c) = v0;
            *(float2*)(g_agg + (size_t)(b * P_ + r + 8) * D_ + c) = v1;
        }
    }
}

// ---------------- kernel: out = LN(agg@mlp_w + mlp_b + wc*x) * ln_g + ln_b
__global__ __launch_bounds__(256) void k_final(
    const float* __restrict__ x, const float* __restrict__ mlp_w,
    const float* __restrict__ mlp_b, const float* __restrict__ ln_g,
    const float* __restrict__ ln_b, float* __restrict__ out)
{
    const int row0 = blockIdx.x * 32;
    const int tid = threadIdx.x;
    const int tx  = tid & 31;
    const int ty  = tid >> 5;

    __shared__ float As[16][36];
    __shared__ float Bs[16][256];
    __shared__ float s_mb[256], s_g[256], s_b[256];

    s_mb[tid] = mlp_b[tid];
    s_g[tid]  = ln_g[tid];
    s_b[tid]  = ln_b[tid];

    const int ar = tid >> 3;
    const int ac = (tid & 7) * 2;
    const float* Ap = g_agg + (size_t)(row0 + ar) * D_ + ac;

    float acc[4][8];
#pragma unroll
    for (int i = 0; i < 4; i++)
#pragma unroll
        for (int j = 0; j < 8; j++) acc[i][j] = 0.f;

    __syncthreads();
    for (int k0 = 0; k0 < D_; k0 += 16) {
        float2 a2 = *(const float2*)(Ap + k0);
        float4 bv[4];
#pragma unroll
        for (int t = 0; t < 4; t++) {
            int idx4 = tid + t * 256;
            int br = idx4 >> 6;
            int bc = (idx4 & 63) * 4;
            bv[t] = *(const float4*)(mlp_w + (size_t)(k0 + br) * D_ + bc);
        }
        As[ac][ar] = a2.x;
        As[ac + 1][ar] = a2.y;
#pragma unroll
        for (int t = 0; t < 4; t++) {
            int idx4 = tid + t * 256;
            int br = idx4 >> 6;
            int bc = (idx4 & 63) * 4;
            *(float4*)&Bs[br][bc] = bv[t];
        }
        __syncthreads();
#pragma unroll
        for (int k = 0; k < 16; k++) {
            float4 a  = *(const float4*)&As[k][ty * 4];
            float4 b0 = *(const float4*)&Bs[k][tx * 4];
            float4 b1 = *(const float4*)&Bs[k][tx * 4 + 128];
            float av[4] = {a.x, a.y, a.z, a.w};
            float bb[8] = {b0.x, b0.y, b0.z, b0.w, b1.x, b1.y, b1.z, b1.w};
#pragma unroll
            for (int i = 0; i < 4; i++)
#pragma unroll
                for (int j = 0; j < 8; j++)
                    acc[i][j] += av[i] * bb[j];
        }
        __syncthreads();
    }

#pragma unroll
    for (int i = 0; i < 4; i++) {
        int r = row0 + ty * 4 + i;
        float w = g_wc[r];
        const float* xr = x + (size_t)r * D_;
        float4 x0 = *(const float4*)(xr + tx * 4);
        float4 x1 = *(const float4*)(xr + tx * 4 + 128);
        float xv[8] = {x0.x, x0.y, x0.z, x0.w, x1.x, x1.y, x1.z, x1.w};
        float h[8];
#pragma unroll
        for (int j = 0; j < 8; j++) {
            int c = (j < 4) ? (tx * 4 + j) : (tx * 4 + 128 + (j - 4));
            h[j] = acc[i][j] + s_mb[c] + w * xv[j];
        }
        float s = 0.f;
#pragma unroll
        for (int j = 0; j < 8; j++) s += h[j];
#pragma unroll
        for (int o = 16; o; o >>= 1) s += __shfl_xor_sync(0xffffffffu, s, o);
        float mu = s * (1.0f / 256.0f);
        float d = 0.f;
#pragma unroll
        for (int j = 0; j < 8; j++) { float t = h[j] - mu; d += t * t; }
#pragma unroll
        for (int o = 16; o; o >>= 1) d += __shfl_xor_sync(0xffffffffu, d, o);
        float inv = rsqrtf(d * (1.0f / 256.0f) + 1e-5f);

        float y[8];
#pragma unroll
        for (int j = 0; j < 8; j++) {
            int c = (j < 4) ? (tx * 4 + j) : (tx * 4 + 128 + (j - 4));
            y[j] = (h[j] - mu) * inv * s_g[c] + s_b[c];
        }
        float4 w0 = make_float4(y[0], y[1], y[2], y[3]);
        float4 w1 = make_float4(y[4], y[5], y[6], y[7]);
        *(float4*)(out + (size_t)r * D_ + tx * 4) = w0;
        *(float4*)(out + (size_t)r * D_ + tx * 4 + 128) = w1;
    }
}

// ---------------- launch ----------------
extern "C" void kernel_launch(void* const* d_in, const int* in_sizes, int n_in,
                              void* d_out, int out_size)
{
    const float* x      = (const float*)d_in[0];
    const float* mlp_w  = (const float*)d_in[1];
    const float* mlp_b  = (const float*)d_in[2];
    const float* his_w  = (const float*)d_in[3];
    const float* his_b  = (const float*)d_in[4];
    const float* cur_w  = (const float*)d_in[5];
    const float* cur_b  = (const float*)d_in[6];
    const float* wl_w   = (const float*)d_in[7];
    const float* wl_b   = (const float*)d_in[8];
    const float* gate_w = (const float*)d_in[9];
    const float* gate_b = (const float*)d_in[10];
    const float* ln_g   = (const float*)d_in[11];
    const float* ln_b   = (const float*)d_in[12];
    float* out = (float*)d_out;

    void *pH, *pL, *pPM, *pPS;
    cudaGetSymbolAddress(&pH, g_H);
    cudaGetSymbolAddress(&pL, g_logits);
    cudaGetSymbolAddress(&pPM, g_pmax);
    cudaGetSymbolAddress(&pPS, g_psum);
    float* gH  = (float*)pH;
    float* gL  = (float*)pL;
    float* gPM = (float*)pPM;
    float* gPS = (float*)pPS;

    const int gemm_smem = (G_STG * 2) * 4;   // 71680 bytes
    cudaFuncSetAttribute(k_gemm_tf32, cudaFuncAttributeMaxDynamicSharedMemorySize, gemm_smem);

    // 1) fused gate weight precompute (parallel, coalesced)
    k_weff<<<D_ / 8, 256>>>(cur_w, cur_b, gate_w, gate_b);
    // 2) per-row gate scalar wc
    k_wc<<<BP_ / 8, 256>>>(x);
    // 3) H = x @ his_w + his_b
    k_gemm_tf32<<<dim3(D_ / 128, BP_ / 128), 256, gemm_smem>>>(
        x, his_w, his_b, gH, D_, D_, 0, nullptr, nullptr);
    // 4) logits = H @ wl_w + wl_b   (+ fused softmax partial stats)
    k_gemm_tf32<<<dim3(P_ / 128, BP_ / 128), 256, gemm_smem>>>(
        gH, wl_w, wl_b, gL, P_, D_, 1, gPM, gPS);
    // 5) combine per-row softmax offsets from partials
    k_rowstat2<<<BP_ / 256, 256>>>();
    // 6) agg = tril(softmax(logits)) @ x
    k_agg_tf32<<<dim3(P_ / 64, 1, B_), 256>>>(x);
    // 7) out = LN(agg @ mlp_w + mlp_b + wc*x)
    k_final<<<BP_ / 32, 256>>>(x, mlp_w, mlp_b, ln_g, ln_b, out);
    // 8) second output: origin (copy of x)
    cudaMemcpyAsync(out + (size_t)BP_ * D_, x,
                    (size_t)BP_ * D_ * sizeof(float),
                    cudaMemcpyDeviceToDevice);
}

// round 11
// speedup vs baseline: 1.7147x; 1.4161x over previous
#include <cuda_runtime.h>
#include <cuda_bf16.h>
#include <cstdint>
#include <cstddef>

#define B_  32
#define P_  2048
#define D_  256
#define BP_ (B_ * P_)   // 65536

// ---------------- device scratch ----------------
__device__ __nv_bfloat16 g_Hbf[(size_t)BP_ * D_];     // 32 MB  H in bf16
__device__ __nv_bfloat16 g_logbf[(size_t)BP_ * P_];   // 256 MB logits bf16
__device__ __nv_bfloat16 g_xbf[(size_t)BP_ * D_];     // 32 MB  x in bf16
__device__ __nv_bfloat16 g_wlbf[(size_t)D_ * P_];     // 1 MB   wl_w bf16
__device__ float g_agg[(size_t)BP_ * D_];             // 64 MB
__device__ float g_pmax[(size_t)BP_ * 16];
__device__ float g_psum[(size_t)BP_ * 16];
__device__ float g_rowoff[BP_];
__device__ float g_wc[BP_];
__device__ float g_weff[D_];
__device__ float g_beff;

// ---------------- helpers ----------------
__device__ __forceinline__ void mma_tf32(float4& c, const uint32_t a[4], const uint32_t b[2]) {
    asm volatile(
        "mma.sync.aligned.m16n8k8.row.col.f32.tf32.tf32.f32 "
        "{%0,%1,%2,%3}, {%4,%5,%6,%7}, {%8,%9}, {%0,%1,%2,%3};\n"
        : "+f"(c.x), "+f"(c.y), "+f"(c.z), "+f"(c.w)
        : "r"(a[0]), "r"(a[1]), "r"(a[2]), "r"(a[3]),
          "r"(b[0]), "r"(b[1]));
}

__device__ __forceinline__ void mma_bf16(float4& c, const uint32_t a[4],
                                         uint32_t b0, uint32_t b1) {
    asm volatile(
        "mma.sync.aligned.m16n8k16.row.col.f32.bf16.bf16.f32 "
        "{%0,%1,%2,%3}, {%4,%5,%6,%7}, {%8,%9}, {%0,%1,%2,%3};\n"
        : "+f"(c.x), "+f"(c.y), "+f"(c.z), "+f"(c.w)
        : "r"(a[0]), "r"(a[1]), "r"(a[2]), "r"(a[3]), "r"(b0), "r"(b1));
}

__device__ __forceinline__ void ldsm_x4(uint32_t r[4], uint32_t addr) {
    asm volatile("ldmatrix.sync.aligned.m8n8.x4.shared.b16 {%0,%1,%2,%3}, [%4];"
                 : "=r"(r[0]), "=r"(r[1]), "=r"(r[2]), "=r"(r[3]) : "r"(addr));
}

__device__ __forceinline__ void ldsm_x4t(uint32_t r[4], uint32_t addr) {
    asm volatile("ldmatrix.sync.aligned.m8n8.x4.trans.shared.b16 {%0,%1,%2,%3}, [%4];"
                 : "=r"(r[0]), "=r"(r[1]), "=r"(r[2]), "=r"(r[3]) : "r"(addr));
}

__device__ __forceinline__ void cp16(uint32_t dst_smem, const void* src) {
    asm volatile("cp.async.cg.shared.global [%0], [%1], 16;\n"
                 :: "r"(dst_smem), "l"(src));
}
#define CP_COMMIT()  asm volatile("cp.async.commit_group;\n" ::: "memory")
#define CP_WAIT(n)   asm volatile("cp.async.wait_group %0;\n" :: "n"(n) : "memory")

// ---------------- fp32 -> bf16 conversion (vectorized x4) ----------------
__global__ void k_cvt(const float4* __restrict__ src, uint2* __restrict__ dst)
{
    int i = blockIdx.x * 256 + threadIdx.x;
    float4 v = src[i];
    __nv_bfloat162 lo = __floats2bfloat162_rn(v.x, v.y);
    __nv_bfloat162 hi = __floats2bfloat162_rn(v.z, v.w);
    uint2 o;
    o.x = *(uint32_t*)&lo;
    o.y = *(uint32_t*)&hi;
    dst[i] = o;
}

// ---------------- w_eff / b_eff ----------------
__global__ void k_weff(const float* __restrict__ cur_w, const float* __restrict__ cur_b,
                       const float* __restrict__ gate_w, const float* __restrict__ gate_b)
{
    int warp = threadIdx.x >> 5;
    int lane = threadIdx.x & 31;
    int k = blockIdx.x * 8 + warp;
    float s = 0.f;
#pragma unroll
    for (int i = 0; i < 8; i++)
        s += cur_w[(size_t)k * D_ + lane + 32 * i] * __ldg(&gate_w[lane + 32 * i]);
#pragma unroll
    for (int o = 16; o; o >>= 1) s += __shfl_xor_sync(0xffffffffu, s, o);
    if (lane == 0) g_weff[k] = s;

    if (blockIdx.x == 0 && warp == 0) {
        float t = 0.f;
#pragma unroll
        for (int i = 0; i < 8; i++)
            t += cur_b[lane + 32 * i] * __ldg(&gate_w[lane + 32 * i]);
#pragma unroll
        for (int o = 16; o; o >>= 1) t += __shfl_xor_sync(0xffffffffu, t, o);
        if (lane == 0) g_beff = t + gate_b[0];
    }
}

// ---------------- wc[row] = x.w_eff + b_eff ----------------
__global__ void k_wc(const float* __restrict__ x)
{
    int row  = blockIdx.x * 8 + (threadIdx.x >> 5);
    int lane = threadIdx.x & 31;
    const float* xr = x + (size_t)row * D_;
    float s = 0.f;
#pragma unroll
    for (int i = 0; i < 8; i++) s += xr[lane + 32 * i] * g_weff[lane + 32 * i];
#pragma unroll
    for (int o = 16; o; o >>= 1) s += __shfl_xor_sync(0xffffffffu, s, o);
    if (lane == 0) g_wc[row] = s + g_beff;
}

// ---------------- TF32 GEMM for H (output bf16): H = x@his_w + his_b
#define G_AS 36
#define G_BS 136
#define G_AW (128 * G_AS)
#define G_BW (32 * G_BS)
#define G_STG (G_AW + G_BW)

__global__ __launch_bounds__(256, 2) void k_gemm_tf32(
    const float* __restrict__ A, const float* __restrict__ Bm,
    const float* __restrict__ bias, __nv_bfloat16* __restrict__ C,
    int N, int K)
{
    extern __shared__ float sm[];
    const uint32_t smb = (uint32_t)__cvta_generic_to_shared(sm);
    const uint32_t* smu = (const uint32_t*)sm;

    const int tid  = threadIdx.x;
    const int lane = tid & 31;
    const int warp = tid >> 5;
    const int wm = (warp & 1) * 64;
    const int wn = (warp >> 1) * 32;
    const int g   = lane >> 2;
    const int tig = lane & 3;
    const int row0 = blockIdx.y * 128;
    const int col0 = blockIdx.x * 128;

    const int am = tid & 127;
    const int aq = (tid >> 7) * 16;
    const float* Ap = A + (size_t)(row0 + am) * K + aq;
    const int bk  = tid >> 5;
    const int bn4 = (tid & 31) * 4;
    const float* Bp = Bm + (size_t)bk * N + col0 + bn4;

    const int rowit = lane & 15;
    const int colw  = (lane & 16) ? 4 : 0;

    float4 acc[4][4];
#pragma unroll
    for (int mi = 0; mi < 4; mi++)
#pragma unroll
        for (int ni = 0; ni < 4; ni++) acc[mi][ni] = make_float4(0.f, 0.f, 0.f, 0.f);

    const int nk = K / 32;
    {
#pragma unroll
        for (int v = 0; v < 4; v++)
            cp16(smb + (uint32_t)(am * G_AS + aq + v * 4) * 4, Ap + v * 4);
#pragma unroll
        for (int v = 0; v < 4; v++)
            cp16(smb + (uint32_t)(G_AW + (bk + v * 8) * G_BS + bn4) * 4,
                 Bp + (size_t)(v * 8) * N);
        CP_COMMIT();
    }

    for (int kt = 0; kt < nk; kt++) {
        const int s = kt & 1;
        if (kt + 1 < nk) {
            uint32_t base = smb + (uint32_t)((s ^ 1) * G_STG) * 4;
            const int k0 = (kt + 1) * 32;
#pragma unroll
            for (int v = 0; v < 4; v++)
                cp16(base + (uint32_t)(am * G_AS + aq + v * 4) * 4, Ap + k0 + v * 4);
#pragma unroll
            for (int v = 0; v < 4; v++)
                cp16(base + (uint32_t)(G_AW + (bk + v * 8) * G_BS + bn4) * 4,
                     Bp + (size_t)(k0 + v * 8) * N);
            CP_COMMIT();
            CP_WAIT(1);
        } else {
            CP_WAIT(0);
        }
        __syncthreads();

        const uint32_t aBase = smb + (uint32_t)(s * G_STG + (wm + rowit) * G_AS + colw) * 4;
        const int bBase = s * G_STG + G_AW;
#pragma unroll
        for (int ks = 0; ks < 4; ks++) {
            uint32_t af[4][4];
#pragma unroll
            for (int mi = 0; mi < 4; mi++)
                ldsm_x4(af[mi], aBase + (uint32_t)(mi * 16 * G_AS * 4 + ks * 32));
            uint32_t bf[4][2];
#pragma unroll
            for (int ni = 0; ni < 4; ni++) {
                int c = wn + ni * 8 + g;
                bf[ni][0] = smu[bBase + (ks * 8 + tig) * G_BS + c];
                bf[ni][1] = smu[bBase + (ks * 8 + tig + 4) * G_BS + c];
            }
#pragma unroll
            for (int mi = 0; mi < 4; mi++)
#pragma unroll
                for (int ni = 0; ni < 4; ni++)
                    mma_tf32(acc[mi][ni], af[mi], bf[ni]);
        }
        __syncthreads();
    }

#pragma unroll
    for (int mi = 0; mi < 4; mi++) {
        int r = row0 + wm + mi * 16 + g;
#pragma unroll
        for (int ni = 0; ni < 4; ni++) {
            int c = col0 + wn + ni * 8 + tig * 2;
            float b0 = bias[c], b1 = bias[c + 1];
            __nv_bfloat162 v0 = __floats2bfloat162_rn(acc[mi][ni].x + b0, acc[mi][ni].y + b1);
            __nv_bfloat162 v1 = __floats2bfloat162_rn(acc[mi][ni].z + b0, acc[mi][ni].w + b1);
            *(__nv_bfloat162*)(C + (size_t)r * N + c) = v0;
            *(__nv_bfloat162*)(C + (size_t)(r + 8) * N + c) = v1;
        }
    }
}

// ---------------- BF16 GEMM for logits: L = Hbf @ wlbf + wl_b, + fused stats
// block 128x128, 8 warps (2m x 4n), warp tile 64x32, K-tile 32 (2 ks of k16).
// A smem [m][k] stride 40 bf16 (80B), B smem [k][n] stride 136 bf16 (272B).
#define L_ABYTES (128 * 80)     // 10240
#define L_BBYTES (32 * 272)     // 8704
#define L_STGB (L_ABYTES + L_BBYTES)

__global__ __launch_bounds__(256, 2) void k_gemm_bf16(
    const __nv_bfloat16* __restrict__ A, const __nv_bfloat16* __restrict__ Bm,
    const float* __restrict__ bias, __nv_bfloat16* __restrict__ C,
    float* __restrict__ pmax, float* __restrict__ psum)
{
    extern __shared__ float sm[];
    const uint32_t smb = (uint32_t)__cvta_generic_to_shared(sm);

    const int tid  = threadIdx.x;
    const int lane = tid & 31;
    const int warp = tid >> 5;
    const int wm = (warp & 1) * 64;
    const int wn = (warp >> 1) * 32;
    const int wcol = warp >> 1;
    const int g   = lane >> 2;
    const int tig = lane & 3;
    const int row0 = blockIdx.y * 128;
    const int col0 = blockIdx.x * 128;

    // loaders: A 512 chunks (128 rows x 4), B 512 chunks (32 rows x 16)
    const int ar = tid >> 1;               // pairs: 2 ids per thread via i-loop
    const int rowit = lane & 15;
    const int colb  = (lane & 16) ? 16 : 0;

    float4 acc[4][4];
#pragma unroll
    for (int mi = 0; mi < 4; mi++)
#pragma unroll
        for (int ni = 0; ni < 4; ni++) acc[mi][ni] = make_float4(0.f, 0.f, 0.f, 0.f);

    // stage-0 loads
    {
#pragma unroll
        for (int i = 0; i < 2; i++) {
            int id = tid + i * 256;
            int rw = id >> 2, ch = id & 3;
            cp16(smb + (uint32_t)(rw * 80 + ch * 16),
                 A + (size_t)(row0 + rw) * 256 + ch * 8);
            int brw = id >> 4, bch = id & 15;
            cp16(smb + (uint32_t)(L_ABYTES + brw * 272 + bch * 16),
                 Bm + (size_t)brw * 2048 + col0 + bch * 8);
        }
        CP_COMMIT();
    }

#pragma unroll 2
    for (int kt = 0; kt < 8; kt++) {
        const int s = kt & 1;
        if (kt < 7) {
            uint32_t base = smb + (uint32_t)((s ^ 1) * L_STGB);
            const int k0 = (kt + 1) * 32;
#pragma unroll
            for (int i = 0; i < 2; i++) {
                int id = tid + i * 256;
                int rw = id >> 2, ch = id & 3;
                cp16(base + (uint32_t)(rw * 80 + ch * 16),
                     A + (size_t)(row0 + rw) * 256 + k0 + ch * 8);
                int brw = id >> 4, bch = id & 15;
                cp16(base + (uint32_t)(L_ABYTES + brw * 272 + bch * 16),
                     Bm + (size_t)(k0 + brw) * 2048 + col0 + bch * 8);
            }
            CP_COMMIT();
            CP_WAIT(1);
        } else {
            CP_WAIT(0);
        }
        __syncthreads();

        const uint32_t aB = smb + (uint32_t)(s * L_STGB + (wm + rowit) * 80 + colb);
        const uint32_t bB = smb + (uint32_t)(s * L_STGB + L_ABYTES + rowit * 272 + colb + wn * 2);
#pragma unroll
        for (int ks = 0; ks < 2; ks++) {
            uint32_t af[4][4];
#pragma unroll
            for (int mi = 0; mi < 4; mi++)
                ldsm_x4(af[mi], aB + (uint32_t)(mi * 16 * 80 + ks * 32));
#pragma unroll
            for (int nj = 0; nj < 2; nj++) {
                uint32_t bq[4];
                ldsm_x4t(bq, bB + (uint32_t)(ks * 16 * 272 + nj * 32));
#pragma unroll
                for (int mi = 0; mi < 4; mi++) {
                    mma_bf16(acc[mi][nj * 2],     af[mi], bq[0], bq[1]);
                    mma_bf16(acc[mi][nj * 2 + 1], af[mi], bq[2], bq[3]);
                }
            }
        }
        __syncthreads();
    }

    // bias add (stats need biased logits)
#pragma unroll
    for (int ni = 0; ni < 4; ni++) {
        int c = col0 + wn + ni * 8 + tig * 2;
        float b0 = bias[c], b1 = bias[c + 1];
#pragma unroll
        for (int mi = 0; mi < 4; mi++) {
            acc[mi][ni].x += b0; acc[mi][ni].y += b1;
            acc[mi][ni].z += b0; acc[mi][ni].w += b1;
        }
    }

    // store bf16 logits
#pragma unroll
    for (int mi = 0; mi < 4; mi++) {
        int r = row0 + wm + mi * 16 + g;
#pragma unroll
        for (int ni = 0; ni < 4; ni++) {
            int c = col0 + wn + ni * 8 + tig * 2;
            __nv_bfloat162 v0 = __floats2bfloat162_rn(acc[mi][ni].x, acc[mi][ni].y);
            __nv_bfloat162 v1 = __floats2bfloat162_rn(acc[mi][ni].z, acc[mi][ni].w);
            *(__nv_bfloat162*)(C + (size_t)r * 2048 + c) = v0;
            *(__nv_bfloat162*)(C + (size_t)(r + 8) * 2048 + c) = v1;
        }
    }

    // fused softmax partial stats over this block's 128 columns
    {
        float* red_m = sm;          // [128][4]
        float* red_s = sm + 512;    // [128][4]
#pragma unroll
        for (int mi = 0; mi < 4; mi++) {
            float m1 = -1e30f, m2 = -1e30f;
#pragma unroll
            for (int ni = 0; ni < 4; ni++) {
                m1 = fmaxf(m1, fmaxf(acc[mi][ni].x, acc[mi][ni].y));
                m2 = fmaxf(m2, fmaxf(acc[mi][ni].z, acc[mi][ni].w));
            }
            m1 = fmaxf(m1, __shfl_xor_sync(0xffffffffu, m1, 1));
            m1 = fmaxf(m1, __shfl_xor_sync(0xffffffffu, m1, 2));
            m2 = fmaxf(m2, __shfl_xor_sync(0xffffffffu, m2, 1));
            m2 = fmaxf(m2, __shfl_xor_sync(0xffffffffu, m2, 2));
            float s1 = 0.f, s2 = 0.f;
#pragma unroll
            for (int ni = 0; ni < 4; ni++) {
                s1 += __expf(acc[mi][ni].x - m1) + __expf(acc[mi][ni].y - m1);
                s2 += __expf(acc[mi][ni].z - m2) + __expf(acc[mi][ni].w - m2);
            }
            s1 += __shfl_xor_sync(0xffffffffu, s1, 1);
            s1 += __shfl_xor_sync(0xffffffffu, s1, 2);
            s2 += __shfl_xor_sync(0xffffffffu, s2, 1);
            s2 += __shfl_xor_sync(0xffffffffu, s2, 2);
            if (tig == 0) {
                int rb1 = wm + mi * 16 + g;
                red_m[rb1 * 4 + wcol] = m1;  red_s[rb1 * 4 + wcol] = s1;
                red_m[(rb1 + 8) * 4 + wcol] = m2;  red_s[(rb1 + 8) * 4 + wcol] = s2;
            }
        }
        __syncthreads();
        if (tid < 128) {
            float M = -1e30f;
#pragma unroll
            for (int j = 0; j < 4; j++) M = fmaxf(M, red_m[tid * 4 + j]);
            float S = 0.f;
#pragma unroll
            for (int j = 0; j < 4; j++)
                S += red_s[tid * 4 + j] * __expf(red_m[tid * 4 + j] - M);
            size_t idx = (size_t)(row0 + tid) * 16 + blockIdx.x;
            pmax[idx] = M;
            psum[idx] = S;
        }
    }
}

// ---------------- combine partials ----------------
__global__ void k_rowstat2()
{
    int row = blockIdx.x * 256 + threadIdx.x;
    const float* pm = g_pmax + (size_t)row * 16;
    const float* ps = g_psum + (size_t)row * 16;
    float M = -1e30f;
#pragma unroll
    for (int j = 0; j < 16; j++) M = fmaxf(M, pm[j]);
    float S = 0.f;
#pragma unroll
    for (int j = 0; j < 16; j++) S += ps[j] * __expf(pm[j] - M);
    g_rowoff[row] = M + __logf(S);
}

// ---------------- BF16 agg: agg = tril(softmax) @ x
// block 64 rows x 256 cols, 8 warps (2m x 4n), warp tile 32x64, K-tile 32.
// A (exp) [m=64][k=32] bf16 stride 40 (80B); B (x) [k=32][n=256] bf16 stride 264 (528B).
__global__ __launch_bounds__(256, 2) void k_agg_bf16()
{
    __shared__ __align__(16) char AsB[64 * 80];     //  5120 B
    __shared__ __align__(16) char BsB[32 * 528];    // 16896 B

    const uint32_t asb = (uint32_t)__cvta_generic_to_shared(AsB);
    const uint32_t bsb = (uint32_t)__cvta_generic_to_shared(BsB);

    const int b  = blockIdx.z;
    const int p0 = blockIdx.x * 64;
    const int tid  = threadIdx.x;
    const int lane = tid & 31;
    const int warp = tid >> 5;
    const int wm = (warp & 1) * 32;
    const int wn = (warp >> 1) * 64;
    const int g   = lane >> 2;
    const int tig = lane & 3;

    const int ar  = tid >> 2;              // 0..63
    const int ac8 = (tid & 3) * 8;
    const int prow = p0 + ar;
    const float off = g_rowoff[b * P_ + prow];
    const __nv_bfloat16* Lp = g_logbf + (size_t)(b * P_ + prow) * P_ + ac8;
    const __nv_bfloat16* xb = g_xbf + (size_t)b * P_ * D_;

    const int rowit = lane & 15;
    const int colb  = (lane & 16) ? 16 : 0;

    float4 acc[2][8];
#pragma unroll
    for (int mi = 0; mi < 2; mi++)
#pragma unroll
        for (int ni = 0; ni < 8; ni++) acc[mi][ni] = make_float4(0.f, 0.f, 0.f, 0.f);

    const int nkt = (p0 + 64) / 32;
    uint4 raw = *(const uint4*)(Lp);

    for (int kt = 0; kt < nkt; kt++) {
        const int k0 = kt * 32;
        __syncthreads();   // previous tile consumed

        // exp + mask + cvt bf16 + store A tile
        {
            const __nv_bfloat162* h = (const __nv_bfloat162*)&raw;
            float2 f0 = __bfloat1622float2(h[0]);
            float2 f1 = __bfloat1622float2(h[1]);
            float2 f2 = __bfloat1622float2(h[2]);
            float2 f3 = __bfloat1622float2(h[3]);
            int kq = k0 + ac8;
            float e0 = (kq     <= prow) ? __expf(f0.x - off) : 0.f;
            float e1 = (kq + 1 <= prow) ? __expf(f0.y - off) : 0.f;
            float e2 = (kq + 2 <= prow) ? __expf(f1.x - off) : 0.f;
            float e3 = (kq + 3 <= prow) ? __expf(f1.y - off) : 0.f;
            float e4 = (kq + 4 <= prow) ? __expf(f2.x - off) : 0.f;
            float e5 = (kq + 5 <= prow) ? __expf(f2.y - off) : 0.f;
            float e6 = (kq + 6 <= prow) ? __expf(f3.x - off) : 0.f;
            float e7 = (kq + 7 <= prow) ? __expf(f3.y - off) : 0.f;
            __nv_bfloat162 p0b = __floats2bfloat162_rn(e0, e1);
            __nv_bfloat162 p1b = __floats2bfloat162_rn(e2, e3);
            __nv_bfloat162 p2b = __floats2bfloat162_rn(e4, e5);
            __nv_bfloat162 p3b = __floats2bfloat162_rn(e6, e7);
            uint4 pk;
            pk.x = *(uint32_t*)&p0b; pk.y = *(uint32_t*)&p1b;
            pk.z = *(uint32_t*)&p2b; pk.w = *(uint32_t*)&p3b;
            *(uint4*)(AsB + ar * 80 + ac8 * 2) = pk;
        }

        // cp.async x tile [k=32][n=256] bf16
#pragma unroll
        for (int t = 0; t < 4; t++) {
            int id = tid + t * 256;
            int krow = id >> 5;
            int ch = id & 31;
            cp16(bsb + (uint32_t)(krow * 528 + ch * 16),
                 xb + (size_t)(k0 + krow) * D_ + ch * 8);
        }
        CP_COMMIT();

        if (kt + 1 < nkt) raw = *(const uint4*)(Lp + k0 + 32);

        CP_WAIT(0);
        __syncthreads();

        const uint32_t aB = asb + (uint32_t)((wm + rowit) * 80 + colb);
        const uint32_t bB = bsb + (uint32_t)(rowit * 528 + colb + wn * 2);
#pragma unroll
        for (int ks = 0; ks < 2; ks++) {
            uint32_t af[2][4];
#pragma unroll
            for (int mi = 0; mi < 2; mi++)
                ldsm_x4(af[mi], aB + (uint32_t)(mi * 16 * 80 + ks * 32));
#pragma unroll
            for (int nj = 0; nj < 4; nj++) {
                uint32_t bq[4];
                ldsm_x4t(bq, bB + (uint32_t)(ks * 16 * 528 + nj * 32));
#pragma unroll
                for (int mi = 0; mi < 2; mi++) {
                    mma_bf16(acc[mi][nj * 2],     af[mi], bq[0], bq[1]);
                    mma_bf16(acc[mi][nj * 2 + 1], af[mi], bq[2], bq[3]);
                }
            }
        }
    }

#pragma unroll
    for (int mi = 0; mi < 2; mi++) {
        int r = p0 + wm + mi * 16 + g;
#pragma unroll
        for (int ni = 0; ni < 8; ni++) {
            int c = wn + ni * 8 + tig * 2;
            *(float2*)(g_agg + (size_t)(b * P_ + r) * D_ + c) =
                make_float2(acc[mi][ni].x, acc[mi][ni].y);
            *(float2*)(g_agg + (size_t)(b * P_ + r + 8) * D_ + c) =
                make_float2(acc[mi][ni].z, acc[mi][ni].w);
        }
    }
}

// ---------------- out = LN(agg@mlp_w + mlp_b + wc*x) * ln_g + ln_b
__global__ __launch_bounds__(256) void k_final(
    const float* __restrict__ x, const float* __restrict__ mlp_w,
    const float* __restrict__ mlp_b, const float* __restrict__ ln_g,
    const float* __restrict__ ln_b, float* __restrict__ out)
{
    const int row0 = blockIdx.x * 32;
    const int tid = threadIdx.x;
    const int tx  = tid & 31;
    const int ty  = tid >> 5;

    __shared__ float As[16][36];
    __shared__ float Bs[16][256];
    __shared__ float s_mb[256], s_g[256], s_b[256];

    s_mb[tid] = mlp_b[tid];
    s_g[tid]  = ln_g[tid];
    s_b[tid]  = ln_b[tid];

    const int ar = tid >> 3;
    const int ac = (tid & 7) * 2;
    const float* Ap = g_agg + (size_t)(row0 + ar) * D_ + ac;

    float acc[4][8];
#pragma unroll
    for (int i = 0; i < 4; i++)
#pragma unroll
        for (int j = 0; j < 8; j++) acc[i][j] = 0.f;

    __syncthreads();
    for (int k0 = 0; k0 < D_; k0 += 16) {
        float2 a2 = *(const float2*)(Ap + k0);
        float4 bv[4];
#pragma unroll
        for (int t = 0; t < 4; t++) {
            int idx4 = tid + t * 256;
            int br = idx4 >> 6;
            int bc = (idx4 & 63) * 4;
            bv[t] = *(const float4*)(mlp_w + (size_t)(k0 + br) * D_ + bc);
        }
        As[ac][ar] = a2.x;
        As[ac + 1][ar] = a2.y;
#pragma unroll
        for (int t = 0; t < 4; t++) {
            int idx4 = tid + t * 256;
            int br = idx4 >> 6;
            int bc = (idx4 & 63) * 4;
            *(float4*)&Bs[br][bc] = bv[t];
        }
        __syncthreads();
#pragma unroll
        for (int k = 0; k < 16; k++) {
            float4 a  = *(const float4*)&As[k][ty * 4];
            float4 b0 = *(const float4*)&Bs[k][tx * 4];
            float4 b1 = *(const float4*)&Bs[k][tx * 4 + 128];
            float av[4] = {a.x, a.y, a.z, a.w};
            float bb[8] = {b0.x, b0.y, b0.z, b0.w, b1.x, b1.y, b1.z, b1.w};
#pragma unroll
            for (int i = 0; i < 4; i++)
#pragma unroll
                for (int j = 0; j < 8; j++)
                    acc[i][j] += av[i] * bb[j];
        }
        __syncthreads();
    }

#pragma unroll
    for (int i = 0; i < 4; i++) {
        int r = row0 + ty * 4 + i;
        float w = g_wc[r];
        const float* xr = x + (size_t)r * D_;
        float4 x0 = *(const float4*)(xr + tx * 4);
        float4 x1 = *(const float4*)(xr + tx * 4 + 128);
        float xv[8] = {x0.x, x0.y, x0.z, x0.w, x1.x, x1.y, x1.z, x1.w};
        float h[8];
#pragma unroll
        for (int j = 0; j < 8; j++) {
            int c = (j < 4) ? (tx * 4 + j) : (tx * 4 + 128 + (j - 4));
            h[j] = acc[i][j] + s_mb[c] + w * xv[j];
        }
        float s = 0.f;
#pragma unroll
        for (int j = 0; j < 8; j++) s += h[j];
#pragma unroll
        for (int o = 16; o; o >>= 1) s += __shfl_xor_sync(0xffffffffu, s, o);
        float mu = s * (1.0f / 256.0f);
        float d = 0.f;
#pragma unroll
        for (int j = 0; j < 8; j++) { float t = h[j] - mu; d += t * t; }
#pragma unroll
        for (int o = 16; o; o >>= 1) d += __shfl_xor_sync(0xffffffffu, d, o);
        float inv = rsqrtf(d * (1.0f / 256.0f) + 1e-5f);

        float y[8];
#pragma unroll
        for (int j = 0; j < 8; j++) {
            int c = (j < 4) ? (tx * 4 + j) : (tx * 4 + 128 + (j - 4));
            y[j] = (h[j] - mu) * inv * s_g[c] + s_b[c];
        }
        *(float4*)(out + (size_t)r * D_ + tx * 4) = make_float4(y[0], y[1], y[2], y[3]);
        *(float4*)(out + (size_t)r * D_ + tx * 4 + 128) = make_float4(y[4], y[5], y[6], y[7]);
    }
}

// ---------------- launch ----------------
extern "C" void kernel_launch(void* const* d_in, const int* in_sizes, int n_in,
                              void* d_out, int out_size)
{
    const float* x      = (const float*)d_in[0];
    const float* mlp_w  = (const float*)d_in[1];
    const float* mlp_b  = (const float*)d_in[2];
    const float* his_w  = (const float*)d_in[3];
    const float* his_b  = (const float*)d_in[4];
    const float* cur_w  = (const float*)d_in[5];
    const float* cur_b  = (const float*)d_in[6];
    const float* wl_w   = (const float*)d_in[7];
    const float* wl_b   = (const float*)d_in[8];
    const float* gate_w = (const float*)d_in[9];
    const float* gate_b = (const float*)d_in[10];
    const float* ln_g   = (const float*)d_in[11];
    const float* ln_b   = (const float*)d_in[12];
    float* out = (float*)d_out;

    void *pHbf, *pLbf, *pXbf, *pWLbf, *pPM, *pPS;
    cudaGetSymbolAddress(&pHbf, g_Hbf);
    cudaGetSymbolAddress(&pLbf, g_logbf);
    cudaGetSymbolAddress(&pXbf, g_xbf);
    cudaGetSymbolAddress(&pWLbf, g_wlbf);
    cudaGetSymbolAddress(&pPM, g_pmax);
    cudaGetSymbolAddress(&pPS, g_psum);
    __nv_bfloat16* gHbf  = (__nv_bfloat16*)pHbf;
    __nv_bfloat16* gLbf  = (__nv_bfloat16*)pLbf;
    __nv_bfloat16* gXbf  = (__nv_bfloat16*)pXbf;
    __nv_bfloat16* gWLbf = (__nv_bfloat16*)pWLbf;
    float* gPM = (float*)pPM;
    float* gPS = (float*)pPS;

    const int tf32_smem = (G_STG * 2) * 4;   // 71680 bytes
    cudaFuncSetAttribute(k_gemm_tf32, cudaFuncAttributeMaxDynamicSharedMemorySize, tf32_smem);
    const int bf16_smem = L_STGB * 2;        // 37888 bytes
    cudaFuncSetAttribute(k_gemm_bf16, cudaFuncAttributeMaxDynamicSharedMemorySize, bf16_smem);

    // conversions
    k_cvt<<<(BP_ * D_ / 4) / 256, 256>>>((const float4*)x, (uint2*)gXbf);
    k_cvt<<<(D_ * P_ / 4) / 256, 256>>>((const float4*)wl_w, (uint2*)gWLbf);

    // gate precompute
    k_weff<<<D_ / 8, 256>>>(cur_w, cur_b, gate_w, gate_b);
    k_wc<<<BP_ / 8, 256>>>(x);

    // H = x @ his_w + his_b  (tf32, bf16 output)
    k_gemm_tf32<<<dim3(D_ / 128, BP_ / 128), 256, tf32_smem>>>(
        x, his_w, his_b, gHbf, D_, D_);
    // logits = Hbf @ wlbf + wl_b  (bf16 MMA, bf16 logits, fused stats)
    k_gemm_bf16<<<dim3(P_ / 128, BP_ / 128), 256, bf16_smem>>>(
        gHbf, gWLbf, wl_b, gLbf, gPM, gPS);
    // combine softmax offsets
    k_rowstat2<<<BP_ / 256, 256>>>();
    // agg = tril(softmax(logits)) @ x  (bf16 MMA)
    k_agg_bf16<<<dim3(P_ / 64, 1, B_), 256>>>();
    // out = LN(agg @ mlp_w + mlp_b + wc*x)
    k_final<<<BP_ / 32, 256>>>(x, mlp_w, mlp_b, ln_g, ln_b, out);
    // second output: origin
    cudaMemcpyAsync(out + (size_t)BP_ * D_, x,
                    (size_t)BP_ * D_ * sizeof(float),
                    cudaMemcpyDeviceToDevice);
}

// round 12
// speedup vs baseline: 2.0360x; 1.1874x over previous
#include <cuda_runtime.h>
#include <cuda_bf16.h>
#include <cstdint>
#include <cstddef>

#define B_  32
#define P_  2048
#define D_  256
#define BP_ (B_ * P_)   // 65536

// ---------------- device scratch ----------------
__device__ __nv_bfloat16 g_Hbf[(size_t)BP_ * D_];     // 32 MB  H in bf16
__device__ __nv_bfloat16 g_logbf[(size_t)BP_ * P_];   // 256 MB logits bf16
__device__ __nv_bfloat16 g_xmbf[(size_t)BP_ * D_];    // 32 MB  xm = x@mlp_w (bf16)
__device__ __nv_bfloat16 g_wlbf[(size_t)D_ * P_];     // 1 MB   wl_w bf16
__device__ float g_pmax[(size_t)BP_ * 16];
__device__ float g_psum[(size_t)BP_ * 16];
__device__ float g_rowoff[BP_];
__device__ float g_wc[BP_];
__device__ float g_weff[D_];
__device__ float g_beff;
__device__ float g_zero[D_];                          // stays zero (bias for xm gemm)

// ---------------- helpers ----------------
__device__ __forceinline__ void mma_tf32(float4& c, const uint32_t a[4], const uint32_t b[2]) {
    asm volatile(
        "mma.sync.aligned.m16n8k8.row.col.f32.tf32.tf32.f32 "
        "{%0,%1,%2,%3}, {%4,%5,%6,%7}, {%8,%9}, {%0,%1,%2,%3};\n"
        : "+f"(c.x), "+f"(c.y), "+f"(c.z), "+f"(c.w)
        : "r"(a[0]), "r"(a[1]), "r"(a[2]), "r"(a[3]),
          "r"(b[0]), "r"(b[1]));
}

__device__ __forceinline__ void mma_bf16(float4& c, const uint32_t a[4],
                                         uint32_t b0, uint32_t b1) {
    asm volatile(
        "mma.sync.aligned.m16n8k16.row.col.f32.bf16.bf16.f32 "
        "{%0,%1,%2,%3}, {%4,%5,%6,%7}, {%8,%9}, {%0,%1,%2,%3};\n"
        : "+f"(c.x), "+f"(c.y), "+f"(c.z), "+f"(c.w)
        : "r"(a[0]), "r"(a[1]), "r"(a[2]), "r"(a[3]), "r"(b0), "r"(b1));
}

__device__ __forceinline__ void ldsm_x4(uint32_t r[4], uint32_t addr) {
    asm volatile("ldmatrix.sync.aligned.m8n8.x4.shared.b16 {%0,%1,%2,%3}, [%4];"
                 : "=r"(r[0]), "=r"(r[1]), "=r"(r[2]), "=r"(r[3]) : "r"(addr));
}

__device__ __forceinline__ void ldsm_x4t(uint32_t r[4], uint32_t addr) {
    asm volatile("ldmatrix.sync.aligned.m8n8.x4.trans.shared.b16 {%0,%1,%2,%3}, [%4];"
                 : "=r"(r[0]), "=r"(r[1]), "=r"(r[2]), "=r"(r[3]) : "r"(addr));
}

__device__ __forceinline__ void cp16(uint32_t dst_smem, const void* src) {
    asm volatile("cp.async.cg.shared.global [%0], [%1], 16;\n"
                 :: "r"(dst_smem), "l"(src));
}
#define CP_COMMIT()  asm volatile("cp.async.commit_group;\n" ::: "memory")
#define CP_WAIT(n)   asm volatile("cp.async.wait_group %0;\n" :: "n"(n) : "memory")

// ---------------- fp32 -> bf16 conversion (vectorized x4) ----------------
__global__ void k_cvt(const float4* __restrict__ src, uint2* __restrict__ dst)
{
    int i = blockIdx.x * 256 + threadIdx.x;
    float4 v = src[i];
    __nv_bfloat162 lo = __floats2bfloat162_rn(v.x, v.y);
    __nv_bfloat162 hi = __floats2bfloat162_rn(v.z, v.w);
    uint2 o;
    o.x = *(uint32_t*)&lo;
    o.y = *(uint32_t*)&hi;
    dst[i] = o;
}

// ---------------- w_eff / b_eff ----------------
__global__ void k_weff(const float* __restrict__ cur_w, const float* __restrict__ cur_b,
                       const float* __restrict__ gate_w, const float* __restrict__ gate_b)
{
    int warp = threadIdx.x >> 5;
    int lane = threadIdx.x & 31;
    int k = blockIdx.x * 8 + warp;
    float s = 0.f;
#pragma unroll
    for (int i = 0; i < 8; i++)
        s += cur_w[(size_t)k * D_ + lane + 32 * i] * __ldg(&gate_w[lane + 32 * i]);
#pragma unroll
    for (int o = 16; o; o >>= 1) s += __shfl_xor_sync(0xffffffffu, s, o);
    if (lane == 0) g_weff[k] = s;

    if (blockIdx.x == 0 && warp == 0) {
        float t = 0.f;
#pragma unroll
        for (int i = 0; i < 8; i++)
            t += cur_b[lane + 32 * i] * __ldg(&gate_w[lane + 32 * i]);
#pragma unroll
        for (int o = 16; o; o >>= 1) t += __shfl_xor_sync(0xffffffffu, t, o);
        if (lane == 0) g_beff = t + gate_b[0];
    }
}

// ---------------- wc[row] = x.w_eff + b_eff ----------------
__global__ void k_wc(const float* __restrict__ x)
{
    int row  = blockIdx.x * 8 + (threadIdx.x >> 5);
    int lane = threadIdx.x & 31;
    const float* xr = x + (size_t)row * D_;
    float s = 0.f;
#pragma unroll
    for (int i = 0; i < 8; i++) s += xr[lane + 32 * i] * g_weff[lane + 32 * i];
#pragma unroll
    for (int o = 16; o; o >>= 1) s += __shfl_xor_sync(0xffffffffu, s, o);
    if (lane == 0) g_wc[row] = s + g_beff;
}

// ---------------- TF32 GEMM (fp32 in, bf16 out): C = A@B + bias
#define G_AS 36
#define G_BS 136
#define G_AW (128 * G_AS)
#define G_BW (32 * G_BS)
#define G_STG (G_AW + G_BW)

__global__ __launch_bounds__(256, 2) void k_gemm_tf32(
    const float* __restrict__ A, const float* __restrict__ Bm,
    const float* __restrict__ bias, __nv_bfloat16* __restrict__ C,
    int N, int K)
{
    extern __shared__ float sm[];
    const uint32_t smb = (uint32_t)__cvta_generic_to_shared(sm);
    const uint32_t* smu = (const uint32_t*)sm;

    const int tid  = threadIdx.x;
    const int lane = tid & 31;
    const int warp = tid >> 5;
    const int wm = (warp & 1) * 64;
    const int wn = (warp >> 1) * 32;
    const int g   = lane >> 2;
    const int tig = lane & 3;
    const int row0 = blockIdx.y * 128;
    const int col0 = blockIdx.x * 128;

    const int am = tid & 127;
    const int aq = (tid >> 7) * 16;
    const float* Ap = A + (size_t)(row0 + am) * K + aq;
    const int bk  = tid >> 5;
    const int bn4 = (tid & 31) * 4;
    const float* Bp = Bm + (size_t)bk * N + col0 + bn4;

    const int rowit = lane & 15;
    const int colw  = (lane & 16) ? 4 : 0;

    float4 acc[4][4];
#pragma unroll
    for (int mi = 0; mi < 4; mi++)
#pragma unroll
        for (int ni = 0; ni < 4; ni++) acc[mi][ni] = make_float4(0.f, 0.f, 0.f, 0.f);

    const int nk = K / 32;
    {
#pragma unroll
        for (int v = 0; v < 4; v++)
            cp16(smb + (uint32_t)(am * G_AS + aq + v * 4) * 4, Ap + v * 4);
#pragma unroll
        for (int v = 0; v < 4; v++)
            cp16(smb + (uint32_t)(G_AW + (bk + v * 8) * G_BS + bn4) * 4,
                 Bp + (size_t)(v * 8) * N);
        CP_COMMIT();
    }

    for (int kt = 0; kt < nk; kt++) {
        const int s = kt & 1;
        if (kt + 1 < nk) {
            uint32_t base = smb + (uint32_t)((s ^ 1) * G_STG) * 4;
            const int k0 = (kt + 1) * 32;
#pragma unroll
            for (int v = 0; v < 4; v++)
                cp16(base + (uint32_t)(am * G_AS + aq + v * 4) * 4, Ap + k0 + v * 4);
#pragma unroll
            for (int v = 0; v < 4; v++)
                cp16(base + (uint32_t)(G_AW + (bk + v * 8) * G_BS + bn4) * 4,
                     Bp + (size_t)(k0 + v * 8) * N);
            CP_COMMIT();
            CP_WAIT(1);
        } else {
            CP_WAIT(0);
        }
        __syncthreads();

        const uint32_t aBase = smb + (uint32_t)(s * G_STG + (wm + rowit) * G_AS + colw) * 4;
        const int bBase = s * G_STG + G_AW;
#pragma unroll
        for (int ks = 0; ks < 4; ks++) {
            uint32_t af[4][4];
#pragma unroll
            for (int mi = 0; mi < 4; mi++)
                ldsm_x4(af[mi], aBase + (uint32_t)(mi * 16 * G_AS * 4 + ks * 32));
            uint32_t bf[4][2];
#pragma unroll
            for (int ni = 0; ni < 4; ni++) {
                int c = wn + ni * 8 + g;
                bf[ni][0] = smu[bBase + (ks * 8 + tig) * G_BS + c];
                bf[ni][1] = smu[bBase + (ks * 8 + tig + 4) * G_BS + c];
            }
#pragma unroll
            for (int mi = 0; mi < 4; mi++)
#pragma unroll
                for (int ni = 0; ni < 4; ni++)
                    mma_tf32(acc[mi][ni], af[mi], bf[ni]);
        }
        __syncthreads();
    }

#pragma unroll
    for (int mi = 0; mi < 4; mi++) {
        int r = row0 + wm + mi * 16 + g;
#pragma unroll
        for (int ni = 0; ni < 4; ni++) {
            int c = col0 + wn + ni * 8 + tig * 2;
            float b0 = bias[c], b1 = bias[c + 1];
            __nv_bfloat162 v0 = __floats2bfloat162_rn(acc[mi][ni].x + b0, acc[mi][ni].y + b1);
            __nv_bfloat162 v1 = __floats2bfloat162_rn(acc[mi][ni].z + b0, acc[mi][ni].w + b1);
            *(__nv_bfloat162*)(C + (size_t)r * N + c) = v0;
            *(__nv_bfloat162*)(C + (size_t)(r + 8) * N + c) = v1;
        }
    }
}

// ---------------- BF16 GEMM for logits: L = Hbf @ wlbf + wl_b, + fused stats
#define L_ABYTES (128 * 80)     // 10240
#define L_BBYTES (32 * 272)     // 8704
#define L_STGB (L_ABYTES + L_BBYTES)

__global__ __launch_bounds__(256, 2) void k_gemm_bf16(
    const __nv_bfloat16* __restrict__ A, const __nv_bfloat16* __restrict__ Bm,
    const float* __restrict__ bias, __nv_bfloat16* __restrict__ C,
    float* __restrict__ pmax, float* __restrict__ psum)
{
    extern __shared__ float sm[];
    const uint32_t smb = (uint32_t)__cvta_generic_to_shared(sm);

    const int tid  = threadIdx.x;
    const int lane = tid & 31;
    const int warp = tid >> 5;
    const int wm = (warp & 1) * 64;
    const int wn = (warp >> 1) * 32;
    const int wcol = warp >> 1;
    const int g   = lane >> 2;
    const int tig = lane & 3;
    const int row0 = blockIdx.y * 128;
    const int col0 = blockIdx.x * 128;

    const int rowit = lane & 15;
    const int colb  = (lane & 16) ? 16 : 0;

    float4 acc[4][4];
#pragma unroll
    for (int mi = 0; mi < 4; mi++)
#pragma unroll
        for (int ni = 0; ni < 4; ni++) acc[mi][ni] = make_float4(0.f, 0.f, 0.f, 0.f);

    {
#pragma unroll
        for (int i = 0; i < 2; i++) {
            int id = tid + i * 256;
            int rw = id >> 2, ch = id & 3;
            cp16(smb + (uint32_t)(rw * 80 + ch * 16),
                 A + (size_t)(row0 + rw) * 256 + ch * 8);
            int brw = id >> 4, bch = id & 15;
            cp16(smb + (uint32_t)(L_ABYTES + brw * 272 + bch * 16),
                 Bm + (size_t)brw * 2048 + col0 + bch * 8);
        }
        CP_COMMIT();
    }

#pragma unroll 2
    for (int kt = 0; kt < 8; kt++) {
        const int s = kt & 1;
        if (kt < 7) {
            uint32_t base = smb + (uint32_t)((s ^ 1) * L_STGB);
            const int k0 = (kt + 1) * 32;
#pragma unroll
            for (int i = 0; i < 2; i++) {
                int id = tid + i * 256;
                int rw = id >> 2, ch = id & 3;
                cp16(base + (uint32_t)(rw * 80 + ch * 16),
                     A + (size_t)(row0 + rw) * 256 + k0 + ch * 8);
                int brw = id >> 4, bch = id & 15;
                cp16(base + (uint32_t)(L_ABYTES + brw * 272 + bch * 16),
                     Bm + (size_t)(k0 + brw) * 2048 + col0 + bch * 8);
            }
            CP_COMMIT();
            CP_WAIT(1);
        } else {
            CP_WAIT(0);
        }
        __syncthreads();

        const uint32_t aB = smb + (uint32_t)(s * L_STGB + (wm + rowit) * 80 + colb);
        const uint32_t bB = smb + (uint32_t)(s * L_STGB + L_ABYTES + rowit * 272 + colb + wn * 2);
#pragma unroll
        for (int ks = 0; ks < 2; ks++) {
            uint32_t af[4][4];
#pragma unroll
            for (int mi = 0; mi < 4; mi++)
                ldsm_x4(af[mi], aB + (uint32_t)(mi * 16 * 80 + ks * 32));
#pragma unroll
            for (int nj = 0; nj < 2; nj++) {
                uint32_t bq[4];
                ldsm_x4t(bq, bB + (uint32_t)(ks * 16 * 272 + nj * 32));
#pragma unroll
                for (int mi = 0; mi < 4; mi++) {
                    mma_bf16(acc[mi][nj * 2],     af[mi], bq[0], bq[1]);
                    mma_bf16(acc[mi][nj * 2 + 1], af[mi], bq[2], bq[3]);
                }
            }
        }
        __syncthreads();
    }

#pragma unroll
    for (int ni = 0; ni < 4; ni++) {
        int c = col0 + wn + ni * 8 + tig * 2;
        float b0 = bias[c], b1 = bias[c + 1];
#pragma unroll
        for (int mi = 0; mi < 4; mi++) {
            acc[mi][ni].x += b0; acc[mi][ni].y += b1;
            acc[mi][ni].z += b0; acc[mi][ni].w += b1;
        }
    }

#pragma unroll
    for (int mi = 0; mi < 4; mi++) {
        int r = row0 + wm + mi * 16 + g;
#pragma unroll
        for (int ni = 0; ni < 4; ni++) {
            int c = col0 + wn + ni * 8 + tig * 2;
            __nv_bfloat162 v0 = __floats2bfloat162_rn(acc[mi][ni].x, acc[mi][ni].y);
            __nv_bfloat162 v1 = __floats2bfloat162_rn(acc[mi][ni].z, acc[mi][ni].w);
            *(__nv_bfloat162*)(C + (size_t)r * 2048 + c) = v0;
            *(__nv_bfloat162*)(C + (size_t)(r + 8) * 2048 + c) = v1;
        }
    }

    {
        float* red_m = sm;          // [128][4]
        float* red_s = sm + 512;    // [128][4]
#pragma unroll
        for (int mi = 0; mi < 4; mi++) {
            float m1 = -1e30f, m2 = -1e30f;
#pragma unroll
            for (int ni = 0; ni < 4; ni++) {
                m1 = fmaxf(m1, fmaxf(acc[mi][ni].x, acc[mi][ni].y));
                m2 = fmaxf(m2, fmaxf(acc[mi][ni].z, acc[mi][ni].w));
            }
            m1 = fmaxf(m1, __shfl_xor_sync(0xffffffffu, m1, 1));
            m1 = fmaxf(m1, __shfl_xor_sync(0xffffffffu, m1, 2));
            m2 = fmaxf(m2, __shfl_xor_sync(0xffffffffu, m2, 1));
            m2 = fmaxf(m2, __shfl_xor_sync(0xffffffffu, m2, 2));
            float s1 = 0.f, s2 = 0.f;
#pragma unroll
            for (int ni = 0; ni < 4; ni++) {
                s1 += __expf(acc[mi][ni].x - m1) + __expf(acc[mi][ni].y - m1);
                s2 += __expf(acc[mi][ni].z - m2) + __expf(acc[mi][ni].w - m2);
            }
            s1 += __shfl_xor_sync(0xffffffffu, s1, 1);
            s1 += __shfl_xor_sync(0xffffffffu, s1, 2);
            s2 += __shfl_xor_sync(0xffffffffu, s2, 1);
            s2 += __shfl_xor_sync(0xffffffffu, s2, 2);
            if (tig == 0) {
                int rb1 = wm + mi * 16 + g;
                red_m[rb1 * 4 + wcol] = m1;  red_s[rb1 * 4 + wcol] = s1;
                red_m[(rb1 + 8) * 4 + wcol] = m2;  red_s[(rb1 + 8) * 4 + wcol] = s2;
            }
        }
        __syncthreads();
        if (tid < 128) {
            float M = -1e30f;
#pragma unroll
            for (int j = 0; j < 4; j++) M = fmaxf(M, red_m[tid * 4 + j]);
            float S = 0.f;
#pragma unroll
            for (int j = 0; j < 4; j++)
                S += red_s[tid * 4 + j] * __expf(red_m[tid * 4 + j] - M);
            size_t idx = (size_t)(row0 + tid) * 16 + blockIdx.x;
            pmax[idx] = M;
            psum[idx] = S;
        }
    }
}

// ---------------- combine partials ----------------
__global__ void k_rowstat2()
{
    int row = blockIdx.x * 256 + threadIdx.x;
    const float* pm = g_pmax + (size_t)row * 16;
    const float* ps = g_psum + (size_t)row * 16;
    float M = -1e30f;
#pragma unroll
    for (int j = 0; j < 16; j++) M = fmaxf(M, pm[j]);
    float S = 0.f;
#pragma unroll
    for (int j = 0; j < 16; j++) S += ps[j] * __expf(pm[j] - M);
    g_rowoff[row] = M + __logf(S);
}

// ---------------- BF16 agg + FULL FUSED EPILOGUE:
// acc = tril(softmax(logits)) @ xm  (= H_history - mlp_b)
// out = LN(acc + mlp_b + wc*x) * ln_g + ln_b   written directly.
__global__ __launch_bounds__(256, 2) void k_agg_bf16(
    const float* __restrict__ x, const float* __restrict__ mlp_b,
    const float* __restrict__ ln_g, const float* __restrict__ ln_b,
    float* __restrict__ out)
{
    __shared__ __align__(16) char AsB[64 * 80];     //  5120 B
    __shared__ __align__(16) char BsB[32 * 528];    // 16896 B
    __shared__ float red_s[64 * 4];
    __shared__ float red_q[64 * 4];
    __shared__ float s_mb[256], s_g[256], s_b[256];

    const uint32_t asb = (uint32_t)__cvta_generic_to_shared(AsB);
    const uint32_t bsb = (uint32_t)__cvta_generic_to_shared(BsB);

    const int b  = blockIdx.z;
    const int p0 = blockIdx.x * 64;
    const int tid  = threadIdx.x;
    const int lane = tid & 31;
    const int warp = tid >> 5;
    const int wm = (warp & 1) * 32;
    const int wn = (warp >> 1) * 64;
    const int wngrp = warp >> 1;
    const int g   = lane >> 2;
    const int tig = lane & 3;

    s_mb[tid] = mlp_b[tid];
    s_g[tid]  = ln_g[tid];
    s_b[tid]  = ln_b[tid];

    const int ar  = tid >> 2;              // 0..63
    const int ac8 = (tid & 3) * 8;
    const int prow = p0 + ar;
    const float off = g_rowoff[b * P_ + prow];
    const __nv_bfloat16* Lp = g_logbf + (size_t)(b * P_ + prow) * P_ + ac8;
    const __nv_bfloat16* xmb = g_xmbf + (size_t)b * P_ * D_;

    const int rowit = lane & 15;
    const int colb  = (lane & 16) ? 16 : 0;

    float4 acc[2][8];
#pragma unroll
    for (int mi = 0; mi < 2; mi++)
#pragma unroll
        for (int ni = 0; ni < 8; ni++) acc[mi][ni] = make_float4(0.f, 0.f, 0.f, 0.f);

    const int nkt = (p0 + 64) / 32;
    uint4 raw = *(const uint4*)(Lp);

    for (int kt = 0; kt < nkt; kt++) {
        const int k0 = kt * 32;
        __syncthreads();   // previous tile consumed (also covers s_mb init)

        {
            const __nv_bfloat162* h = (const __nv_bfloat162*)&raw;
            float2 f0 = __bfloat1622float2(h[0]);
            float2 f1 = __bfloat1622float2(h[1]);
            float2 f2 = __bfloat1622float2(h[2]);
            float2 f3 = __bfloat1622float2(h[3]);
            int kq = k0 + ac8;
            float e0 = (kq     <= prow) ? __expf(f0.x - off) : 0.f;
            float e1 = (kq + 1 <= prow) ? __expf(f0.y - off) : 0.f;
            float e2 = (kq + 2 <= prow) ? __expf(f1.x - off) : 0.f;
            float e3 = (kq + 3 <= prow) ? __expf(f1.y - off) : 0.f;
            float e4 = (kq + 4 <= prow) ? __expf(f2.x - off) : 0.f;
            float e5 = (kq + 5 <= prow) ? __expf(f2.y - off) : 0.f;
            float e6 = (kq + 6 <= prow) ? __expf(f3.x - off) : 0.f;
            float e7 = (kq + 7 <= prow) ? __expf(f3.y - off) : 0.f;
            __nv_bfloat162 p0b = __floats2bfloat162_rn(e0, e1);
            __nv_bfloat162 p1b = __floats2bfloat162_rn(e2, e3);
            __nv_bfloat162 p2b = __floats2bfloat162_rn(e4, e5);
            __nv_bfloat162 p3b = __floats2bfloat162_rn(e6, e7);
            uint4 pk;
            pk.x = *(uint32_t*)&p0b; pk.y = *(uint32_t*)&p1b;
            pk.z = *(uint32_t*)&p2b; pk.w = *(uint32_t*)&p3b;
            *(uint4*)(AsB + ar * 80 + ac8 * 2) = pk;
        }

#pragma unroll
        for (int t = 0; t < 4; t++) {
            int id = tid + t * 256;
            int krow = id >> 5;
            int ch = id & 31;
            cp16(bsb + (uint32_t)(krow * 528 + ch * 16),
                 xmb + (size_t)(k0 + krow) * D_ + ch * 8);
        }
        CP_COMMIT();

        if (kt + 1 < nkt) raw = *(const uint4*)(Lp + k0 + 32);

        CP_WAIT(0);
        __syncthreads();

        const uint32_t aB = asb + (uint32_t)((wm + rowit) * 80 + colb);
        const uint32_t bB = bsb + (uint32_t)(rowit * 528 + colb + wn * 2);
#pragma unroll
        for (int ks = 0; ks < 2; ks++) {
            uint32_t af[2][4];
#pragma unroll
            for (int mi = 0; mi < 2; mi++)
                ldsm_x4(af[mi], aB + (uint32_t)(mi * 16 * 80 + ks * 32));
#pragma unroll
            for (int nj = 0; nj < 4; nj++) {
                uint32_t bq[4];
                ldsm_x4t(bq, bB + (uint32_t)(ks * 16 * 528 + nj * 32));
#pragma unroll
                for (int mi = 0; mi < 2; mi++) {
                    mma_bf16(acc[mi][nj * 2],     af[mi], bq[0], bq[1]);
                    mma_bf16(acc[mi][nj * 2 + 1], af[mi], bq[2], bq[3]);
                }
            }
        }
    }

    // ===== fused epilogue: h = acc + mlp_b + wc*x; LN; write out =====
    float ssum[2][2] = {{0.f, 0.f}, {0.f, 0.f}};
    float qsum[2][2] = {{0.f, 0.f}, {0.f, 0.f}};
#pragma unroll
    for (int mi = 0; mi < 2; mi++) {
        int gr0 = b * P_ + p0 + wm + mi * 16 + g;
        int gr1 = gr0 + 8;
        float wc0 = g_wc[gr0], wc1 = g_wc[gr1];
        const float* xr0 = x + (size_t)gr0 * D_;
        const float* xr1 = x + (size_t)gr1 * D_;
#pragma unroll
        for (int ni = 0; ni < 8; ni++) {
            int c = wn + ni * 8 + tig * 2;
            float2 xv0 = *(const float2*)(xr0 + c);
            float2 xv1 = *(const float2*)(xr1 + c);
            acc[mi][ni].x += s_mb[c]     + wc0 * xv0.x;
            acc[mi][ni].y += s_mb[c + 1] + wc0 * xv0.y;
            acc[mi][ni].z += s_mb[c]     + wc1 * xv1.x;
            acc[mi][ni].w += s_mb[c + 1] + wc1 * xv1.y;
            ssum[mi][0] += acc[mi][ni].x + acc[mi][ni].y;
            ssum[mi][1] += acc[mi][ni].z + acc[mi][ni].w;
            qsum[mi][0] += acc[mi][ni].x * acc[mi][ni].x + acc[mi][ni].y * acc[mi][ni].y;
            qsum[mi][1] += acc[mi][ni].z * acc[mi][ni].z + acc[mi][ni].w * acc[mi][ni].w;
        }
    }
    // quad reduce (over tig) then cross-warp via smem
#pragma unroll
    for (int mi = 0; mi < 2; mi++)
#pragma unroll
        for (int hf = 0; hf < 2; hf++) {
            ssum[mi][hf] += __shfl_xor_sync(0xffffffffu, ssum[mi][hf], 1);
            ssum[mi][hf] += __shfl_xor_sync(0xffffffffu, ssum[mi][hf], 2);
            qsum[mi][hf] += __shfl_xor_sync(0xffffffffu, qsum[mi][hf], 1);
            qsum[mi][hf] += __shfl_xor_sync(0xffffffffu, qsum[mi][hf], 2);
        }
    if (tig == 0) {
#pragma unroll
        for (int mi = 0; mi < 2; mi++)
#pragma unroll
            for (int hf = 0; hf < 2; hf++) {
                int rl = wm + mi * 16 + g + hf * 8;
                red_s[rl * 4 + wngrp] = ssum[mi][hf];
                red_q[rl * 4 + wngrp] = qsum[mi][hf];
            }
    }
    __syncthreads();

#pragma unroll
    for (int mi = 0; mi < 2; mi++) {
#pragma unroll
        for (int hf = 0; hf < 2; hf++) {
            int rl = wm + mi * 16 + g + hf * 8;
            float S = red_s[rl * 4] + red_s[rl * 4 + 1] + red_s[rl * 4 + 2] + red_s[rl * 4 + 3];
            float Q = red_q[rl * 4] + red_q[rl * 4 + 1] + red_q[rl * 4 + 2] + red_q[rl * 4 + 3];
            float mu = S * (1.0f / 256.0f);
            float var = Q * (1.0f / 256.0f) - mu * mu;
            float inv = rsqrtf(var + 1e-5f);
            int gr = b * P_ + p0 + rl;
            float* orow = out + (size_t)gr * D_;
#pragma unroll
            for (int ni = 0; ni < 8; ni++) {
                int c = wn + ni * 8 + tig * 2;
                float h0 = (hf == 0) ? acc[mi][ni].x : acc[mi][ni].z;
                float h1 = (hf == 0) ? acc[mi][ni].y : acc[mi][ni].w;
                float2 y;
                y.x = (h0 - mu) * inv * s_g[c] + s_b[c];
                y.y = (h1 - mu) * inv * s_g[c + 1] + s_b[c + 1];
                *(float2*)(orow + c) = y;
            }
        }
    }
}

// ---------------- launch ----------------
extern "C" void kernel_launch(void* const* d_in, const int* in_sizes, int n_in,
                              void* d_out, int out_size)
{
    const float* x      = (const float*)d_in[0];
    const float* mlp_w  = (const float*)d_in[1];
    const float* mlp_b  = (const float*)d_in[2];
    const float* his_w  = (const float*)d_in[3];
    const float* his_b  = (const float*)d_in[4];
    const float* cur_w  = (const float*)d_in[5];
    const float* cur_b  = (const float*)d_in[6];
    const float* wl_w   = (const float*)d_in[7];
    const float* wl_b   = (const float*)d_in[8];
    const float* gate_w = (const float*)d_in[9];
    const float* gate_b = (const float*)d_in[10];
    const float* ln_g   = (const float*)d_in[11];
    const float* ln_b   = (const float*)d_in[12];
    float* out = (float*)d_out;

    void *pHbf, *pLbf, *pXM, *pWLbf, *pPM, *pPS, *pZ;
    cudaGetSymbolAddress(&pHbf, g_Hbf);
    cudaGetSymbolAddress(&pLbf, g_logbf);
    cudaGetSymbolAddress(&pXM, g_xmbf);
    cudaGetSymbolAddress(&pWLbf, g_wlbf);
    cudaGetSymbolAddress(&pPM, g_pmax);
    cudaGetSymbolAddress(&pPS, g_psum);
    cudaGetSymbolAddress(&pZ, g_zero);
    __nv_bfloat16* gHbf  = (__nv_bfloat16*)pHbf;
    __nv_bfloat16* gLbf  = (__nv_bfloat16*)pLbf;
    __nv_bfloat16* gXMbf = (__nv_bfloat16*)pXM;
    __nv_bfloat16* gWLbf = (__nv_bfloat16*)pWLbf;
    float* gPM = (float*)pPM;
    float* gPS = (float*)pPS;
    float* gZ  = (float*)pZ;

    const int tf32_smem = (G_STG * 2) * 4;   // 71680 bytes
    cudaFuncSetAttribute(k_gemm_tf32, cudaFuncAttributeMaxDynamicSharedMemorySize, tf32_smem);
    const int bf16_smem = L_STGB * 2;        // 37888 bytes
    cudaFuncSetAttribute(k_gemm_bf16, cudaFuncAttributeMaxDynamicSharedMemorySize, bf16_smem);

    // wl_w -> bf16
    k_cvt<<<(D_ * P_ / 4) / 256, 256>>>((const float4*)wl_w, (uint2*)gWLbf);

    // gate precompute
    k_weff<<<D_ / 8, 256>>>(cur_w, cur_b, gate_w, gate_b);
    k_wc<<<BP_ / 8, 256>>>(x);

    // H = x @ his_w + his_b  (tf32, bf16 out)
    k_gemm_tf32<<<dim3(D_ / 128, BP_ / 128), 256, tf32_smem>>>(
        x, his_w, his_b, gHbf, D_, D_);
    // xm = x @ mlp_w  (tf32, bf16 out, zero bias) -- associativity: (adj@x)@mlp_w = adj@xm
    k_gemm_tf32<<<dim3(D_ / 128, BP_ / 128), 256, tf32_smem>>>(
        x, mlp_w, gZ, gXMbf, D_, D_);
    // logits = Hbf @ wlbf + wl_b  (bf16 MMA, fused stats)
    k_gemm_bf16<<<dim3(P_ / 128, BP_ / 128), 256, bf16_smem>>>(
        gHbf, gWLbf, wl_b, gLbf, gPM, gPS);
    // combine softmax offsets
    k_rowstat2<<<BP_ / 256, 256>>>();
    // out = LN(tril(softmax)@xm + mlp_b + wc*x)  -- fully fused
    k_agg_bf16<<<dim3(P_ / 64, 1, B_), 256>>>(x, mlp_b, ln_g, ln_b, out);
    // second output: origin
    cudaMemcpyAsync(out + (size_t)BP_ * D_, x,
                    (size_t)BP_ * D_ * sizeof(float),
                    cudaMemcpyDeviceToDevice);
}

// round 13
// speedup vs baseline: 2.2184x; 1.0896x over previous
#include <cuda_runtime.h>
#include <cuda_bf16.h>
#include <cstdint>
#include <cstddef>

#define B_  32
#define P_  2048
#define D_  256
#define BP_ (B_ * P_)   // 65536

// ---------------- device scratch ----------------
__device__ __nv_bfloat16 g_Hbf[(size_t)BP_ * D_];     // 32 MB  H bf16
__device__ __nv_bfloat16 g_logbf[(size_t)BP_ * P_];   // 256 MB logits bf16
__device__ __nv_bfloat16 g_xmbf[(size_t)BP_ * D_];    // 32 MB  xm = x@mlp_w
__device__ __nv_bfloat16 g_xbf[(size_t)BP_ * D_];     // 32 MB  x bf16
__device__ __nv_bfloat16 g_wlbf[(size_t)D_ * P_];     // 1 MB   wl_w bf16
__device__ __nv_bfloat16 g_hisbf[(size_t)D_ * D_];    // his_w bf16
__device__ __nv_bfloat16 g_mlpbf[(size_t)D_ * D_];    // mlp_w bf16
__device__ float g_pmax[(size_t)BP_ * 16];
__device__ float g_psum[(size_t)BP_ * 16];
__device__ float g_rowoff[BP_];
__device__ float g_wc[BP_];
__device__ float g_weff[D_];
__device__ float g_beff;
__device__ float g_zero[D_];                          // stays zero

// ---------------- helpers ----------------
__device__ __forceinline__ void mma_bf16(float4& c, const uint32_t a[4],
                                         uint32_t b0, uint32_t b1) {
    asm volatile(
        "mma.sync.aligned.m16n8k16.row.col.f32.bf16.bf16.f32 "
        "{%0,%1,%2,%3}, {%4,%5,%6,%7}, {%8,%9}, {%0,%1,%2,%3};\n"
        : "+f"(c.x), "+f"(c.y), "+f"(c.z), "+f"(c.w)
        : "r"(a[0]), "r"(a[1]), "r"(a[2]), "r"(a[3]), "r"(b0), "r"(b1));
}

__device__ __forceinline__ void ldsm_x4(uint32_t r[4], uint32_t addr) {
    asm volatile("ldmatrix.sync.aligned.m8n8.x4.shared.b16 {%0,%1,%2,%3}, [%4];"
                 : "=r"(r[0]), "=r"(r[1]), "=r"(r[2]), "=r"(r[3]) : "r"(addr));
}

__device__ __forceinline__ void ldsm_x4t(uint32_t r[4], uint32_t addr) {
    asm volatile("ldmatrix.sync.aligned.m8n8.x4.trans.shared.b16 {%0,%1,%2,%3}, [%4];"
                 : "=r"(r[0]), "=r"(r[1]), "=r"(r[2]), "=r"(r[3]) : "r"(addr));
}

__device__ __forceinline__ void cp16(uint32_t dst_smem, const void* src) {
    asm volatile("cp.async.cg.shared.global [%0], [%1], 16;\n"
                 :: "r"(dst_smem), "l"(src));
}
#define CP_COMMIT()  asm volatile("cp.async.commit_group;\n" ::: "memory")
#define CP_WAIT(n)   asm volatile("cp.async.wait_group %0;\n" :: "n"(n) : "memory")

// ---------------- fp32 -> bf16 conversion (vectorized x4) ----------------
__global__ void k_cvt(const float4* __restrict__ src, uint2* __restrict__ dst)
{
    int i = blockIdx.x * 256 + threadIdx.x;
    float4 v = src[i];
    __nv_bfloat162 lo = __floats2bfloat162_rn(v.x, v.y);
    __nv_bfloat162 hi = __floats2bfloat162_rn(v.z, v.w);
    uint2 o;
    o.x = *(uint32_t*)&lo;
    o.y = *(uint32_t*)&hi;
    dst[i] = o;
}

// ---------------- w_eff / b_eff ----------------
__global__ void k_weff(const float* __restrict__ cur_w, const float* __restrict__ cur_b,
                       const float* __restrict__ gate_w, const float* __restrict__ gate_b)
{
    int warp = threadIdx.x >> 5;
    int lane = threadIdx.x & 31;
    int k = blockIdx.x * 8 + warp;
    float s = 0.f;
#pragma unroll
    for (int i = 0; i < 8; i++)
        s += cur_w[(size_t)k * D_ + lane + 32 * i] * __ldg(&gate_w[lane + 32 * i]);
#pragma unroll
    for (int o = 16; o; o >>= 1) s += __shfl_xor_sync(0xffffffffu, s, o);
    if (lane == 0) g_weff[k] = s;

    if (blockIdx.x == 0 && warp == 0) {
        float t = 0.f;
#pragma unroll
        for (int i = 0; i < 8; i++)
            t += cur_b[lane + 32 * i] * __ldg(&gate_w[lane + 32 * i]);
#pragma unroll
        for (int o = 16; o; o >>= 1) t += __shfl_xor_sync(0xffffffffu, t, o);
        if (lane == 0) g_beff = t + gate_b[0];
    }
}

// ---------------- wc[row] = x.w_eff + b_eff ----------------
__global__ void k_wc(const float* __restrict__ x)
{
    int row  = blockIdx.x * 8 + (threadIdx.x >> 5);
    int lane = threadIdx.x & 31;
    const float* xr = x + (size_t)row * D_;
    float s = 0.f;
#pragma unroll
    for (int i = 0; i < 8; i++) s += xr[lane + 32 * i] * g_weff[lane + 32 * i];
#pragma unroll
    for (int o = 16; o; o >>= 1) s += __shfl_xor_sync(0xffffffffu, s, o);
    if (lane == 0) g_wc[row] = s + g_beff;
}

// ---------------- BF16 GEMM: C[M,N] = Abf[M,256] @ Bbf[256,N] + bias[N]
// block 128x128, 8 warps (2m x 4n), warp tile 64x32, K-tile 32 (2 ks of k16), K=256.
// A smem [m][k] stride 40 bf16 (80B), B smem [k][n] stride 136 bf16 (272B).
// Optional fused softmax partial-stats epilogue (per 128-col block).
#define L_ABYTES (128 * 80)     // 10240
#define L_BBYTES (32 * 272)     // 8704
#define L_STGB (L_ABYTES + L_BBYTES)

__global__ __launch_bounds__(256, 2) void k_gemm_bf16(
    const __nv_bfloat16* __restrict__ A, const __nv_bfloat16* __restrict__ Bm,
    const float* __restrict__ bias, __nv_bfloat16* __restrict__ C,
    int N, int do_stats,
    float* __restrict__ pmax, float* __restrict__ psum)
{
    extern __shared__ float sm[];
    const uint32_t smb = (uint32_t)__cvta_generic_to_shared(sm);

    const int tid  = threadIdx.x;
    const int lane = tid & 31;
    const int warp = tid >> 5;
    const int wm = (warp & 1) * 64;
    const int wn = (warp >> 1) * 32;
    const int wcol = warp >> 1;
    const int g   = lane >> 2;
    const int tig = lane & 3;
    const int row0 = blockIdx.y * 128;
    const int col0 = blockIdx.x * 128;

    const int rowit = lane & 15;
    const int colb  = (lane & 16) ? 16 : 0;

    float4 acc[4][4];
#pragma unroll
    for (int mi = 0; mi < 4; mi++)
#pragma unroll
        for (int ni = 0; ni < 4; ni++) acc[mi][ni] = make_float4(0.f, 0.f, 0.f, 0.f);

    {
#pragma unroll
        for (int i = 0; i < 2; i++) {
            int id = tid + i * 256;
            int rw = id >> 2, ch = id & 3;
            cp16(smb + (uint32_t)(rw * 80 + ch * 16),
                 A + (size_t)(row0 + rw) * 256 + ch * 8);
            int brw = id >> 4, bch = id & 15;
            cp16(smb + (uint32_t)(L_ABYTES + brw * 272 + bch * 16),
                 Bm + (size_t)brw * N + col0 + bch * 8);
        }
        CP_COMMIT();
    }

#pragma unroll 2
    for (int kt = 0; kt < 8; kt++) {
        const int s = kt & 1;
        if (kt < 7) {
            uint32_t base = smb + (uint32_t)((s ^ 1) * L_STGB);
            const int k0 = (kt + 1) * 32;
#pragma unroll
            for (int i = 0; i < 2; i++) {
                int id = tid + i * 256;
                int rw = id >> 2, ch = id & 3;
                cp16(base + (uint32_t)(rw * 80 + ch * 16),
                     A + (size_t)(row0 + rw) * 256 + k0 + ch * 8);
                int brw = id >> 4, bch = id & 15;
                cp16(base + (uint32_t)(L_ABYTES + brw * 272 + bch * 16),
                     Bm + (size_t)(k0 + brw) * N + col0 + bch * 8);
            }
            CP_COMMIT();
            CP_WAIT(1);
        } else {
            CP_WAIT(0);
        }
        __syncthreads();

        const uint32_t aB = smb + (uint32_t)(s * L_STGB + (wm + rowit) * 80 + colb);
        const uint32_t bB = smb + (uint32_t)(s * L_STGB + L_ABYTES + rowit * 272 + colb + wn * 2);
#pragma unroll
        for (int ks = 0; ks < 2; ks++) {
            uint32_t af[4][4];
#pragma unroll
            for (int mi = 0; mi < 4; mi++)
                ldsm_x4(af[mi], aB + (uint32_t)(mi * 16 * 80 + ks * 32));
#pragma unroll
            for (int nj = 0; nj < 2; nj++) {
                uint32_t bq[4];
                ldsm_x4t(bq, bB + (uint32_t)(ks * 16 * 272 + nj * 32));
#pragma unroll
                for (int mi = 0; mi < 4; mi++) {
                    mma_bf16(acc[mi][nj * 2],     af[mi], bq[0], bq[1]);
                    mma_bf16(acc[mi][nj * 2 + 1], af[mi], bq[2], bq[3]);
                }
            }
        }
        __syncthreads();
    }

    // bias add (stats need biased values)
#pragma unroll
    for (int ni = 0; ni < 4; ni++) {
        int c = col0 + wn + ni * 8 + tig * 2;
        float b0 = bias[c], b1 = bias[c + 1];
#pragma unroll
        for (int mi = 0; mi < 4; mi++) {
            acc[mi][ni].x += b0; acc[mi][ni].y += b1;
            acc[mi][ni].z += b0; acc[mi][ni].w += b1;
        }
    }

    // store bf16
#pragma unroll
    for (int mi = 0; mi < 4; mi++) {
        int r = row0 + wm + mi * 16 + g;
#pragma unroll
        for (int ni = 0; ni < 4; ni++) {
            int c = col0 + wn + ni * 8 + tig * 2;
            __nv_bfloat162 v0 = __floats2bfloat162_rn(acc[mi][ni].x, acc[mi][ni].y);
            __nv_bfloat162 v1 = __floats2bfloat162_rn(acc[mi][ni].z, acc[mi][ni].w);
            *(__nv_bfloat162*)(C + (size_t)r * N + c) = v0;
            *(__nv_bfloat162*)(C + (size_t)(r + 8) * N + c) = v1;
        }
    }

    if (do_stats) {
        float* red_m = sm;          // [128][4]
        float* red_s = sm + 512;    // [128][4]
#pragma unroll
        for (int mi = 0; mi < 4; mi++) {
            float m1 = -1e30f, m2 = -1e30f;
#pragma unroll
            for (int ni = 0; ni < 4; ni++) {
                m1 = fmaxf(m1, fmaxf(acc[mi][ni].x, acc[mi][ni].y));
                m2 = fmaxf(m2, fmaxf(acc[mi][ni].z, acc[mi][ni].w));
            }
            m1 = fmaxf(m1, __shfl_xor_sync(0xffffffffu, m1, 1));
            m1 = fmaxf(m1, __shfl_xor_sync(0xffffffffu, m1, 2));
            m2 = fmaxf(m2, __shfl_xor_sync(0xffffffffu, m2, 1));
            m2 = fmaxf(m2, __shfl_xor_sync(0xffffffffu, m2, 2));
            float s1 = 0.f, s2 = 0.f;
#pragma unroll
            for (int ni = 0; ni < 4; ni++) {
                s1 += __expf(acc[mi][ni].x - m1) + __expf(acc[mi][ni].y - m1);
                s2 += __expf(acc[mi][ni].z - m2) + __expf(acc[mi][ni].w - m2);
            }
            s1 += __shfl_xor_sync(0xffffffffu, s1, 1);
            s1 += __shfl_xor_sync(0xffffffffu, s1, 2);
            s2 += __shfl_xor_sync(0xffffffffu, s2, 1);
            s2 += __shfl_xor_sync(0xffffffffu, s2, 2);
            if (tig == 0) {
                int rb1 = wm + mi * 16 + g;
                red_m[rb1 * 4 + wcol] = m1;  red_s[rb1 * 4 + wcol] = s1;
                red_m[(rb1 + 8) * 4 + wcol] = m2;  red_s[(rb1 + 8) * 4 + wcol] = s2;
            }
        }
        __syncthreads();
        if (tid < 128) {
            float M = -1e30f;
#pragma unroll
            for (int j = 0; j < 4; j++) M = fmaxf(M, red_m[tid * 4 + j]);
            float S = 0.f;
#pragma unroll
            for (int j = 0; j < 4; j++)
                S += red_s[tid * 4 + j] * __expf(red_m[tid * 4 + j] - M);
            size_t idx = (size_t)(row0 + tid) * 16 + blockIdx.x;
            pmax[idx] = M;
            psum[idx] = S;
        }
    }
}

// ---------------- combine partials ----------------
__global__ void k_rowstat2()
{
    int row = blockIdx.x * 256 + threadIdx.x;
    const float* pm = g_pmax + (size_t)row * 16;
    const float* ps = g_psum + (size_t)row * 16;
    float M = -1e30f;
#pragma unroll
    for (int j = 0; j < 16; j++) M = fmaxf(M, pm[j]);
    float S = 0.f;
#pragma unroll
    for (int j = 0; j < 16; j++) S += ps[j] * __expf(pm[j] - M);
    g_rowoff[row] = M + __logf(S);
}

// ---------------- BF16 agg + FULL FUSED EPILOGUE:
// acc = tril(softmax(logits)) @ xm  (= H_history - mlp_b)
// out = LN(acc + mlp_b + wc*x) * ln_g + ln_b   written directly.
__global__ __launch_bounds__(256, 2) void k_agg_bf16(
    const float* __restrict__ x, const float* __restrict__ mlp_b,
    const float* __restrict__ ln_g, const float* __restrict__ ln_b,
    float* __restrict__ out)
{
    __shared__ __align__(16) char AsB[64 * 80];     //  5120 B
    __shared__ __align__(16) char BsB[32 * 528];    // 16896 B
    __shared__ float red_s[64 * 4];
    __shared__ float red_q[64 * 4];
    __shared__ float s_mb[256], s_g[256], s_b[256];

    const uint32_t asb = (uint32_t)__cvta_generic_to_shared(AsB);
    const uint32_t bsb = (uint32_t)__cvta_generic_to_shared(BsB);

    const int b  = blockIdx.z;
    const int p0 = blockIdx.x * 64;
    const int tid  = threadIdx.x;
    const int lane = tid & 31;
    const int warp = tid >> 5;
    const int wm = (warp & 1) * 32;
    const int wn = (warp >> 1) * 64;
    const int wngrp = warp >> 1;
    const int g   = lane >> 2;
    const int tig = lane & 3;

    s_mb[tid] = mlp_b[tid];
    s_g[tid]  = ln_g[tid];
    s_b[tid]  = ln_b[tid];

    const int ar  = tid >> 2;              // 0..63
    const int ac8 = (tid & 3) * 8;
    const int prow = p0 + ar;
    const float off = g_rowoff[b * P_ + prow];
    const __nv_bfloat16* Lp = g_logbf + (size_t)(b * P_ + prow) * P_ + ac8;
    const __nv_bfloat16* xmb = g_xmbf + (size_t)b * P_ * D_;

    const int rowit = lane & 15;
    const int colb  = (lane & 16) ? 16 : 0;

    float4 acc[2][8];
#pragma unroll
    for (int mi = 0; mi < 2; mi++)
#pragma unroll
        for (int ni = 0; ni < 8; ni++) acc[mi][ni] = make_float4(0.f, 0.f, 0.f, 0.f);

    const int nkt = (p0 + 64) / 32;
    uint4 raw = *(const uint4*)(Lp);

    for (int kt = 0; kt < nkt; kt++) {
        const int k0 = kt * 32;
        __syncthreads();   // previous tile consumed (also covers s_mb init)

        {
            const __nv_bfloat162* h = (const __nv_bfloat162*)&raw;
            float2 f0 = __bfloat1622float2(h[0]);
            float2 f1 = __bfloat1622float2(h[1]);
            float2 f2 = __bfloat1622float2(h[2]);
            float2 f3 = __bfloat1622float2(h[3]);
            int kq = k0 + ac8;
            float e0 = (kq     <= prow) ? __expf(f0.x - off) : 0.f;
            float e1 = (kq + 1 <= prow) ? __expf(f0.y - off) : 0.f;
            float e2 = (kq + 2 <= prow) ? __expf(f1.x - off) : 0.f;
            float e3 = (kq + 3 <= prow) ? __expf(f1.y - off) : 0.f;
            float e4 = (kq + 4 <= prow) ? __expf(f2.x - off) : 0.f;
            float e5 = (kq + 5 <= prow) ? __expf(f2.y - off) : 0.f;
            float e6 = (kq + 6 <= prow) ? __expf(f3.x - off) : 0.f;
            float e7 = (kq + 7 <= prow) ? __expf(f3.y - off) : 0.f;
            __nv_bfloat162 p0b = __floats2bfloat162_rn(e0, e1);
            __nv_bfloat162 p1b = __floats2bfloat162_rn(e2, e3);
            __nv_bfloat162 p2b = __floats2bfloat162_rn(e4, e5);
            __nv_bfloat162 p3b = __floats2bfloat162_rn(e6, e7);
            uint4 pk;
            pk.x = *(uint32_t*)&p0b; pk.y = *(uint32_t*)&p1b;
            pk.z = *(uint32_t*)&p2b; pk.w = *(uint32_t*)&p3b;
            *(uint4*)(AsB + ar * 80 + ac8 * 2) = pk;
        }

#pragma unroll
        for (int t = 0; t < 4; t++) {
            int id = tid + t * 256;
            int krow = id >> 5;
            int ch = id & 31;
            cp16(bsb + (uint32_t)(krow * 528 + ch * 16),
                 xmb + (size_t)(k0 + krow) * D_ + ch * 8);
        }
        CP_COMMIT();

        if (kt + 1 < nkt) raw = *(const uint4*)(Lp + k0 + 32);

        CP_WAIT(0);
        __syncthreads();

        const uint32_t aB = asb + (uint32_t)((wm + rowit) * 80 + colb);
        const uint32_t bB = bsb + (uint32_t)(rowit * 528 + colb + wn * 2);
#pragma unroll
        for (int ks = 0; ks < 2; ks++) {
            uint32_t af[2][4];
#pragma unroll
            for (int mi = 0; mi < 2; mi++)
                ldsm_x4(af[mi], aB + (uint32_t)(mi * 16 * 80 + ks * 32));
#pragma unroll
            for (int nj = 0; nj < 4; nj++) {
                uint32_t bq[4];
                ldsm_x4t(bq, bB + (uint32_t)(ks * 16 * 528 + nj * 32));
#pragma unroll
                for (int mi = 0; mi < 2; mi++) {
                    mma_bf16(acc[mi][nj * 2],     af[mi], bq[0], bq[1]);
                    mma_bf16(acc[mi][nj * 2 + 1], af[mi], bq[2], bq[3]);
                }
            }
        }
    }

    // ===== fused epilogue: h = acc + mlp_b + wc*x; LN; write out =====
    float ssum[2][2] = {{0.f, 0.f}, {0.f, 0.f}};
    float qsum[2][2] = {{0.f, 0.f}, {0.f, 0.f}};
#pragma unroll
    for (int mi = 0; mi < 2; mi++) {
        int gr0 = b * P_ + p0 + wm + mi * 16 + g;
        int gr1 = gr0 + 8;
        float wc0 = g_wc[gr0], wc1 = g_wc[gr1];
        const float* xr0 = x + (size_t)gr0 * D_;
        const float* xr1 = x + (size_t)gr1 * D_;
#pragma unroll
        for (int ni = 0; ni < 8; ni++) {
            int c = wn + ni * 8 + tig * 2;
            float2 xv0 = *(const float2*)(xr0 + c);
            float2 xv1 = *(const float2*)(xr1 + c);
            acc[mi][ni].x += s_mb[c]     + wc0 * xv0.x;
            acc[mi][ni].y += s_mb[c + 1] + wc0 * xv0.y;
            acc[mi][ni].z += s_mb[c]     + wc1 * xv1.x;
            acc[mi][ni].w += s_mb[c + 1] + wc1 * xv1.y;
            ssum[mi][0] += acc[mi][ni].x + acc[mi][ni].y;
            ssum[mi][1] += acc[mi][ni].z + acc[mi][ni].w;
            qsum[mi][0] += acc[mi][ni].x * acc[mi][ni].x + acc[mi][ni].y * acc[mi][ni].y;
            qsum[mi][1] += acc[mi][ni].z * acc[mi][ni].z + acc[mi][ni].w * acc[mi][ni].w;
        }
    }
#pragma unroll
    for (int mi = 0; mi < 2; mi++)
#pragma unroll
        for (int hf = 0; hf < 2; hf++) {
            ssum[mi][hf] += __shfl_xor_sync(0xffffffffu, ssum[mi][hf], 1);
            ssum[mi][hf] += __shfl_xor_sync(0xffffffffu, ssum[mi][hf], 2);
            qsum[mi][hf] += __shfl_xor_sync(0xffffffffu, qsum[mi][hf], 1);
            qsum[mi][hf] += __shfl_xor_sync(0xffffffffu, qsum[mi][hf], 2);
        }
    if (tig == 0) {
#pragma unroll
        for (int mi = 0; mi < 2; mi++)
#pragma unroll
            for (int hf = 0; hf < 2; hf++) {
                int rl = wm + mi * 16 + g + hf * 8;
                red_s[rl * 4 + wngrp] = ssum[mi][hf];
                red_q[rl * 4 + wngrp] = qsum[mi][hf];
            }
    }
    __syncthreads();

#pragma unroll
    for (int mi = 0; mi < 2; mi++) {
#pragma unroll
        for (int hf = 0; hf < 2; hf++) {
            int rl = wm + mi * 16 + g + hf * 8;
            float S = red_s[rl * 4] + red_s[rl * 4 + 1] + red_s[rl * 4 + 2] + red_s[rl * 4 + 3];
            float Q = red_q[rl * 4] + red_q[rl * 4 + 1] + red_q[rl * 4 + 2] + red_q[rl * 4 + 3];
            float mu = S * (1.0f / 256.0f);
            float var = Q * (1.0f / 256.0f) - mu * mu;
            float inv = rsqrtf(var + 1e-5f);
            int gr = b * P_ + p0 + rl;
            float* orow = out + (size_t)gr * D_;
#pragma unroll
            for (int ni = 0; ni < 8; ni++) {
                int c = wn + ni * 8 + tig * 2;
                float h0 = (hf == 0) ? acc[mi][ni].x : acc[mi][ni].z;
                float h1 = (hf == 0) ? acc[mi][ni].y : acc[mi][ni].w;
                float2 y;
                y.x = (h0 - mu) * inv * s_g[c] + s_b[c];
                y.y = (h1 - mu) * inv * s_g[c + 1] + s_b[c + 1];
                *(float2*)(orow + c) = y;
            }
        }
    }
}

// ---------------- launch ----------------
extern "C" void kernel_launch(void* const* d_in, const int* in_sizes, int n_in,
                              void* d_out, int out_size)
{
    const float* x      = (const float*)d_in[0];
    const float* mlp_w  = (const float*)d_in[1];
    const float* mlp_b  = (const float*)d_in[2];
    const float* his_w  = (const float*)d_in[3];
    const float* his_b  = (const float*)d_in[4];
    const float* cur_w  = (const float*)d_in[5];
    const float* cur_b  = (const float*)d_in[6];
    const float* wl_w   = (const float*)d_in[7];
    const float* wl_b   = (const float*)d_in[8];
    const float* gate_w = (const float*)d_in[9];
    const float* gate_b = (const float*)d_in[10];
    const float* ln_g   = (const float*)d_in[11];
    const float* ln_b   = (const float*)d_in[12];
    float* out = (float*)d_out;

    void *pHbf, *pLbf, *pXM, *pXbf, *pWLbf, *pHIS, *pMLP, *pPM, *pPS, *pZ;
    cudaGetSymbolAddress(&pHbf, g_Hbf);
    cudaGetSymbolAddress(&pLbf, g_logbf);
    cudaGetSymbolAddress(&pXM, g_xmbf);
    cudaGetSymbolAddress(&pXbf, g_xbf);
    cudaGetSymbolAddress(&pWLbf, g_wlbf);
    cudaGetSymbolAddress(&pHIS, g_hisbf);
    cudaGetSymbolAddress(&pMLP, g_mlpbf);
    cudaGetSymbolAddress(&pPM, g_pmax);
    cudaGetSymbolAddress(&pPS, g_psum);
    cudaGetSymbolAddress(&pZ, g_zero);
    __nv_bfloat16* gHbf   = (__nv_bfloat16*)pHbf;
    __nv_bfloat16* gLbf   = (__nv_bfloat16*)pLbf;
    __nv_bfloat16* gXMbf  = (__nv_bfloat16*)pXM;
    __nv_bfloat16* gXbf   = (__nv_bfloat16*)pXbf;
    __nv_bfloat16* gWLbf  = (__nv_bfloat16*)pWLbf;
    __nv_bfloat16* gHISbf = (__nv_bfloat16*)pHIS;
    __nv_bfloat16* gMLPbf = (__nv_bfloat16*)pMLP;
    float* gPM = (float*)pPM;
    float* gPS = (float*)pPS;
    float* gZ  = (float*)pZ;

    const int bf16_smem = L_STGB * 2;        // 37888 bytes
    cudaFuncSetAttribute(k_gemm_bf16, cudaFuncAttributeMaxDynamicSharedMemorySize, bf16_smem);

    // bf16 conversions: x, wl_w, his_w, mlp_w
    k_cvt<<<(BP_ * D_ / 4) / 256, 256>>>((const float4*)x, (uint2*)gXbf);
    k_cvt<<<(D_ * P_ / 4) / 256, 256>>>((const float4*)wl_w, (uint2*)gWLbf);
    k_cvt<<<(D_ * D_ / 4) / 256, 256>>>((const float4*)his_w, (uint2*)gHISbf);
    k_cvt<<<(D_ * D_ / 4) / 256, 256>>>((const float4*)mlp_w, (uint2*)gMLPbf);

    // gate precompute
    k_weff<<<D_ / 8, 256>>>(cur_w, cur_b, gate_w, gate_b);
    k_wc<<<BP_ / 8, 256>>>(x);

    // H = x @ his_w + his_b   (bf16 MMA)
    k_gemm_bf16<<<dim3(D_ / 128, BP_ / 128), 256, bf16_smem>>>(
        gXbf, gHISbf, his_b, gHbf, D_, 0, nullptr, nullptr);
    // xm = x @ mlp_w          (bf16 MMA, zero bias; associativity)
    k_gemm_bf16<<<dim3(D_ / 128, BP_ / 128), 256, bf16_smem>>>(
        gXbf, gMLPbf, gZ, gXMbf, D_, 0, nullptr, nullptr);
    // logits = H @ wl_w + wl_b (bf16 MMA + fused softmax stats)
    k_gemm_bf16<<<dim3(P_ / 128, BP_ / 128), 256, bf16_smem>>>(
        gHbf, gWLbf, wl_b, gLbf, P_, 1, gPM, gPS);
    // combine softmax offsets
    k_rowstat2<<<BP_ / 256, 256>>>();
    // out = LN(tril(softmax)@xm + mlp_b + wc*x)  -- fully fused
    k_agg_bf16<<<dim3(P_ / 64, 1, B_), 256>>>(x, mlp_b, ln_g, ln_b, out);
    // second output: origin
    cudaMemcpyAsync(out + (size_t)BP_ * D_, x,
                    (size_t)BP_ * D_ * sizeof(float),
                    cudaMemcpyDeviceToDevice);
}

// round 15
// speedup vs baseline: 2.2714x; 1.0239x over previous
#include <cuda_runtime.h>
#include <cuda_bf16.h>
#include <cstdint>
#include <cstddef>

#define B_  32
#define P_  2048
#define D_  256
#define BP_ (B_ * P_)   // 65536

// ---------------- device scratch ----------------
__device__ __nv_bfloat16 g_Hbf[(size_t)BP_ * D_];     // 32 MB  H bf16
__device__ __nv_bfloat16 g_logbf[(size_t)BP_ * P_];   // 256 MB logits bf16
__device__ __nv_bfloat16 g_xmbf[(size_t)BP_ * D_];    // 32 MB  xm = x@mlp_w
__device__ __nv_bfloat16 g_xbf[(size_t)BP_ * D_];     // 32 MB  x bf16
__device__ __nv_bfloat16 g_wlbf[(size_t)D_ * P_];     // 1 MB   wl_w bf16
__device__ __nv_bfloat16 g_wcatbf[(size_t)D_ * 512];  // [his_w | mlp_w] bf16
__device__ float g_pmax[(size_t)BP_ * 16];
__device__ float g_psum[(size_t)BP_ * 16];
__device__ float g_rowoff[BP_];
__device__ float g_wc[BP_];
__device__ float g_weff[D_];
__device__ float g_beff;
__device__ float g_zero[D_];                          // stays zero

// ---------------- helpers ----------------
__device__ __forceinline__ void mma_bf16(float4& c, const uint32_t a[4],
                                         uint32_t b0, uint32_t b1) {
    asm volatile(
        "mma.sync.aligned.m16n8k16.row.col.f32.bf16.bf16.f32 "
        "{%0,%1,%2,%3}, {%4,%5,%6,%7}, {%8,%9}, {%0,%1,%2,%3};\n"
        : "+f"(c.x), "+f"(c.y), "+f"(c.z), "+f"(c.w)
        : "r"(a[0]), "r"(a[1]), "r"(a[2]), "r"(a[3]), "r"(b0), "r"(b1));
}

__device__ __forceinline__ void ldsm_x4(uint32_t r[4], uint32_t addr) {
    asm volatile("ldmatrix.sync.aligned.m8n8.x4.shared.b16 {%0,%1,%2,%3}, [%4];"
                 : "=r"(r[0]), "=r"(r[1]), "=r"(r[2]), "=r"(r[3]) : "r"(addr));
}

__device__ __forceinline__ void ldsm_x4t(uint32_t r[4], uint32_t addr) {
    asm volatile("ldmatrix.sync.aligned.m8n8.x4.trans.shared.b16 {%0,%1,%2,%3}, [%4];"
                 : "=r"(r[0]), "=r"(r[1]), "=r"(r[2]), "=r"(r[3]) : "r"(addr));
}

__device__ __forceinline__ void cp16(uint32_t dst_smem, const void* src) {
    asm volatile("cp.async.cg.shared.global [%0], [%1], 16;\n"
                 :: "r"(dst_smem), "l"(src));
}
#define CP_COMMIT()  asm volatile("cp.async.commit_group;\n" ::: "memory")
#define CP_WAIT(n)   asm volatile("cp.async.wait_group %0;\n" :: "n"(n) : "memory")

// ---------------- wl_w fp32 -> bf16 (vectorized x4) ----------------
__global__ void k_cvt(const float4* __restrict__ src, uint2* __restrict__ dst)
{
    int i = blockIdx.x * 256 + threadIdx.x;
    float4 v = src[i];
    __nv_bfloat162 lo = __floats2bfloat162_rn(v.x, v.y);
    __nv_bfloat162 hi = __floats2bfloat162_rn(v.z, v.w);
    uint2 o;
    o.x = *(uint32_t*)&lo;
    o.y = *(uint32_t*)&hi;
    dst[i] = o;
}

// ---------------- build wcat = [his_w | mlp_w] bf16 ----------------
__global__ void k_cvtW(const float* __restrict__ his, const float* __restrict__ mlp,
                       __nv_bfloat16* __restrict__ wcat)
{
    int i = blockIdx.x * 256 + threadIdx.x;     // 0 .. 65535
    int k = i >> 8, c = i & 255;
    wcat[(size_t)k * 512 + c]       = __float2bfloat16(his[i]);
    wcat[(size_t)k * 512 + 256 + c] = __float2bfloat16(mlp[i]);
}

// ---------------- w_eff / b_eff ----------------
__global__ void k_weff(const float* __restrict__ cur_w, const float* __restrict__ cur_b,
                       const float* __restrict__ gate_w, const float* __restrict__ gate_b)
{
    int warp = threadIdx.x >> 5;
    int lane = threadIdx.x & 31;
    int k = blockIdx.x * 8 + warp;
    float s = 0.f;
#pragma unroll
    for (int i = 0; i < 8; i++)
        s += cur_w[(size_t)k * D_ + lane + 32 * i] * __ldg(&gate_w[lane + 32 * i]);
#pragma unroll
    for (int o = 16; o; o >>= 1) s += __shfl_xor_sync(0xffffffffu, s, o);
    if (lane == 0) g_weff[k] = s;

    if (blockIdx.x == 0 && warp == 0) {
        float t = 0.f;
#pragma unroll
        for (int i = 0; i < 8; i++)
            t += cur_b[lane + 32 * i] * __ldg(&gate_w[lane + 32 * i]);
#pragma unroll
        for (int o = 16; o; o >>= 1) t += __shfl_xor_sync(0xffffffffu, t, o);
        if (lane == 0) g_beff = t + gate_b[0];
    }
}

// ---------------- fused: x -> bf16 AND wc[row] = x.w_eff + b_eff (1 warp/row)
__global__ void k_cvtx_wc(const float* __restrict__ x)
{
    __shared__ float sw[D_];
    int tid = threadIdx.x;
    sw[tid] = g_weff[tid];
    __syncthreads();
    int warp = tid >> 5, lane = tid & 31;
    int row = blockIdx.x * 8 + warp;
    const float* xr = x + (size_t)row * D_;
    uint2* dst = (uint2*)(g_xbf + (size_t)row * D_);
    float s = 0.f;
#pragma unroll
    for (int j = 0; j < 2; j++) {
        int c = lane * 4 + j * 128;
        float4 v = *(const float4*)(xr + c);
        __nv_bfloat162 lo = __floats2bfloat162_rn(v.x, v.y);
        __nv_bfloat162 hi = __floats2bfloat162_rn(v.z, v.w);
        uint2 o;
        o.x = *(uint32_t*)&lo;
        o.y = *(uint32_t*)&hi;
        dst[lane + j * 32] = o;
        s += v.x * sw[c] + v.y * sw[c + 1] + v.z * sw[c + 2] + v.w * sw[c + 3];
    }
#pragma unroll
    for (int o = 16; o; o >>= 1) s += __shfl_xor_sync(0xffffffffu, s, o);
    if (lane == 0) g_wc[row] = s + g_beff;
}

// ---------------- BF16 GEMM: C = Abf[M,256] @ Bbf[256,N] + bias
// block 128x128, 8 warps (2m x 4n), warp tile 64x32, K-tile 32, K=256.
// Split-output mode: blocks with col0 >= splitcol write to C2/bias2 (col-256),
// each output row-major with Nout columns. Optional fused softmax stats.
#define L_ABYTES (128 * 80)     // 10240
#define L_BBYTES (32 * 272)     // 8704
#define L_STGB (L_ABYTES + L_BBYTES)

__global__ __launch_bounds__(256, 2) void k_gemm_bf16(
    const __nv_bfloat16* __restrict__ A, const __nv_bfloat16* __restrict__ Bm,
    const float* __restrict__ bias, const float* __restrict__ bias2,
    __nv_bfloat16* __restrict__ C, __nv_bfloat16* __restrict__ C2,
    int N, int Nout, int splitcol, int do_stats,
    float* __restrict__ pmax, float* __restrict__ psum)
{
    extern __shared__ float sm[];
    const uint32_t smb = (uint32_t)__cvta_generic_to_shared(sm);

    const int tid  = threadIdx.x;
    const int lane = tid & 31;
    const int warp = tid >> 5;
    const int wm = (warp & 1) * 64;
    const int wn = (warp >> 1) * 32;
    const int wcol = warp >> 1;
    const int g   = lane >> 2;
    const int tig = lane & 3;
    const int row0 = blockIdx.y * 128;
    const int col0 = blockIdx.x * 128;

    const int rowit = lane & 15;
    const int colb  = (lane & 16) ? 16 : 0;

    // output routing
    __nv_bfloat16* Cout = C;
    const float* bptr = bias;
    int cbase = col0;
    if (col0 >= splitcol) { Cout = C2; bptr = bias2; cbase = col0 - splitcol; }

    float4 acc[4][4];
#pragma unroll
    for (int mi = 0; mi < 4; mi++)
#pragma unroll
        for (int ni = 0; ni < 4; ni++) acc[mi][ni] = make_float4(0.f, 0.f, 0.f, 0.f);

    {
#pragma unroll
        for (int i = 0; i < 2; i++) {
            int id = tid + i * 256;
            int rw = id >> 2, ch = id & 3;
            cp16(smb + (uint32_t)(rw * 80 + ch * 16),
                 A + (size_t)(row0 + rw) * 256 + ch * 8);
            int brw = id >> 4, bch = id & 15;
            cp16(smb + (uint32_t)(L_ABYTES + brw * 272 + bch * 16),
                 Bm + (size_t)brw * N + col0 + bch * 8);
        }
        CP_COMMIT();
    }

#pragma unroll 2
    for (int kt = 0; kt < 8; kt++) {
        const int s = kt & 1;
        if (kt < 7) {
            uint32_t base = smb + (uint32_t)((s ^ 1) * L_STGB);
            const int k0 = (kt + 1) * 32;
#pragma unroll
            for (int i = 0; i < 2; i++) {
                int id = tid + i * 256;
                int rw = id >> 2, ch = id & 3;
                cp16(base + (uint32_t)(rw * 80 + ch * 16),
                     A + (size_t)(row0 + rw) * 256 + k0 + ch * 8);
                int brw = id >> 4, bch = id & 15;
                cp16(base + (uint32_t)(L_ABYTES + brw * 272 + bch * 16),
                     Bm + (size_t)(k0 + brw) * N + col0 + bch * 8);
            }
            CP_COMMIT();
            CP_WAIT(1);
        } else {
            CP_WAIT(0);
        }
        __syncthreads();

        const uint32_t aB = smb + (uint32_t)(s * L_STGB + (wm + rowit) * 80 + colb);
        const uint32_t bB = smb + (uint32_t)(s * L_STGB + L_ABYTES + rowit * 272 + colb + wn * 2);
#pragma unroll
        for (int ks = 0; ks < 2; ks++) {
            uint32_t af[4][4];
#pragma unroll
            for (int mi = 0; mi < 4; mi++)
                ldsm_x4(af[mi], aB + (uint32_t)(mi * 16 * 80 + ks * 32));
#pragma unroll
            for (int nj = 0; nj < 2; nj++) {
                uint32_t bq[4];
                ldsm_x4t(bq, bB + (uint32_t)(ks * 16 * 272 + nj * 32));
#pragma unroll
                for (int mi = 0; mi < 4; mi++) {
                    mma_bf16(acc[mi][nj * 2],     af[mi], bq[0], bq[1]);
                    mma_bf16(acc[mi][nj * 2 + 1], af[mi], bq[2], bq[3]);
                }
            }
        }
        __syncthreads();
    }

    // bias add (stats need biased values)
#pragma unroll
    for (int ni = 0; ni < 4; ni++) {
        int c = cbase + wn + ni * 8 + tig * 2;
        float b0 = bptr[c], b1 = bptr[c + 1];
#pragma unroll
        for (int mi = 0; mi < 4; mi++) {
            acc[mi][ni].x += b0; acc[mi][ni].y += b1;
            acc[mi][ni].z += b0; acc[mi][ni].w += b1;
        }
    }

    // store bf16
#pragma unroll
    for (int mi = 0; mi < 4; mi++) {
        int r = row0 + wm + mi * 16 + g;
#pragma unroll
        for (int ni = 0; ni < 4; ni++) {
            int c = cbase + wn + ni * 8 + tig * 2;
            __nv_bfloat162 v0 = __floats2bfloat162_rn(acc[mi][ni].x, acc[mi][ni].y);
            __nv_bfloat162 v1 = __floats2bfloat162_rn(acc[mi][ni].z, acc[mi][ni].w);
            *(__nv_bfloat162*)(Cout + (size_t)r * Nout + c) = v0;
            *(__nv_bfloat162*)(Cout + (size_t)(r + 8) * Nout + c) = v1;
        }
    }

    if (do_stats) {
        float* red_m = sm;          // [128][4]
        float* red_s = sm + 512;    // [128][4]
#pragma unroll
        for (int mi = 0; mi < 4; mi++) {
            float m1 = -1e30f, m2 = -1e30f;
#pragma unroll
            for (int ni = 0; ni < 4; ni++) {
                m1 = fmaxf(m1, fmaxf(acc[mi][ni].x, acc[mi][ni].y));
                m2 = fmaxf(m2, fmaxf(acc[mi][ni].z, acc[mi][ni].w));
            }
            m1 = fmaxf(m1, __shfl_xor_sync(0xffffffffu, m1, 1));
            m1 = fmaxf(m1, __shfl_xor_sync(0xffffffffu, m1, 2));
            m2 = fmaxf(m2, __shfl_xor_sync(0xffffffffu, m2, 1));
            m2 = fmaxf(m2, __shfl_xor_sync(0xffffffffu, m2, 2));
            float s1 = 0.f, s2 = 0.f;
#pragma unroll
            for (int ni = 0; ni < 4; ni++) {
                s1 += __expf(acc[mi][ni].x - m1) + __expf(acc[mi][ni].y - m1);
                s2 += __expf(acc[mi][ni].z - m2) + __expf(acc[mi][ni].w - m2);
            }
            s1 += __shfl_xor_sync(0xffffffffu, s1, 1);
            s1 += __shfl_xor_sync(0xffffffffu, s1, 2);
            s2 += __shfl_xor_sync(0xffffffffu, s2, 1);
            s2 += __shfl_xor_sync(0xffffffffu, s2, 2);
            if (tig == 0) {
                int rb1 = wm + mi * 16 + g;
                red_m[rb1 * 4 + wcol] = m1;  red_s[rb1 * 4 + wcol] = s1;
                red_m[(rb1 + 8) * 4 + wcol] = m2;  red_s[(rb1 + 8) * 4 + wcol] = s2;
            }
        }
        __syncthreads();
        if (tid < 128) {
            float M = -1e30f;
#pragma unroll
            for (int j = 0; j < 4; j++) M = fmaxf(M, red_m[tid * 4 + j]);
            float S = 0.f;
#pragma unroll
            for (int j = 0; j < 4; j++)
                S += red_s[tid * 4 + j] * __expf(red_m[tid * 4 + j] - M);
            size_t idx = (size_t)(row0 + tid) * 16 + blockIdx.x;
            pmax[idx] = M;
            psum[idx] = S;
        }
    }
}

// ---------------- combine partials ----------------
__global__ void k_rowstat2()
{
    int row = blockIdx.x * 256 + threadIdx.x;
    const float* pm = g_pmax + (size_t)row * 16;
    const float* ps = g_psum + (size_t)row * 16;
    float M = -1e30f;
#pragma unroll
    for (int j = 0; j < 16; j++) M = fmaxf(M, pm[j]);
    float S = 0.f;
#pragma unroll
    for (int j = 0; j < 16; j++) S += ps[j] * __expf(pm[j] - M);
    g_rowoff[row] = M + __logf(S);
}

// ---------------- BF16 agg + FULL FUSED EPILOGUE (R13, unchanged) ----------------
__global__ __launch_bounds__(256, 2) void k_agg_bf16(
    const float* __restrict__ x, const float* __restrict__ mlp_b,
    const float* __restrict__ ln_g, const float* __restrict__ ln_b,
    float* __restrict__ out)
{
    __shared__ __align__(16) char AsB[64 * 80];
    __shared__ __align__(16) char BsB[32 * 528];
    __shared__ float red_s[64 * 4];
    __shared__ float red_q[64 * 4];
    __shared__ float s_mb[256], s_g[256], s_b[256];

    const uint32_t asb = (uint32_t)__cvta_generic_to_shared(AsB);
    const uint32_t bsb = (uint32_t)__cvta_generic_to_shared(BsB);

    const int b  = blockIdx.z;
    const int p0 = blockIdx.x * 64;
    const int tid  = threadIdx.x;
    const int lane = tid & 31;
    const int warp = tid >> 5;
    const int wm = (warp & 1) * 32;
    const int wn = (warp >> 1) * 64;
    const int wngrp = warp >> 1;
    const int g   = lane >> 2;
    const int tig = lane & 3;

    s_mb[tid] = mlp_b[tid];
    s_g[tid]  = ln_g[tid];
    s_b[tid]  = ln_b[tid];

    const int ar  = tid >> 2;
    const int ac8 = (tid & 3) * 8;
    const int prow = p0 + ar;
    const float off = g_rowoff[b * P_ + prow];
    const __nv_bfloat16* Lp = g_logbf + (size_t)(b * P_ + prow) * P_ + ac8;
    const __nv_bfloat16* xmb = g_xmbf + (size_t)b * P_ * D_;

    const int rowit = lane & 15;
    const int colb  = (lane & 16) ? 16 : 0;

    float4 acc[2][8];
#pragma unroll
    for (int mi = 0; mi < 2; mi++)
#pragma unroll
        for (int ni = 0; ni < 8; ni++) acc[mi][ni] = make_float4(0.f, 0.f, 0.f, 0.f);

    const int nkt = (p0 + 64) / 32;
    uint4 raw = *(const uint4*)(Lp);

    for (int kt = 0; kt < nkt; kt++) {
        const int k0 = kt * 32;
        __syncthreads();

        {
            const __nv_bfloat162* h = (const __nv_bfloat162*)&raw;
            float2 f0 = __bfloat1622float2(h[0]);
            float2 f1 = __bfloat1622float2(h[1]);
            float2 f2 = __bfloat1622float2(h[2]);
            float2 f3 = __bfloat1622float2(h[3]);
            int kq = k0 + ac8;
            float e0 = (kq     <= prow) ? __expf(f0.x - off) : 0.f;
            float e1 = (kq + 1 <= prow) ? __expf(f0.y - off) : 0.f;
            float e2 = (kq + 2 <= prow) ? __expf(f1.x - off) : 0.f;
            float e3 = (kq + 3 <= prow) ? __expf(f1.y - off) : 0.f;
            float e4 = (kq + 4 <= prow) ? __expf(f2.x - off) : 0.f;
            float e5 = (kq + 5 <= prow) ? __expf(f2.y - off) : 0.f;
            float e6 = (kq + 6 <= prow) ? __expf(f3.x - off) : 0.f;
            float e7 = (kq + 7 <= prow) ? __expf(f3.y - off) : 0.f;
            __nv_bfloat162 p0b = __floats2bfloat162_rn(e0, e1);
            __nv_bfloat162 p1b = __floats2bfloat162_rn(e2, e3);
            __nv_bfloat162 p2b = __floats2bfloat162_rn(e4, e5);
            __nv_bfloat162 p3b = __floats2bfloat162_rn(e6, e7);
            uint4 pk;
            pk.x = *(uint32_t*)&p0b; pk.y = *(uint32_t*)&p1b;
            pk.z = *(uint32_t*)&p2b; pk.w = *(uint32_t*)&p3b;
            *(uint4*)(AsB + ar * 80 + ac8 * 2) = pk;
        }

#pragma unroll
        for (int t = 0; t < 4; t++) {
            int id = tid + t * 256;
            int krow = id >> 5;
            int ch = id & 31;
            cp16(bsb + (uint32_t)(krow * 528 + ch * 16),
                 xmb + (size_t)(k0 + krow) * D_ + ch * 8);
        }
        CP_COMMIT();

        if (kt + 1 < nkt) raw = *(const uint4*)(Lp + k0 + 32);

        CP_WAIT(0);
        __syncthreads();

        const uint32_t aB = asb + (uint32_t)((wm + rowit) * 80 + colb);
        const uint32_t bB = bsb + (uint32_t)(rowit * 528 + colb + wn * 2);
#pragma unroll
        for (int ks = 0; ks < 2; ks++) {
            uint32_t af[2][4];
#pragma unroll
            for (int mi = 0; mi < 2; mi++)
                ldsm_x4(af[mi], aB + (uint32_t)(mi * 16 * 80 + ks * 32));
#pragma unroll
            for (int nj = 0; nj < 4; nj++) {
                uint32_t bq[4];
                ldsm_x4t(bq, bB + (uint32_t)(ks * 16 * 528 + nj * 32));
#pragma unroll
                for (int mi = 0; mi < 2; mi++) {
                    mma_bf16(acc[mi][nj * 2],     af[mi], bq[0], bq[1]);
                    mma_bf16(acc[mi][nj * 2 + 1], af[mi], bq[2], bq[3]);
                }
            }
        }
    }

    float ssum[2][2] = {{0.f, 0.f}, {0.f, 0.f}};
    float qsum[2][2] = {{0.f, 0.f}, {0.f, 0.f}};
#pragma unroll
    for (int mi = 0; mi < 2; mi++) {
        int gr0 = b * P_ + p0 + wm + mi * 16 + g;
        int gr1 = gr0 + 8;
        float wc0 = g_wc[gr0], wc1 = g_wc[gr1];
        const float* xr0 = x + (size_t)gr0 * D_;
        const float* xr1 = x + (size_t)gr1 * D_;
#pragma unroll
        for (int ni = 0; ni < 8; ni++) {
            int c = wn + ni * 8 + tig * 2;
            float2 xv0 = *(const float2*)(xr0 + c);
            float2 xv1 = *(const float2*)(xr1 + c);
            acc[mi][ni].x += s_mb[c]     + wc0 * xv0.x;
            acc[mi][ni].y += s_mb[c + 1] + wc0 * xv0.y;
            acc[mi][ni].z += s_mb[c]     + wc1 * xv1.x;
            acc[mi][ni].w += s_mb[c + 1] + wc1 * xv1.y;
            ssum[mi][0] += acc[mi][ni].x + acc[mi][ni].y;
            ssum[mi][1] += acc[mi][ni].z + acc[mi][ni].w;
            qsum[mi][0] += acc[mi][ni].x * acc[mi][ni].x + acc[mi][ni].y * acc[mi][ni].y;
            qsum[mi][1] += acc[mi][ni].z * acc[mi][ni].z + acc[mi][ni].w * acc[mi][ni].w;
        }
    }
#pragma unroll
    for (int mi = 0; mi < 2; mi++)
#pragma unroll
        for (int hf = 0; hf < 2; hf++) {
            ssum[mi][hf] += __shfl_xor_sync(0xffffffffu, ssum[mi][hf], 1);
            ssum[mi][hf] += __shfl_xor_sync(0xffffffffu, ssum[mi][hf], 2);
            qsum[mi][hf] += __shfl_xor_sync(0xffffffffu, qsum[mi][hf], 1);
            qsum[mi][hf] += __shfl_xor_sync(0xffffffffu, qsum[mi][hf], 2);
        }
    if (tig == 0) {
#pragma unroll
        for (int mi = 0; mi < 2; mi++)
#pragma unroll
            for (int hf = 0; hf < 2; hf++) {
                int rl = wm + mi * 16 + g + hf * 8;
                red_s[rl * 4 + wngrp] = ssum[mi][hf];
                red_q[rl * 4 + wngrp] = qsum[mi][hf];
            }
    }
    __syncthreads();

#pragma unroll
    for (int mi = 0; mi < 2; mi++) {
#pragma unroll
        for (int hf = 0; hf < 2; hf++) {
            int rl = wm + mi * 16 + g + hf * 8;
            float S = red_s[rl * 4] + red_s[rl * 4 + 1] + red_s[rl * 4 + 2] + red_s[rl * 4 + 3];
            float Q = red_q[rl * 4] + red_q[rl * 4 + 1] + red_q[rl * 4 + 2] + red_q[rl * 4 + 3];
            float mu = S * (1.0f / 256.0f);
            float var = Q * (1.0f / 256.0f) - mu * mu;
            float inv = rsqrtf(var + 1e-5f);
            int gr = b * P_ + p0 + rl;
            float* orow = out + (size_t)gr * D_;
#pragma unroll
            for (int ni = 0; ni < 8; ni++) {
                int c = wn + ni * 8 + tig * 2;
                float h0 = (hf == 0) ? acc[mi][ni].x : acc[mi][ni].z;
                float h1 = (hf == 0) ? acc[mi][ni].y : acc[mi][ni].w;
                float2 y;
                y.x = (h0 - mu) * inv * s_g[c] + s_b[c];
                y.y = (h1 - mu) * inv * s_g[c + 1] + s_b[c + 1];
                *(float2*)(orow + c) = y;
            }
        }
    }
}

// ---------------- launch ----------------
extern "C" void kernel_launch(void* const* d_in, const int* in_sizes, int n_in,
                              void* d_out, int out_size)
{
    const float* x      = (const float*)d_in[0];
    const float* mlp_w  = (const float*)d_in[1];
    const float* mlp_b  = (const float*)d_in[2];
    const float* his_w  = (const float*)d_in[3];
    const float* his_b  = (const float*)d_in[4];
    const float* cur_w  = (const float*)d_in[5];
    const float* cur_b  = (const float*)d_in[6];
    const float* wl_w   = (const float*)d_in[7];
    const float* wl_b   = (const float*)d_in[8];
    const float* gate_w = (const float*)d_in[9];
    const float* gate_b = (const float*)d_in[10];
    const float* ln_g   = (const float*)d_in[11];
    const float* ln_b   = (const float*)d_in[12];
    float* out = (float*)d_out;

    void *pHbf, *pLbf, *pXM, *pXbf, *pWLbf, *pWCAT, *pPM, *pPS, *pZ;
    cudaGetSymbolAddress(&pHbf, g_Hbf);
    cudaGetSymbolAddress(&pLbf, g_logbf);
    cudaGetSymbolAddress(&pXM, g_xmbf);
    cudaGetSymbolAddress(&pXbf, g_xbf);
    cudaGetSymbolAddress(&pWLbf, g_wlbf);
    cudaGetSymbolAddress(&pWCAT, g_wcatbf);
    cudaGetSymbolAddress(&pPM, g_pmax);
    cudaGetSymbolAddress(&pPS, g_psum);
    cudaGetSymbolAddress(&pZ, g_zero);
    __nv_bfloat16* gHbf   = (__nv_bfloat16*)pHbf;
    __nv_bfloat16* gLbf   = (__nv_bfloat16*)pLbf;
    __nv_bfloat16* gXMbf  = (__nv_bfloat16*)pXM;
    __nv_bfloat16* gXbf   = (__nv_bfloat16*)pXbf;
    __nv_bfloat16* gWLbf  = (__nv_bfloat16*)pWLbf;
    __nv_bfloat16* gWCAT  = (__nv_bfloat16*)pWCAT;
    float* gPM = (float*)pPM;
    float* gPS = (float*)pPS;
    float* gZ  = (float*)pZ;

    const int bf16_smem = L_STGB * 2;        // 37888 bytes
    cudaFuncSetAttribute(k_gemm_bf16, cudaFuncAttributeMaxDynamicSharedMemorySize, bf16_smem);

    // weight conversions
    k_cvt<<<(D_ * P_ / 4) / 256, 256>>>((const float4*)wl_w, (uint2*)gWLbf);
    k_cvtW<<<(D_ * D_) / 256, 256>>>(his_w, mlp_w, gWCAT);

    // gate precompute, then fused x->bf16 + wc
    k_weff<<<D_ / 8, 256>>>(cur_w, cur_b, gate_w, gate_b);
    k_cvtx_wc<<<BP_ / 8, 256>>>(x);

    // [H | xm] = x @ [his_w | mlp_w]  (one merged GEMM, split outputs)
    k_gemm_bf16<<<dim3(512 / 128, BP_ / 128), 256, bf16_smem>>>(
        gXbf, gWCAT, his_b, gZ, gHbf, gXMbf,
        512, D_, 256, 0, nullptr, nullptr);
    // logits = H @ wl_w + wl_b  (bf16 MMA + fused softmax stats)
    k_gemm_bf16<<<dim3(P_ / 128, BP_ / 128), 256, bf16_smem>>>(
        gHbf, gWLbf, wl_b, wl_b, gLbf, gLbf,
        P_, P_, P_, 1, gPM, gPS);
    // combine softmax offsets
    k_rowstat2<<<BP_ / 256, 256>>>();
    // out = LN(tril(softmax)@xm + mlp_b + wc*x)  -- fully fused
    k_agg_bf16<<<dim3(P_ / 64, 1, B_), 256>>>(x, mlp_b, ln_g, ln_b, out);
    // second output: origin
    cudaMemcpyAsync(out + (size_t)BP_ * D_, x,
                    (size_t)BP_ * D_ * sizeof(float),
                    cudaMemcpyDeviceToDevice);
}

// round 16
// speedup vs baseline: 2.4904x; 1.0964x over previous
#include <cuda_runtime.h>
#include <cuda_bf16.h>
#include <cstdint>
#include <cstddef>

#define B_  32
#define P_  2048
#define D_  256
#define BP_ (B_ * P_)   // 65536

// ---------------- device scratch ----------------
__device__ __nv_bfloat16 g_Hbf[(size_t)BP_ * D_];     // 32 MB  H bf16
__device__ __nv_bfloat16 g_logbf[(size_t)BP_ * P_];   // 256 MB logits bf16
__device__ __nv_bfloat16 g_xmbf[(size_t)BP_ * D_];    // 32 MB  xm = x@mlp_w
__device__ __nv_bfloat16 g_xbf[(size_t)BP_ * D_];     // 32 MB  x bf16
__device__ __nv_bfloat16 g_wlbf[(size_t)D_ * P_];     // 1 MB   wl_w bf16
__device__ __nv_bfloat16 g_wcatbf[(size_t)D_ * 512];  // [his_w | mlp_w] bf16
__device__ float g_pmax[(size_t)BP_ * 16];
__device__ float g_psum[(size_t)BP_ * 16];
__device__ float g_rowoff[BP_];
__device__ float g_wc[BP_];
__device__ float g_weff[D_];
__device__ float g_beff;
__device__ float g_zero[D_];                          // stays zero

// ---------------- helpers ----------------
__device__ __forceinline__ void mma_bf16(float4& c, const uint32_t a[4],
                                         uint32_t b0, uint32_t b1) {
    asm volatile(
        "mma.sync.aligned.m16n8k16.row.col.f32.bf16.bf16.f32 "
        "{%0,%1,%2,%3}, {%4,%5,%6,%7}, {%8,%9}, {%0,%1,%2,%3};\n"
        : "+f"(c.x), "+f"(c.y), "+f"(c.z), "+f"(c.w)
        : "r"(a[0]), "r"(a[1]), "r"(a[2]), "r"(a[3]), "r"(b0), "r"(b1));
}

__device__ __forceinline__ void ldsm_x4(uint32_t r[4], uint32_t addr) {
    asm volatile("ldmatrix.sync.aligned.m8n8.x4.shared.b16 {%0,%1,%2,%3}, [%4];"
                 : "=r"(r[0]), "=r"(r[1]), "=r"(r[2]), "=r"(r[3]) : "r"(addr));
}

__device__ __forceinline__ void ldsm_x4t(uint32_t r[4], uint32_t addr) {
    asm volatile("ldmatrix.sync.aligned.m8n8.x4.trans.shared.b16 {%0,%1,%2,%3}, [%4];"
                 : "=r"(r[0]), "=r"(r[1]), "=r"(r[2]), "=r"(r[3]) : "r"(addr));
}

__device__ __forceinline__ void cp16(uint32_t dst_smem, const void* src) {
    asm volatile("cp.async.cg.shared.global [%0], [%1], 16;\n"
                 :: "r"(dst_smem), "l"(src));
}
#define CP_COMMIT()  asm volatile("cp.async.commit_group;\n" ::: "memory")
#define CP_WAIT(n)   asm volatile("cp.async.wait_group %0;\n" :: "n"(n) : "memory")

// ---------------- wl_w fp32 -> bf16 (vectorized x4) ----------------
__global__ void k_cvt(const float4* __restrict__ src, uint2* __restrict__ dst)
{
    int i = blockIdx.x * 256 + threadIdx.x;
    float4 v = src[i];
    __nv_bfloat162 lo = __floats2bfloat162_rn(v.x, v.y);
    __nv_bfloat162 hi = __floats2bfloat162_rn(v.z, v.w);
    uint2 o;
    o.x = *(uint32_t*)&lo;
    o.y = *(uint32_t*)&hi;
    dst[i] = o;
}

// ---------------- build wcat = [his_w | mlp_w] bf16 ----------------
__global__ void k_cvtW(const float* __restrict__ his, const float* __restrict__ mlp,
                       __nv_bfloat16* __restrict__ wcat)
{
    int i = blockIdx.x * 256 + threadIdx.x;     // 0 .. 65535
    int k = i >> 8, c = i & 255;
    wcat[(size_t)k * 512 + c]       = __float2bfloat16(his[i]);
    wcat[(size_t)k * 512 + 256 + c] = __float2bfloat16(mlp[i]);
}

// ---------------- w_eff / b_eff ----------------
__global__ void k_weff(const float* __restrict__ cur_w, const float* __restrict__ cur_b,
                       const float* __restrict__ gate_w, const float* __restrict__ gate_b)
{
    int warp = threadIdx.x >> 5;
    int lane = threadIdx.x & 31;
    int k = blockIdx.x * 8 + warp;
    float s = 0.f;
#pragma unroll
    for (int i = 0; i < 8; i++)
        s += cur_w[(size_t)k * D_ + lane + 32 * i] * __ldg(&gate_w[lane + 32 * i]);
#pragma unroll
    for (int o = 16; o; o >>= 1) s += __shfl_xor_sync(0xffffffffu, s, o);
    if (lane == 0) g_weff[k] = s;

    if (blockIdx.x == 0 && warp == 0) {
        float t = 0.f;
#pragma unroll
        for (int i = 0; i < 8; i++)
            t += cur_b[lane + 32 * i] * __ldg(&gate_w[lane + 32 * i]);
#pragma unroll
        for (int o = 16; o; o >>= 1) t += __shfl_xor_sync(0xffffffffu, t, o);
        if (lane == 0) g_beff = t + gate_b[0];
    }
}

// ---------------- fused: x->bf16, wc[row], AND origin copy (1 warp/row)
__global__ void k_cvtx_wc(const float* __restrict__ x, float* __restrict__ out2)
{
    __shared__ float sw[D_];
    int tid = threadIdx.x;
    sw[tid] = g_weff[tid];
    __syncthreads();
    int warp = tid >> 5, lane = tid & 31;
    int row = blockIdx.x * 8 + warp;
    const float* xr = x + (size_t)row * D_;
    float* o2 = out2 + (size_t)row * D_;
    uint2* dst = (uint2*)(g_xbf + (size_t)row * D_);
    float s = 0.f;
#pragma unroll
    for (int j = 0; j < 2; j++) {
        int c = lane * 4 + j * 128;
        float4 v = *(const float4*)(xr + c);
        __nv_bfloat162 lo = __floats2bfloat162_rn(v.x, v.y);
        __nv_bfloat162 hi = __floats2bfloat162_rn(v.z, v.w);
        uint2 o;
        o.x = *(uint32_t*)&lo;
        o.y = *(uint32_t*)&hi;
        dst[lane + j * 32] = o;
        *(float4*)(o2 + c) = v;                 // origin copy fused
        s += v.x * sw[c] + v.y * sw[c + 1] + v.z * sw[c + 2] + v.w * sw[c + 3];
    }
#pragma unroll
    for (int o = 16; o; o >>= 1) s += __shfl_xor_sync(0xffffffffu, s, o);
    if (lane == 0) g_wc[row] = s + g_beff;
}

// ---------------- BF16 GEMM: C = Abf[M,256] @ Bbf[256,N] + bias
// block 128x128, 8 warps (2m x 4n), warp tile 64x32, K-tile 32, K=256.
// Split-output mode + optional fused softmax stats.
#define L_ABYTES (128 * 80)     // 10240
#define L_BBYTES (32 * 272)     // 8704
#define L_STGB (L_ABYTES + L_BBYTES)

__global__ __launch_bounds__(256, 2) void k_gemm_bf16(
    const __nv_bfloat16* __restrict__ A, const __nv_bfloat16* __restrict__ Bm,
    const float* __restrict__ bias, const float* __restrict__ bias2,
    __nv_bfloat16* __restrict__ C, __nv_bfloat16* __restrict__ C2,
    int N, int Nout, int splitcol, int do_stats,
    float* __restrict__ pmax, float* __restrict__ psum)
{
    extern __shared__ float sm[];
    const uint32_t smb = (uint32_t)__cvta_generic_to_shared(sm);

    const int tid  = threadIdx.x;
    const int lane = tid & 31;
    const int warp = tid >> 5;
    const int wm = (warp & 1) * 64;
    const int wn = (warp >> 1) * 32;
    const int wcol = warp >> 1;
    const int g   = lane >> 2;
    const int tig = lane & 3;
    const int row0 = blockIdx.y * 128;
    const int col0 = blockIdx.x * 128;

    const int rowit = lane & 15;
    const int colb  = (lane & 16) ? 16 : 0;

    __nv_bfloat16* Cout = C;
    const float* bptr = bias;
    int cbase = col0;
    if (col0 >= splitcol) { Cout = C2; bptr = bias2; cbase = col0 - splitcol; }

    float4 acc[4][4];
#pragma unroll
    for (int mi = 0; mi < 4; mi++)
#pragma unroll
        for (int ni = 0; ni < 4; ni++) acc[mi][ni] = make_float4(0.f, 0.f, 0.f, 0.f);

    {
#pragma unroll
        for (int i = 0; i < 2; i++) {
            int id = tid + i * 256;
            int rw = id >> 2, ch = id & 3;
            cp16(smb + (uint32_t)(rw * 80 + ch * 16),
                 A + (size_t)(row0 + rw) * 256 + ch * 8);
            int brw = id >> 4, bch = id & 15;
            cp16(smb + (uint32_t)(L_ABYTES + brw * 272 + bch * 16),
                 Bm + (size_t)brw * N + col0 + bch * 8);
        }
        CP_COMMIT();
    }

#pragma unroll 2
    for (int kt = 0; kt < 8; kt++) {
        const int s = kt & 1;
        if (kt < 7) {
            uint32_t base = smb + (uint32_t)((s ^ 1) * L_STGB);
            const int k0 = (kt + 1) * 32;
#pragma unroll
            for (int i = 0; i < 2; i++) {
                int id = tid + i * 256;
                int rw = id >> 2, ch = id & 3;
                cp16(base + (uint32_t)(rw * 80 + ch * 16),
                     A + (size_t)(row0 + rw) * 256 + k0 + ch * 8);
                int brw = id >> 4, bch = id & 15;
                cp16(base + (uint32_t)(L_ABYTES + brw * 272 + bch * 16),
                     Bm + (size_t)(k0 + brw) * N + col0 + bch * 8);
            }
            CP_COMMIT();
            CP_WAIT(1);
        } else {
            CP_WAIT(0);
        }
        __syncthreads();

        const uint32_t aB = smb + (uint32_t)(s * L_STGB + (wm + rowit) * 80 + colb);
        const uint32_t bB = smb + (uint32_t)(s * L_STGB + L_ABYTES + rowit * 272 + colb + wn * 2);
#pragma unroll
        for (int ks = 0; ks < 2; ks++) {
            uint32_t af[4][4];
#pragma unroll
            for (int mi = 0; mi < 4; mi++)
                ldsm_x4(af[mi], aB + (uint32_t)(mi * 16 * 80 + ks * 32));
#pragma unroll
            for (int nj = 0; nj < 2; nj++) {
                uint32_t bq[4];
                ldsm_x4t(bq, bB + (uint32_t)(ks * 16 * 272 + nj * 32));
#pragma unroll
                for (int mi = 0; mi < 4; mi++) {
                    mma_bf16(acc[mi][nj * 2],     af[mi], bq[0], bq[1]);
                    mma_bf16(acc[mi][nj * 2 + 1], af[mi], bq[2], bq[3]);
                }
            }
        }
        __syncthreads();
    }

#pragma unroll
    for (int ni = 0; ni < 4; ni++) {
        int c = cbase + wn + ni * 8 + tig * 2;
        float b0 = bptr[c], b1 = bptr[c + 1];
#pragma unroll
        for (int mi = 0; mi < 4; mi++) {
            acc[mi][ni].x += b0; acc[mi][ni].y += b1;
            acc[mi][ni].z += b0; acc[mi][ni].w += b1;
        }
    }

#pragma unroll
    for (int mi = 0; mi < 4; mi++) {
        int r = row0 + wm + mi * 16 + g;
#pragma unroll
        for (int ni = 0; ni < 4; ni++) {
            int c = cbase + wn + ni * 8 + tig * 2;
            __nv_bfloat162 v0 = __floats2bfloat162_rn(acc[mi][ni].x, acc[mi][ni].y);
            __nv_bfloat162 v1 = __floats2bfloat162_rn(acc[mi][ni].z, acc[mi][ni].w);
            *(__nv_bfloat162*)(Cout + (size_t)r * Nout + c) = v0;
            *(__nv_bfloat162*)(Cout + (size_t)(r + 8) * Nout + c) = v1;
        }
    }

    if (do_stats) {
        float* red_m = sm;          // [128][4]
        float* red_s = sm + 512;    // [128][4]
#pragma unroll
        for (int mi = 0; mi < 4; mi++) {
            float m1 = -1e30f, m2 = -1e30f;
#pragma unroll
            for (int ni = 0; ni < 4; ni++) {
                m1 = fmaxf(m1, fmaxf(acc[mi][ni].x, acc[mi][ni].y));
                m2 = fmaxf(m2, fmaxf(acc[mi][ni].z, acc[mi][ni].w));
            }
            m1 = fmaxf(m1, __shfl_xor_sync(0xffffffffu, m1, 1));
            m1 = fmaxf(m1, __shfl_xor_sync(0xffffffffu, m1, 2));
            m2 = fmaxf(m2, __shfl_xor_sync(0xffffffffu, m2, 1));
            m2 = fmaxf(m2, __shfl_xor_sync(0xffffffffu, m2, 2));
            float s1 = 0.f, s2 = 0.f;
#pragma unroll
            for (int ni = 0; ni < 4; ni++) {
                s1 += __expf(acc[mi][ni].x - m1) + __expf(acc[mi][ni].y - m1);
                s2 += __expf(acc[mi][ni].z - m2) + __expf(acc[mi][ni].w - m2);
            }
            s1 += __shfl_xor_sync(0xffffffffu, s1, 1);
            s1 += __shfl_xor_sync(0xffffffffu, s1, 2);
            s2 += __shfl_xor_sync(0xffffffffu, s2, 1);
            s2 += __shfl_xor_sync(0xffffffffu, s2, 2);
            if (tig == 0) {
                int rb1 = wm + mi * 16 + g;
                red_m[rb1 * 4 + wcol] = m1;  red_s[rb1 * 4 + wcol] = s1;
                red_m[(rb1 + 8) * 4 + wcol] = m2;  red_s[(rb1 + 8) * 4 + wcol] = s2;
            }
        }
        __syncthreads();
        if (tid < 128) {
            float M = -1e30f;
#pragma unroll
            for (int j = 0; j < 4; j++) M = fmaxf(M, red_m[tid * 4 + j]);
            float S = 0.f;
#pragma unroll
            for (int j = 0; j < 4; j++)
                S += red_s[tid * 4 + j] * __expf(red_m[tid * 4 + j] - M);
            size_t idx = (size_t)(row0 + tid) * 16 + blockIdx.x;
            pmax[idx] = M;
            psum[idx] = S;
        }
    }
}

// ---------------- combine partials ----------------
__global__ void k_rowstat2()
{
    int row = blockIdx.x * 256 + threadIdx.x;
    const float* pm = g_pmax + (size_t)row * 16;
    const float* ps = g_psum + (size_t)row * 16;
    float M = -1e30f;
#pragma unroll
    for (int j = 0; j < 16; j++) M = fmaxf(M, pm[j]);
    float S = 0.f;
#pragma unroll
    for (int j = 0; j < 16; j++) S += ps[j] * __expf(pm[j] - M);
    g_rowoff[row] = M + __logf(S);
}

// ---------------- BF16 agg + fused LN epilogue — double-buffered mainloop
// acc = tril(softmax(logits)) @ xm; out = LN(acc + mlp_b + wc*x)*ln_g + ln_b.
// Stages: As[2] 64x32 exp tile (5120 B each), Bs[2] 32x256 xm tile (16896 B each).
#define AG_AST 5120
#define AG_BST 16896

__global__ __launch_bounds__(256, 2) void k_agg_bf16(
    const float* __restrict__ x, const float* __restrict__ mlp_b,
    const float* __restrict__ ln_g, const float* __restrict__ ln_b,
    float* __restrict__ out)
{
    __shared__ __align__(16) char AsB[2 * AG_AST];   // 10240 B
    __shared__ __align__(16) char BsB[2 * AG_BST];   // 33792 B
    __shared__ float red_s[64 * 4];
    __shared__ float red_q[64 * 4];
    __shared__ float s_mb[256], s_g[256], s_b[256];

    const uint32_t asb = (uint32_t)__cvta_generic_to_shared(AsB);
    const uint32_t bsb = (uint32_t)__cvta_generic_to_shared(BsB);

    const int b  = blockIdx.z;
    const int p0 = ((int)gridDim.x - 1 - (int)blockIdx.x) * 64;   // longest blocks first
    const int tid  = threadIdx.x;
    const int lane = tid & 31;
    const int warp = tid >> 5;
    const int wm = (warp & 1) * 32;
    const int wn = (warp >> 1) * 64;
    const int wngrp = warp >> 1;
    const int g   = lane >> 2;
    const int tig = lane & 3;

    s_mb[tid] = mlp_b[tid];
    s_g[tid]  = ln_g[tid];
    s_b[tid]  = ln_b[tid];

    const int ar  = tid >> 2;
    const int ac8 = (tid & 3) * 8;
    const int prow = p0 + ar;
    const float off = g_rowoff[b * P_ + prow];
    const __nv_bfloat16* Lp = g_logbf + (size_t)(b * P_ + prow) * P_ + ac8;
    const __nv_bfloat16* xmb = g_xmbf + (size_t)b * P_ * D_;

    const int rowit = lane & 15;
    const int colb  = (lane & 16) ? 16 : 0;

    float4 acc[2][8];
#pragma unroll
    for (int mi = 0; mi < 2; mi++)
#pragma unroll
        for (int ni = 0; ni < 8; ni++) acc[mi][ni] = make_float4(0.f, 0.f, 0.f, 0.f);

    const int nkt = (p0 + 64) / 32;

    // prologue: issue Bs[0] (tile 0), preload logits regs for tile 0
#pragma unroll
    for (int t = 0; t < 4; t++) {
        int id = tid + t * 256;
        int krow = id >> 5;
        int ch = id & 31;
        cp16(bsb + (uint32_t)(krow * 528 + ch * 16),
             xmb + (size_t)krow * D_ + ch * 8);
    }
    CP_COMMIT();
    uint4 raw = *(const uint4*)(Lp);

    for (int kt = 0; kt < nkt; kt++) {
        const int s = kt & 1;
        const int k0 = kt * 32;

        // exp + mask + cvt bf16 -> As[s]  (tile kt; As[s] free since compute kt-2)
        {
            const __nv_bfloat162* h = (const __nv_bfloat162*)&raw;
            float2 f0 = __bfloat1622float2(h[0]);
            float2 f1 = __bfloat1622float2(h[1]);
            float2 f2 = __bfloat1622float2(h[2]);
            float2 f3 = __bfloat1622float2(h[3]);
            int kq = k0 + ac8;
            float e0 = (kq     <= prow) ? __expf(f0.x - off) : 0.f;
            float e1 = (kq + 1 <= prow) ? __expf(f0.y - off) : 0.f;
            float e2 = (kq + 2 <= prow) ? __expf(f1.x - off) : 0.f;
            float e3 = (kq + 3 <= prow) ? __expf(f1.y - off) : 0.f;
            float e4 = (kq + 4 <= prow) ? __expf(f2.x - off) : 0.f;
            float e5 = (kq + 5 <= prow) ? __expf(f2.y - off) : 0.f;
            float e6 = (kq + 6 <= prow) ? __expf(f3.x - off) : 0.f;
            float e7 = (kq + 7 <= prow) ? __expf(f3.y - off) : 0.f;
            __nv_bfloat162 p0b = __floats2bfloat162_rn(e0, e1);
            __nv_bfloat162 p1b = __floats2bfloat162_rn(e2, e3);
            __nv_bfloat162 p2b = __floats2bfloat162_rn(e4, e5);
            __nv_bfloat162 p3b = __floats2bfloat162_rn(e6, e7);
            uint4 pk;
            pk.x = *(uint32_t*)&p0b; pk.y = *(uint32_t*)&p1b;
            pk.z = *(uint32_t*)&p2b; pk.w = *(uint32_t*)&p3b;
            *(uint4*)(AsB + s * AG_AST + ar * 80 + ac8 * 2) = pk;
        }

        CP_WAIT(0);          // tile kt's Bs load complete (only group in flight)
        __syncthreads();     // As[s] + Bs[s] visible; compute(kt-1) done everywhere

        // issue Bs[s^1] for tile kt+1 (overlaps compute below)
        if (kt + 1 < nkt) {
            const int kn = k0 + 32;
#pragma unroll
            for (int t = 0; t < 4; t++) {
                int id = tid + t * 256;
                int krow = id >> 5;
                int ch = id & 31;
                cp16(bsb + (uint32_t)((s ^ 1) * AG_BST + krow * 528 + ch * 16),
                     xmb + (size_t)(kn + krow) * D_ + ch * 8);
            }
            CP_COMMIT();
            raw = *(const uint4*)(Lp + kn);
        }

        const uint32_t aB = asb + (uint32_t)(s * AG_AST + (wm + rowit) * 80 + colb);
        const uint32_t bB = bsb + (uint32_t)(s * AG_BST + rowit * 528 + colb + wn * 2);
#pragma unroll
        for (int ks = 0; ks < 2; ks++) {
            uint32_t af[2][4];
#pragma unroll
            for (int mi = 0; mi < 2; mi++)
                ldsm_x4(af[mi], aB + (uint32_t)(mi * 16 * 80 + ks * 32));
#pragma unroll
            for (int nj = 0; nj < 4; nj++) {
                uint32_t bq[4];
                ldsm_x4t(bq, bB + (uint32_t)(ks * 16 * 528 + nj * 32));
#pragma unroll
                for (int mi = 0; mi < 2; mi++) {
                    mma_bf16(acc[mi][nj * 2],     af[mi], bq[0], bq[1]);
                    mma_bf16(acc[mi][nj * 2 + 1], af[mi], bq[2], bq[3]);
                }
            }
        }
    }

    // ===== fused epilogue: h = acc + mlp_b + wc*x; LN; write out =====
    float ssum[2][2] = {{0.f, 0.f}, {0.f, 0.f}};
    float qsum[2][2] = {{0.f, 0.f}, {0.f, 0.f}};
#pragma unroll
    for (int mi = 0; mi < 2; mi++) {
        int gr0 = b * P_ + p0 + wm + mi * 16 + g;
        int gr1 = gr0 + 8;
        float wc0 = g_wc[gr0], wc1 = g_wc[gr1];
        const float* xr0 = x + (size_t)gr0 * D_;
        const float* xr1 = x + (size_t)gr1 * D_;
#pragma unroll
        for (int ni = 0; ni < 8; ni++) {
            int c = wn + ni * 8 + tig * 2;
            float2 xv0 = *(const float2*)(xr0 + c);
            float2 xv1 = *(const float2*)(xr1 + c);
            acc[mi][ni].x += s_mb[c]     + wc0 * xv0.x;
            acc[mi][ni].y += s_mb[c + 1] + wc0 * xv0.y;
            acc[mi][ni].z += s_mb[c]     + wc1 * xv1.x;
            acc[mi][ni].w += s_mb[c + 1] + wc1 * xv1.y;
            ssum[mi][0] += acc[mi][ni].x + acc[mi][ni].y;
            ssum[mi][1] += acc[mi][ni].z + acc[mi][ni].w;
            qsum[mi][0] += acc[mi][ni].x * acc[mi][ni].x + acc[mi][ni].y * acc[mi][ni].y;
            qsum[mi][1] += acc[mi][ni].z * acc[mi][ni].z + acc[mi][ni].w * acc[mi][ni].w;
        }
    }
#pragma unroll
    for (int mi = 0; mi < 2; mi++)
#pragma unroll
        for (int hf = 0; hf < 2; hf++) {
            ssum[mi][hf] += __shfl_xor_sync(0xffffffffu, ssum[mi][hf], 1);
            ssum[mi][hf] += __shfl_xor_sync(0xffffffffu, ssum[mi][hf], 2);
            qsum[mi][hf] += __shfl_xor_sync(0xffffffffu, qsum[mi][hf], 1);
            qsum[mi][hf] += __shfl_xor_sync(0xffffffffu, qsum[mi][hf], 2);
        }
    if (tig == 0) {
#pragma unroll
        for (int mi = 0; mi < 2; mi++)
#pragma unroll
            for (int hf = 0; hf < 2; hf++) {
                int rl = wm + mi * 16 + g + hf * 8;
                red_s[rl * 4 + wngrp] = ssum[mi][hf];
                red_q[rl * 4 + wngrp] = qsum[mi][hf];
            }
    }
    __syncthreads();

#pragma unroll
    for (int mi = 0; mi < 2; mi++) {
#pragma unroll
        for (int hf = 0; hf < 2; hf++) {
            int rl = wm + mi * 16 + g + hf * 8;
            float S = red_s[rl * 4] + red_s[rl * 4 + 1] + red_s[rl * 4 + 2] + red_s[rl * 4 + 3];
            float Q = red_q[rl * 4] + red_q[rl * 4 + 1] + red_q[rl * 4 + 2] + red_q[rl * 4 + 3];
            float mu = S * (1.0f / 256.0f);
            float var = Q * (1.0f / 256.0f) - mu * mu;
            float inv = rsqrtf(var + 1e-5f);
            int gr = b * P_ + p0 + rl;
            float* orow = out + (size_t)gr * D_;
#pragma unroll
            for (int ni = 0; ni < 8; ni++) {
                int c = wn + ni * 8 + tig * 2;
                float h0 = (hf == 0) ? acc[mi][ni].x : acc[mi][ni].z;
                float h1 = (hf == 0) ? acc[mi][ni].y : acc[mi][ni].w;
                float2 y;
                y.x = (h0 - mu) * inv * s_g[c] + s_b[c];
                y.y = (h1 - mu) * inv * s_g[c + 1] + s_b[c + 1];
                *(float2*)(orow + c) = y;
            }
        }
    }
}

// ---------------- launch ----------------
extern "C" void kernel_launch(void* const* d_in, const int* in_sizes, int n_in,
                              void* d_out, int out_size)
{
    const float* x      = (const float*)d_in[0];
    const float* mlp_w  = (const float*)d_in[1];
    const float* mlp_b  = (const float*)d_in[2];
    const float* his_w  = (const float*)d_in[3];
    const float* his_b  = (const float*)d_in[4];
    const float* cur_w  = (const float*)d_in[5];
    const float* cur_b  = (const float*)d_in[6];
    const float* wl_w   = (const float*)d_in[7];
    const float* wl_b   = (const float*)d_in[8];
    const float* gate_w = (const float*)d_in[9];
    const float* gate_b = (const float*)d_in[10];
    const float* ln_g   = (const float*)d_in[11];
    const float* ln_b   = (const float*)d_in[12];
    float* out = (float*)d_out;

    void *pHbf, *pLbf, *pXM, *pXbf, *pWLbf, *pWCAT, *pPM, *pPS, *pZ;
    cudaGetSymbolAddress(&pHbf, g_Hbf);
    cudaGetSymbolAddress(&pLbf, g_logbf);
    cudaGetSymbolAddress(&pXM, g_xmbf);
    cudaGetSymbolAddress(&pXbf, g_xbf);
    cudaGetSymbolAddress(&pWLbf, g_wlbf);
    cudaGetSymbolAddress(&pWCAT, g_wcatbf);
    cudaGetSymbolAddress(&pPM, g_pmax);
    cudaGetSymbolAddress(&pPS, g_psum);
    cudaGetSymbolAddress(&pZ, g_zero);
    __nv_bfloat16* gHbf   = (__nv_bfloat16*)pHbf;
    __nv_bfloat16* gLbf   = (__nv_bfloat16*)pLbf;
    __nv_bfloat16* gXMbf  = (__nv_bfloat16*)pXM;
    __nv_bfloat16* gXbf   = (__nv_bfloat16*)pXbf;
    __nv_bfloat16* gWLbf  = (__nv_bfloat16*)pWLbf;
    __nv_bfloat16* gWCAT  = (__nv_bfloat16*)pWCAT;
    float* gPM = (float*)pPM;
    float* gPS = (float*)pPS;
    float* gZ  = (float*)pZ;

    const int bf16_smem = L_STGB * 2;        // 37888 bytes
    cudaFuncSetAttribute(k_gemm_bf16, cudaFuncAttributeMaxDynamicSharedMemorySize, bf16_smem);

    // weight conversions
    k_cvt<<<(D_ * P_ / 4) / 256, 256>>>((const float4*)wl_w, (uint2*)gWLbf);
    k_cvtW<<<(D_ * D_) / 256, 256>>>(his_w, mlp_w, gWCAT);

    // gate precompute; fused x->bf16 + wc + origin copy
    k_weff<<<D_ / 8, 256>>>(cur_w, cur_b, gate_w, gate_b);
    k_cvtx_wc<<<BP_ / 8, 256>>>(x, out + (size_t)BP_ * D_);

    // [H | xm] = x @ [his_w | mlp_w]  (one merged GEMM, split outputs)
    k_gemm_bf16<<<dim3(512 / 128, BP_ / 128), 256, bf16_smem>>>(
        gXbf, gWCAT, his_b, gZ, gHbf, gXMbf,
        512, D_, 256, 0, nullptr, nullptr);
    // logits = H @ wl_w + wl_b  (bf16 MMA + fused softmax stats)
    k_gemm_bf16<<<dim3(P_ / 128, BP_ / 128), 256, bf16_smem>>>(
        gHbf, gWLbf, wl_b, wl_b, gLbf, gLbf,
        P_, P_, P_, 1, gPM, gPS);
    // combine softmax offsets
    k_rowstat2<<<BP_ / 256, 256>>>();
    // out = LN(tril(softmax)@xm + mlp_b + wc*x)  -- fully fused, double-buffered
    k_agg_bf16<<<dim3(P_ / 64, 1, B_), 256>>>(x, mlp_b, ln_g, ln_b, out);
}

// round 17
// speedup vs baseline: 2.7820x; 1.1171x over previous
#include <cuda_runtime.h>
#include <cuda_bf16.h>
#include <cstdint>
#include <cstddef>

#define B_  32
#define P_  2048
#define D_  256
#define BP_ (B_ * P_)   // 65536

// ---------------- device scratch ----------------
__device__ __nv_bfloat16 g_Hbf[(size_t)BP_ * D_];     // 32 MB  H bf16
__device__ __nv_bfloat16 g_logbf[(size_t)BP_ * P_];   // 256 MB logits bf16
__device__ __nv_bfloat16 g_xmbf[(size_t)BP_ * D_];    // 32 MB  xm = x@mlp_w
__device__ __nv_bfloat16 g_xbf[(size_t)BP_ * D_];     // 32 MB  x bf16
__device__ __nv_bfloat16 g_wlbf[(size_t)D_ * P_];     // 1 MB   wl_w bf16
__device__ __nv_bfloat16 g_wcatbf[(size_t)D_ * 512];  // [his_w | mlp_w] bf16
__device__ float g_pmax[(size_t)BP_ * 16];
__device__ float g_psum[(size_t)BP_ * 16];
__device__ float g_rowoff[BP_];
__device__ float g_wc[BP_];
__device__ float g_weff[D_];
__device__ float g_beff;
__device__ float g_zero[D_];                          // stays zero

// ---------------- helpers ----------------
__device__ __forceinline__ void mma_bf16(float4& c, const uint32_t a[4],
                                         uint32_t b0, uint32_t b1) {
    asm volatile(
        "mma.sync.aligned.m16n8k16.row.col.f32.bf16.bf16.f32 "
        "{%0,%1,%2,%3}, {%4,%5,%6,%7}, {%8,%9}, {%0,%1,%2,%3};\n"
        : "+f"(c.x), "+f"(c.y), "+f"(c.z), "+f"(c.w)
        : "r"(a[0]), "r"(a[1]), "r"(a[2]), "r"(a[3]), "r"(b0), "r"(b1));
}

__device__ __forceinline__ void ldsm_x4(uint32_t r[4], uint32_t addr) {
    asm volatile("ldmatrix.sync.aligned.m8n8.x4.shared.b16 {%0,%1,%2,%3}, [%4];"
                 : "=r"(r[0]), "=r"(r[1]), "=r"(r[2]), "=r"(r[3]) : "r"(addr));
}

__device__ __forceinline__ void ldsm_x4t(uint32_t r[4], uint32_t addr) {
    asm volatile("ldmatrix.sync.aligned.m8n8.x4.trans.shared.b16 {%0,%1,%2,%3}, [%4];"
                 : "=r"(r[0]), "=r"(r[1]), "=r"(r[2]), "=r"(r[3]) : "r"(addr));
}

__device__ __forceinline__ void cp16(uint32_t dst_smem, const void* src) {
    asm volatile("cp.async.cg.shared.global [%0], [%1], 16;\n"
                 :: "r"(dst_smem), "l"(src));
}
#define CP_COMMIT()  asm volatile("cp.async.commit_group;\n" ::: "memory")
#define CP_WAIT(n)   asm volatile("cp.async.wait_group %0;\n" :: "n"(n) : "memory")

// ---------------- wl_w fp32 -> bf16 (vectorized x4) ----------------
__global__ void k_cvt(const float4* __restrict__ src, uint2* __restrict__ dst)
{
    int i = blockIdx.x * 256 + threadIdx.x;
    float4 v = src[i];
    __nv_bfloat162 lo = __floats2bfloat162_rn(v.x, v.y);
    __nv_bfloat162 hi = __floats2bfloat162_rn(v.z, v.w);
    uint2 o;
    o.x = *(uint32_t*)&lo;
    o.y = *(uint32_t*)&hi;
    dst[i] = o;
}

// ---------------- build wcat = [his_w | mlp_w] bf16 ----------------
__global__ void k_cvtW(const float* __restrict__ his, const float* __restrict__ mlp,
                       __nv_bfloat16* __restrict__ wcat)
{
    int i = blockIdx.x * 256 + threadIdx.x;     // 0 .. 65535
    int k = i >> 8, c = i & 255;
    wcat[(size_t)k * 512 + c]       = __float2bfloat16(his[i]);
    wcat[(size_t)k * 512 + 256 + c] = __float2bfloat16(mlp[i]);
}

// ---------------- w_eff / b_eff ----------------
__global__ void k_weff(const float* __restrict__ cur_w, const float* __restrict__ cur_b,
                       const float* __restrict__ gate_w, const float* __restrict__ gate_b)
{
    int warp = threadIdx.x >> 5;
    int lane = threadIdx.x & 31;
    int k = blockIdx.x * 8 + warp;
    float s = 0.f;
#pragma unroll
    for (int i = 0; i < 8; i++)
        s += cur_w[(size_t)k * D_ + lane + 32 * i] * __ldg(&gate_w[lane + 32 * i]);
#pragma unroll
    for (int o = 16; o; o >>= 1) s += __shfl_xor_sync(0xffffffffu, s, o);
    if (lane == 0) g_weff[k] = s;

    if (blockIdx.x == 0 && warp == 0) {
        float t = 0.f;
#pragma unroll
        for (int i = 0; i < 8; i++)
            t += cur_b[lane + 32 * i] * __ldg(&gate_w[lane + 32 * i]);
#pragma unroll
        for (int o = 16; o; o >>= 1) t += __shfl_xor_sync(0xffffffffu, t, o);
        if (lane == 0) g_beff = t + gate_b[0];
    }
}

// ---------------- fused: x->bf16, wc[row], AND origin copy (1 warp/row)
__global__ void k_cvtx_wc(const float* __restrict__ x, float* __restrict__ out2)
{
    __shared__ float sw[D_];
    int tid = threadIdx.x;
    sw[tid] = g_weff[tid];
    __syncthreads();
    int warp = tid >> 5, lane = tid & 31;
    int row = blockIdx.x * 8 + warp;
    const float* xr = x + (size_t)row * D_;
    float* o2 = out2 + (size_t)row * D_;
    uint2* dst = (uint2*)(g_xbf + (size_t)row * D_);
    float s = 0.f;
#pragma unroll
    for (int j = 0; j < 2; j++) {
        int c = lane * 4 + j * 128;
        float4 v = *(const float4*)(xr + c);
        __nv_bfloat162 lo = __floats2bfloat162_rn(v.x, v.y);
        __nv_bfloat162 hi = __floats2bfloat162_rn(v.z, v.w);
        uint2 o;
        o.x = *(uint32_t*)&lo;
        o.y = *(uint32_t*)&hi;
        dst[lane + j * 32] = o;
        *(float4*)(o2 + c) = v;                 // origin copy fused
        s += v.x * sw[c] + v.y * sw[c + 1] + v.z * sw[c + 2] + v.w * sw[c + 3];
    }
#pragma unroll
    for (int o = 16; o; o >>= 1) s += __shfl_xor_sync(0xffffffffu, s, o);
    if (lane == 0) g_wc[row] = s + g_beff;
}

// ---------------- BF16 GEMM: C = Abf[M,256] @ Bbf[256,N] + bias
// block 128x128, 8 warps (2m x 4n), warp tile 64x32, K-tile 64 (4 k16 steps).
// Single-sync double-buffered mainloop (4 iterations, 4 syncs).
// A smem [m][k64] stride 144B; B smem [k64][n128] stride 272B.
// Split-output mode + optional fused softmax stats.
#define L_AST 144
#define L_ABYTES (128 * L_AST)   // 18432
#define L_BBYTES (64 * 272)      // 17408
#define L_STGB (L_ABYTES + L_BBYTES)   // 35840

__global__ __launch_bounds__(256, 2) void k_gemm_bf16(
    const __nv_bfloat16* __restrict__ A, const __nv_bfloat16* __restrict__ Bm,
    const float* __restrict__ bias, const float* __restrict__ bias2,
    __nv_bfloat16* __restrict__ C, __nv_bfloat16* __restrict__ C2,
    int N, int Nout, int splitcol, int do_stats,
    float* __restrict__ pmax, float* __restrict__ psum)
{
    extern __shared__ float sm[];
    const uint32_t smb = (uint32_t)__cvta_generic_to_shared(sm);

    const int tid  = threadIdx.x;
    const int lane = tid & 31;
    const int warp = tid >> 5;
    const int wm = (warp & 1) * 64;
    const int wn = (warp >> 1) * 32;
    const int wcol = warp >> 1;
    const int g   = lane >> 2;
    const int tig = lane & 3;
    const int row0 = blockIdx.y * 128;
    const int col0 = blockIdx.x * 128;

    const int rowit = lane & 15;
    const int colb  = (lane & 16) ? 16 : 0;

    __nv_bfloat16* Cout = C;
    const float* bptr = bias;
    int cbase = col0;
    if (col0 >= splitcol) { Cout = C2; bptr = bias2; cbase = col0 - splitcol; }

    // loader indices (per 64-K stage): A 1024 chunks, B 1024 chunks
    const int a_rw = tid >> 1;               // with i-loop: row = (tid + i*256)>>3
    (void)a_rw;

    float4 acc[4][4];
#pragma unroll
    for (int mi = 0; mi < 4; mi++)
#pragma unroll
        for (int ni = 0; ni < 4; ni++) acc[mi][ni] = make_float4(0.f, 0.f, 0.f, 0.f);

    // prologue: load tile 0 into stage 0
    {
#pragma unroll
        for (int i = 0; i < 4; i++) {
            int id = tid + i * 256;
            int rw = id >> 3, ch = id & 7;
            cp16(smb + (uint32_t)(rw * L_AST + ch * 16),
                 A + (size_t)(row0 + rw) * 256 + ch * 8);
            int brw = id >> 4, bch = id & 15;
            cp16(smb + (uint32_t)(L_ABYTES + brw * 272 + bch * 16),
                 Bm + (size_t)brw * N + col0 + bch * 8);
        }
        CP_COMMIT();
    }

#pragma unroll
    for (int kt = 0; kt < 4; kt++) {
        const int s = kt & 1;
        CP_WAIT(0);
        __syncthreads();

        // issue next tile into the other stage (overlaps compute below)
        if (kt < 3) {
            const int k0 = (kt + 1) * 64;
            uint32_t base = smb + (uint32_t)((s ^ 1) * L_STGB);
#pragma unroll
            for (int i = 0; i < 4; i++) {
                int id = tid + i * 256;
                int rw = id >> 3, ch = id & 7;
                cp16(base + (uint32_t)(rw * L_AST + ch * 16),
                     A + (size_t)(row0 + rw) * 256 + k0 + ch * 8);
                int brw = id >> 4, bch = id & 15;
                cp16(base + (uint32_t)(L_ABYTES + brw * 272 + bch * 16),
                     Bm + (size_t)(k0 + brw) * N + col0 + bch * 8);
            }
            CP_COMMIT();
        }

        const uint32_t aB = smb + (uint32_t)(s * L_STGB + (wm + rowit) * L_AST + colb);
        const uint32_t bB = smb + (uint32_t)(s * L_STGB + L_ABYTES + rowit * 272 + colb + wn * 2);
#pragma unroll
        for (int ks = 0; ks < 4; ks++) {
            uint32_t af[4][4];
#pragma unroll
            for (int mi = 0; mi < 4; mi++)
                ldsm_x4(af[mi], aB + (uint32_t)(mi * 16 * L_AST + ks * 32));
#pragma unroll
            for (int nj = 0; nj < 2; nj++) {
                uint32_t bq[4];
                ldsm_x4t(bq, bB + (uint32_t)(ks * 16 * 272 + nj * 32));
#pragma unroll
                for (int mi = 0; mi < 4; mi++) {
                    mma_bf16(acc[mi][nj * 2],     af[mi], bq[0], bq[1]);
                    mma_bf16(acc[mi][nj * 2 + 1], af[mi], bq[2], bq[3]);
                }
            }
        }
    }

#pragma unroll
    for (int ni = 0; ni < 4; ni++) {
        int c = cbase + wn + ni * 8 + tig * 2;
        float b0 = bptr[c], b1 = bptr[c + 1];
#pragma unroll
        for (int mi = 0; mi < 4; mi++) {
            acc[mi][ni].x += b0; acc[mi][ni].y += b1;
            acc[mi][ni].z += b0; acc[mi][ni].w += b1;
        }
    }

#pragma unroll
    for (int mi = 0; mi < 4; mi++) {
        int r = row0 + wm + mi * 16 + g;
#pragma unroll
        for (int ni = 0; ni < 4; ni++) {
            int c = cbase + wn + ni * 8 + tig * 2;
            __nv_bfloat162 v0 = __floats2bfloat162_rn(acc[mi][ni].x, acc[mi][ni].y);
            __nv_bfloat162 v1 = __floats2bfloat162_rn(acc[mi][ni].z, acc[mi][ni].w);
            *(__nv_bfloat162*)(Cout + (size_t)r * Nout + c) = v0;
            *(__nv_bfloat162*)(Cout + (size_t)(r + 8) * Nout + c) = v1;
        }
    }

    if (do_stats) {
        // reduction scratch lives in stage-0 A region (last compute used stage 1)
        float* red_m = sm;          // [128][4]
        float* red_s = sm + 512;    // [128][4]
#pragma unroll
        for (int mi = 0; mi < 4; mi++) {
            float m1 = -1e30f, m2 = -1e30f;
#pragma unroll
            for (int ni = 0; ni < 4; ni++) {
                m1 = fmaxf(m1, fmaxf(acc[mi][ni].x, acc[mi][ni].y));
                m2 = fmaxf(m2, fmaxf(acc[mi][ni].z, acc[mi][ni].w));
            }
            m1 = fmaxf(m1, __shfl_xor_sync(0xffffffffu, m1, 1));
            m1 = fmaxf(m1, __shfl_xor_sync(0xffffffffu, m1, 2));
            m2 = fmaxf(m2, __shfl_xor_sync(0xffffffffu, m2, 1));
            m2 = fmaxf(m2, __shfl_xor_sync(0xffffffffu, m2, 2));
            float s1 = 0.f, s2 = 0.f;
#pragma unroll
            for (int ni = 0; ni < 4; ni++) {
                s1 += __expf(acc[mi][ni].x - m1) + __expf(acc[mi][ni].y - m1);
                s2 += __expf(acc[mi][ni].z - m2) + __expf(acc[mi][ni].w - m2);
            }
            s1 += __shfl_xor_sync(0xffffffffu, s1, 1);
            s1 += __shfl_xor_sync(0xffffffffu, s1, 2);
            s2 += __shfl_xor_sync(0xffffffffu, s2, 1);
            s2 += __shfl_xor_sync(0xffffffffu, s2, 2);
            if (tig == 0) {
                int rb1 = wm + mi * 16 + g;
                red_m[rb1 * 4 + wcol] = m1;  red_s[rb1 * 4 + wcol] = s1;
                red_m[(rb1 + 8) * 4 + wcol] = m2;  red_s[(rb1 + 8) * 4 + wcol] = s2;
            }
        }
        __syncthreads();
        if (tid < 128) {
            float M = -1e30f;
#pragma unroll
            for (int j = 0; j < 4; j++) M = fmaxf(M, red_m[tid * 4 + j]);
            float S = 0.f;
#pragma unroll
            for (int j = 0; j < 4; j++)
                S += red_s[tid * 4 + j] * __expf(red_m[tid * 4 + j] - M);
            size_t idx = (size_t)(row0 + tid) * 16 + blockIdx.x;
            pmax[idx] = M;
            psum[idx] = S;
        }
    }
}

// ---------------- combine partials ----------------
__global__ void k_rowstat2()
{
    int row = blockIdx.x * 256 + threadIdx.x;
    const float* pm = g_pmax + (size_t)row * 16;
    const float* ps = g_psum + (size_t)row * 16;
    float M = -1e30f;
#pragma unroll
    for (int j = 0; j < 16; j++) M = fmaxf(M, pm[j]);
    float S = 0.f;
#pragma unroll
    for (int j = 0; j < 16; j++) S += ps[j] * __expf(pm[j] - M);
    g_rowoff[row] = M + __logf(S);
}

// ---------------- BF16 agg + fused LN epilogue — double-buffered (R16, unchanged)
#define AG_AST 5120
#define AG_BST 16896

__global__ __launch_bounds__(256, 2) void k_agg_bf16(
    const float* __restrict__ x, const float* __restrict__ mlp_b,
    const float* __restrict__ ln_g, const float* __restrict__ ln_b,
    float* __restrict__ out)
{
    __shared__ __align__(16) char AsB[2 * AG_AST];   // 10240 B
    __shared__ __align__(16) char BsB[2 * AG_BST];   // 33792 B
    __shared__ float red_s[64 * 4];
    __shared__ float red_q[64 * 4];
    __shared__ float s_mb[256], s_g[256], s_b[256];

    const uint32_t asb = (uint32_t)__cvta_generic_to_shared(AsB);
    const uint32_t bsb = (uint32_t)__cvta_generic_to_shared(BsB);

    const int b  = blockIdx.z;
    const int p0 = ((int)gridDim.x - 1 - (int)blockIdx.x) * 64;   // longest blocks first
    const int tid  = threadIdx.x;
    const int lane = tid & 31;
    const int warp = tid >> 5;
    const int wm = (warp & 1) * 32;
    const int wn = (warp >> 1) * 64;
    const int wngrp = warp >> 1;
    const int g   = lane >> 2;
    const int tig = lane & 3;

    s_mb[tid] = mlp_b[tid];
    s_g[tid]  = ln_g[tid];
    s_b[tid]  = ln_b[tid];

    const int ar  = tid >> 2;
    const int ac8 = (tid & 3) * 8;
    const int prow = p0 + ar;
    const float off = g_rowoff[b * P_ + prow];
    const __nv_bfloat16* Lp = g_logbf + (size_t)(b * P_ + prow) * P_ + ac8;
    const __nv_bfloat16* xmb = g_xmbf + (size_t)b * P_ * D_;

    const int rowit = lane & 15;
    const int colb  = (lane & 16) ? 16 : 0;

    float4 acc[2][8];
#pragma unroll
    for (int mi = 0; mi < 2; mi++)
#pragma unroll
        for (int ni = 0; ni < 8; ni++) acc[mi][ni] = make_float4(0.f, 0.f, 0.f, 0.f);

    const int nkt = (p0 + 64) / 32;

#pragma unroll
    for (int t = 0; t < 4; t++) {
        int id = tid + t * 256;
        int krow = id >> 5;
        int ch = id & 31;
        cp16(bsb + (uint32_t)(krow * 528 + ch * 16),
             xmb + (size_t)krow * D_ + ch * 8);
    }
    CP_COMMIT();
    uint4 raw = *(const uint4*)(Lp);

    for (int kt = 0; kt < nkt; kt++) {
        const int s = kt & 1;
        const int k0 = kt * 32;

        {
            const __nv_bfloat162* h = (const __nv_bfloat162*)&raw;
            float2 f0 = __bfloat1622float2(h[0]);
            float2 f1 = __bfloat1622float2(h[1]);
            float2 f2 = __bfloat1622float2(h[2]);
            float2 f3 = __bfloat1622float2(h[3]);
            int kq = k0 + ac8;
            float e0 = (kq     <= prow) ? __expf(f0.x - off) : 0.f;
            float e1 = (kq + 1 <= prow) ? __expf(f0.y - off) : 0.f;
            float e2 = (kq + 2 <= prow) ? __expf(f1.x - off) : 0.f;
            float e3 = (kq + 3 <= prow) ? __expf(f1.y - off) : 0.f;
            float e4 = (kq + 4 <= prow) ? __expf(f2.x - off) : 0.f;
            float e5 = (kq + 5 <= prow) ? __expf(f2.y - off) : 0.f;
            float e6 = (kq + 6 <= prow) ? __expf(f3.x - off) : 0.f;
            float e7 = (kq + 7 <= prow) ? __expf(f3.y - off) : 0.f;
            __nv_bfloat162 p0b = __floats2bfloat162_rn(e0, e1);
            __nv_bfloat162 p1b = __floats2bfloat162_rn(e2, e3);
            __nv_bfloat162 p2b = __floats2bfloat162_rn(e4, e5);
            __nv_bfloat162 p3b = __floats2bfloat162_rn(e6, e7);
            uint4 pk;
            pk.x = *(uint32_t*)&p0b; pk.y = *(uint32_t*)&p1b;
            pk.z = *(uint32_t*)&p2b; pk.w = *(uint32_t*)&p3b;
            *(uint4*)(AsB + s * AG_AST + ar * 80 + ac8 * 2) = pk;
        }

        CP_WAIT(0);
        __syncthreads();

        if (kt + 1 < nkt) {
            const int kn = k0 + 32;
#pragma unroll
            for (int t = 0; t < 4; t++) {
                int id = tid + t * 256;
                int krow = id >> 5;
                int ch = id & 31;
                cp16(bsb + (uint32_t)((s ^ 1) * AG_BST + krow * 528 + ch * 16),
                     xmb + (size_t)(kn + krow) * D_ + ch * 8);
            }
            CP_COMMIT();
            raw = *(const uint4*)(Lp + kn);
        }

        const uint32_t aB = asb + (uint32_t)(s * AG_AST + (wm + rowit) * 80 + colb);
        const uint32_t bB = bsb + (uint32_t)(s * AG_BST + rowit * 528 + colb + wn * 2);
#pragma unroll
        for (int ks = 0; ks < 2; ks++) {
            uint32_t af[2][4];
#pragma unroll
            for (int mi = 0; mi < 2; mi++)
                ldsm_x4(af[mi], aB + (uint32_t)(mi * 16 * 80 + ks * 32));
#pragma unroll
            for (int nj = 0; nj < 4; nj++) {
                uint32_t bq[4];
                ldsm_x4t(bq, bB + (uint32_t)(ks * 16 * 528 + nj * 32));
#pragma unroll
                for (int mi = 0; mi < 2; mi++) {
                    mma_bf16(acc[mi][nj * 2],     af[mi], bq[0], bq[1]);
                    mma_bf16(acc[mi][nj * 2 + 1], af[mi], bq[2], bq[3]);
                }
            }
        }
    }

    float ssum[2][2] = {{0.f, 0.f}, {0.f, 0.f}};
    float qsum[2][2] = {{0.f, 0.f}, {0.f, 0.f}};
#pragma unroll
    for (int mi = 0; mi < 2; mi++) {
        int gr0 = b * P_ + p0 + wm + mi * 16 + g;
        int gr1 = gr0 + 8;
        float wc0 = g_wc[gr0], wc1 = g_wc[gr1];
        const float* xr0 = x + (size_t)gr0 * D_;
        const float* xr1 = x + (size_t)gr1 * D_;
#pragma unroll
        for (int ni = 0; ni < 8; ni++) {
            int c = wn + ni * 8 + tig * 2;
            float2 xv0 = *(const float2*)(xr0 + c);
            float2 xv1 = *(const float2*)(xr1 + c);
            acc[mi][ni].x += s_mb[c]     + wc0 * xv0.x;
            acc[mi][ni].y += s_mb[c + 1] + wc0 * xv0.y;
            acc[mi][ni].z += s_mb[c]     + wc1 * xv1.x;
            acc[mi][ni].w += s_mb[c + 1] + wc1 * xv1.y;
            ssum[mi][0] += acc[mi][ni].x + acc[mi][ni].y;
            ssum[mi][1] += acc[mi][ni].z + acc[mi][ni].w;
            qsum[mi][0] += acc[mi][ni].x * acc[mi][ni].x + acc[mi][ni].y * acc[mi][ni].y;
            qsum[mi][1] += acc[mi][ni].z * acc[mi][ni].z + acc[mi][ni].w * acc[mi][ni].w;
        }
    }
#pragma unroll
    for (int mi = 0; mi < 2; mi++)
#pragma unroll
        for (int hf = 0; hf < 2; hf++) {
            ssum[mi][hf] += __shfl_xor_sync(0xffffffffu, ssum[mi][hf], 1);
            ssum[mi][hf] += __shfl_xor_sync(0xffffffffu, ssum[mi][hf], 2);
            qsum[mi][hf] += __shfl_xor_sync(0xffffffffu, qsum[mi][hf], 1);
            qsum[mi][hf] += __shfl_xor_sync(0xffffffffu, qsum[mi][hf], 2);
        }
    if (tig == 0) {
#pragma unroll
        for (int mi = 0; mi < 2; mi++)
#pragma unroll
            for (int hf = 0; hf < 2; hf++) {
                int rl = wm + mi * 16 + g + hf * 8;
                red_s[rl * 4 + wngrp] = ssum[mi][hf];
                red_q[rl * 4 + wngrp] = qsum[mi][hf];
            }
    }
    __syncthreads();

#pragma unroll
    for (int mi = 0; mi < 2; mi++) {
#pragma unroll
        for (int hf = 0; hf < 2; hf++) {
            int rl = wm + mi * 16 + g + hf * 8;
            float S = red_s[rl * 4] + red_s[rl * 4 + 1] + red_s[rl * 4 + 2] + red_s[rl * 4 + 3];
            float Q = red_q[rl * 4] + red_q[rl * 4 + 1] + red_q[rl * 4 + 2] + red_q[rl * 4 + 3];
            float mu = S * (1.0f / 256.0f);
            float var = Q * (1.0f / 256.0f) - mu * mu;
            float inv = rsqrtf(var + 1e-5f);
            int gr = b * P_ + p0 + rl;
            float* orow = out + (size_t)gr * D_;
#pragma unroll
            for (int ni = 0; ni < 8; ni++) {
                int c = wn + ni * 8 + tig * 2;
                float h0 = (hf == 0) ? acc[mi][ni].x : acc[mi][ni].z;
                float h1 = (hf == 0) ? acc[mi][ni].y : acc[mi][ni].w;
                float2 y;
                y.x = (h0 - mu) * inv * s_g[c] + s_b[c];
                y.y = (h1 - mu) * inv * s_g[c + 1] + s_b[c + 1];
                *(float2*)(orow + c) = y;
            }
        }
    }
}

// ---------------- launch ----------------
extern "C" void kernel_launch(void* const* d_in, const int* in_sizes, int n_in,
                              void* d_out, int out_size)
{
    const float* x      = (const float*)d_in[0];
    const float* mlp_w  = (const float*)d_in[1];
    const float* mlp_b  = (const float*)d_in[2];
    const float* his_w  = (const float*)d_in[3];
    const float* his_b  = (const float*)d_in[4];
    const float* cur_w  = (const float*)d_in[5];
    const float* cur_b  = (const float*)d_in[6];
    const float* wl_w   = (const float*)d_in[7];
    const float* wl_b   = (const float*)d_in[8];
    const float* gate_w = (const float*)d_in[9];
    const float* gate_b = (const float*)d_in[10];
    const float* ln_g   = (const float*)d_in[11];
    const float* ln_b   = (const float*)d_in[12];
    float* out = (float*)d_out;

    void *pHbf, *pLbf, *pXM, *pXbf, *pWLbf, *pWCAT, *pPM, *pPS, *pZ;
    cudaGetSymbolAddress(&pHbf, g_Hbf);
    cudaGetSymbolAddress(&pLbf, g_logbf);
    cudaGetSymbolAddress(&pXM, g_xmbf);
    cudaGetSymbolAddress(&pXbf, g_xbf);
    cudaGetSymbolAddress(&pWLbf, g_wlbf);
    cudaGetSymbolAddress(&pWCAT, g_wcatbf);
    cudaGetSymbolAddress(&pPM, g_pmax);
    cudaGetSymbolAddress(&pPS, g_psum);
    cudaGetSymbolAddress(&pZ, g_zero);
    __nv_bfloat16* gHbf   = (__nv_bfloat16*)pHbf;
    __nv_bfloat16* gLbf   = (__nv_bfloat16*)pLbf;
    __nv_bfloat16* gXMbf  = (__nv_bfloat16*)pXM;
    __nv_bfloat16* gXbf   = (__nv_bfloat16*)pXbf;
    __nv_bfloat16* gWLbf  = (__nv_bfloat16*)pWLbf;
    __nv_bfloat16* gWCAT  = (__nv_bfloat16*)pWCAT;
    float* gPM = (float*)pPM;
    float* gPS = (float*)pPS;
    float* gZ  = (float*)pZ;

    const int bf16_smem = L_STGB * 2;        // 71680 bytes
    cudaFuncSetAttribute(k_gemm_bf16, cudaFuncAttributeMaxDynamicSharedMemorySize, bf16_smem);

    // weight conversions
    k_cvt<<<(D_ * P_ / 4) / 256, 256>>>((const float4*)wl_w, (uint2*)gWLbf);
    k_cvtW<<<(D_ * D_) / 256, 256>>>(his_w, mlp_w, gWCAT);

    // gate precompute; fused x->bf16 + wc + origin copy
    k_weff<<<D_ / 8, 256>>>(cur_w, cur_b, gate_w, gate_b);
    k_cvtx_wc<<<BP_ / 8, 256>>>(x, out + (size_t)BP_ * D_);

    // [H | xm] = x @ [his_w | mlp_w]  (one merged GEMM, split outputs)
    k_gemm_bf16<<<dim3(512 / 128, BP_ / 128), 256, bf16_smem>>>(
        gXbf, gWCAT, his_b, gZ, gHbf, gXMbf,
        512, D_, 256, 0, nullptr, nullptr);
    // logits = H @ wl_w + wl_b  (bf16 MMA + fused softmax stats)
    k_gemm_bf16<<<dim3(P_ / 128, BP_ / 128), 256, bf16_smem>>>(
        gHbf, gWLbf, wl_b, wl_b, gLbf, gLbf,
        P_, P_, P_, 1, gPM, gPS);
    // combine softmax offsets
    k_rowstat2<<<BP_ / 256, 256>>>();
    // out = LN(tril(softmax)@xm + mlp_b + wc*x)  -- fully fused, double-buffered
    k_agg_bf16<<<dim3(P_ / 64, 1, B_), 256>>>(x, mlp_b, ln_g, ln_b, out);
}